// round 1
// baseline (speedup 1.0000x reference)
#include <cuda_runtime.h>
#include <cuda_bf16.h>
#include <math.h>

// Problem constants
#define B16    16
#define L64    64
#define DM512  512
#define NH8    8
#define HD64   64
#define NCTX   3131
#define DINPROJ 1042
#define CONVDIM 514

// Scratch (static device arrays; allocation-free per harness rules)
__device__ float S_u  [B16*L64*DM512];
__device__ float S_zx [B16*L64*DINPROJ];
__device__ float S_x  [B16*L64*DM512];
__device__ float S_Bv [B16*L64];
__device__ float S_Cv [B16*L64];
__device__ float S_ys [2*B16*L64*DM512];
__device__ float S_yn [B16*L64*DM512];
__device__ float S_out[B16*L64*DM512];

// ---------------------------------------------------------------------------
// u[b,g,h*64+c] = slice_token[b,h,g,c]
__global__ void k_transpose_u(const float* __restrict__ st) {
    int row = blockIdx.x;            // b*64+g
    int b = row >> 6, g = row & 63;
    int tid = threadIdx.x;           // 0..511
    int h = tid >> 6, c = tid & 63;
    S_u[row*DM512 + tid] = st[(((b*8 + h)*64) + g)*64 + c];
}

// ---------------------------------------------------------------------------
// Generic C[m,n] = sum_k A[m,k] * Bm[n,k]   (x @ W^T), M multiple of 64, K mult of 16
__global__ __launch_bounds__(256) void k_gemm_xwt(
    const float* __restrict__ A, const float* __restrict__ Bm,
    float* __restrict__ C, int M, int N, int K)
{
    __shared__ float As[16][65];
    __shared__ float Bs[16][65];
    int tid = threadIdx.x;
    int tx = tid & 15, ty = tid >> 4;
    int m0 = blockIdx.y * 64, n0 = blockIdx.x * 64;
    float acc[4][4] = {};
    for (int k0 = 0; k0 < K; k0 += 16) {
        #pragma unroll
        for (int p = 0; p < 4; ++p) {
            int idx = tid + p*256;
            int m = idx >> 4, kk = idx & 15;
            As[kk][m] = A[(m0 + m)*K + k0 + kk];
        }
        #pragma unroll
        for (int p = 0; p < 4; ++p) {
            int idx = tid + p*256;
            int n = idx >> 4, kk = idx & 15;
            float v = 0.f;
            if (n0 + n < N) v = Bm[(n0 + n)*K + k0 + kk];
            Bs[kk][n] = v;
        }
        __syncthreads();
        #pragma unroll
        for (int kk = 0; kk < 16; ++kk) {
            float a[4], bv[4];
            #pragma unroll
            for (int i = 0; i < 4; ++i) a[i] = As[kk][ty + 16*i];
            #pragma unroll
            for (int j = 0; j < 4; ++j) bv[j] = Bs[kk][tx + 16*j];
            #pragma unroll
            for (int i = 0; i < 4; ++i)
                #pragma unroll
                for (int j = 0; j < 4; ++j) acc[i][j] += a[i]*bv[j];
        }
        __syncthreads();
    }
    #pragma unroll
    for (int i = 0; i < 4; ++i)
        #pragma unroll
        for (int j = 0; j < 4; ++j) {
            int n = n0 + tx + 16*j;
            if (n < N) C[(m0 + ty + 16*i)*N + n] = acc[i][j];
        }
}

// ---------------------------------------------------------------------------
// Depthwise causal conv (DCONV=3) + SiLU on channels 512..1025 of zxbcdt
__global__ void k_conv(const float* __restrict__ conv_w, const float* __restrict__ conv_b) {
    int row = blockIdx.x;        // b*64+t
    int t = row & 63;
    int c = threadIdx.x;
    if (c >= CONVDIM) return;
    float acc = conv_b[c];
    #pragma unroll
    for (int k = 0; k < 3; ++k) {
        int tt = t + k - 2;
        if (tt >= 0) acc += conv_w[c*3 + k] * S_zx[(row + (k - 2))*DINPROJ + 512 + c];
    }
    acc = acc / (1.f + expf(-acc));     // silu
    if (c < 512)       S_x[row*512 + c] = acc;
    else if (c == 512) S_Bv[row] = acc;
    else               S_Cv[row] = acc;
}

// ---------------------------------------------------------------------------
// Sequential scan over L=64 per (extended batch i in 0..31, channel d in 0..511).
// Stores shifted output directly: ys[i,t+1] = h_t * C_t, ys[i,0] = 0
__global__ void k_scan(const float* __restrict__ dt_bias, const float* __restrict__ A_log) {
    int gid = blockIdx.x * blockDim.x + threadIdx.x;   // 0..16383
    int i = gid >> 9;
    int d = gid & 511;
    int h = d >> 6;
    bool bw = (i >= 16);
    int b = bw ? i - 16 : i;
    float Ah = -expf(A_log[h]);
    float bias = dt_bias[h];
    int dtoff = bw ? (1026 + 8 + h) : (1026 + h);
    float hs = 0.f;
    S_ys[(i*64 + 0)*512 + d] = 0.f;
    for (int t = 0; t < 64; ++t) {
        int tt = bw ? (63 - t) : t;
        int row = b*64 + tt;
        float x  = S_x[row*512 + d];
        float Bc = S_Bv[row];
        float Cc = S_Cv[row];
        float v  = S_zx[row*DINPROJ + dtoff] + bias;
        float dt = (v > 20.f) ? v : log1pf(expf(v));
        float a  = expf(dt * Ah);
        hs = a*hs + dt*Bc*x;
        if (t < 63) S_ys[(i*64 + t + 1)*512 + d] = hs * Cc;
    }
}

// ---------------------------------------------------------------------------
// y = y_fw + y_bw + x*dcoef; y *= silu(z); RMSNorm * norm_w  -> S_yn
__global__ __launch_bounds__(512) void k_combine(
    const float* __restrict__ fc_D_w, const float* __restrict__ Dv,
    const float* __restrict__ norm_w)
{
    int row = blockIdx.x;            // b*64+t
    int b = row >> 6, t = row & 63;
    int d = threadIdx.x;
    int h = d >> 6;
    int lane = d & 31, wid = d >> 5;

    float x  = S_x[row*512 + d];
    float z  = S_zx[row*DINPROJ + d];
    float yf = S_ys[row*512 + d];
    float yb = S_ys[((16 + b)*64 + (63 - t))*512 + d];

    // dcoef[h] = sum_d x_d * fc_D_w[h,d]  (8 block reductions via shuffles)
    float px[8];
    #pragma unroll
    for (int hh = 0; hh < 8; ++hh) px[hh] = x * fc_D_w[hh*512 + d];
    #pragma unroll
    for (int off = 16; off; off >>= 1)
        #pragma unroll
        for (int hh = 0; hh < 8; ++hh) px[hh] += __shfl_xor_sync(0xffffffffu, px[hh], off);

    __shared__ float wsum[16][8];
    __shared__ float dcf[8];
    if (lane == 0) {
        #pragma unroll
        for (int hh = 0; hh < 8; ++hh) wsum[wid][hh] = px[hh];
    }
    __syncthreads();
    if (d < 8) {
        float s = 0.f;
        #pragma unroll
        for (int w = 0; w < 16; ++w) s += wsum[w][d];
        dcf[d] = s + Dv[d];
    }
    __syncthreads();

    float y = yf + yb + x * dcf[h];
    y *= z / (1.f + expf(-z));

    // RMS norm over 512
    float sq = y*y;
    #pragma unroll
    for (int off = 16; off; off >>= 1) sq += __shfl_xor_sync(0xffffffffu, sq, off);
    __shared__ float rsum[16];
    __shared__ float rscale;
    if (lane == 0) rsum[wid] = sq;
    __syncthreads();
    if (d == 0) {
        float s = 0.f;
        #pragma unroll
        for (int w = 0; w < 16; ++w) s += rsum[w];
        rscale = rsqrtf(s / 512.f + 1e-5f);
    }
    __syncthreads();
    S_yn[row*512 + d] = y * rscale * norm_w[d];
}

// ---------------------------------------------------------------------------
// outp[b,h,g,c] = S_out[b*64+g, h*64+c]
__global__ void k_permute(float* __restrict__ outp) {
    int row = blockIdx.x;            // b*64+g
    int b = row >> 6, g = row & 63;
    int tid = threadIdx.x;           // 0..511
    int h = tid >> 6, c = tid & 63;
    outp[(((b*8 + h)*64 + g)*64) + c] = S_out[row*512 + tid];
}

// ---------------------------------------------------------------------------
// Fused: out_x tile (einsum) staged in smem, then x @ to_out_w^T + bias.
// Grid: (ceil(3131/64)=49, 16), 256 threads.
__global__ __launch_bounds__(256) void k_final(
    const float* __restrict__ sw, const float* __restrict__ outp,
    const float* __restrict__ W, const float* __restrict__ bias,
    float* __restrict__ out)
{
    extern __shared__ float sm[];
    float* outx = sm;                 // [64][513]
    float* bufA = sm + 64*513;        // 64*65 floats
    float* bufB = bufA + 64*65;       // 64*65 floats
    int tid = threadIdx.x;
    int tx = tid & 15, ty = tid >> 4;
    int n0 = blockIdx.x * 64;
    int b  = blockIdx.y;

    // ---- phase 1: outx[m][h*64+c] = sum_g sw[b,h,n0+m,g] * outp[b,h,g,c]
    for (int h = 0; h < 8; ++h) {
        const float* swb = sw + ((size_t)(b*8 + h)*NCTX + n0)*64;
        #pragma unroll
        for (int p = 0; p < 16; ++p) {
            int idx = tid + p*256;
            int m = idx >> 6, g = idx & 63;
            float v = 0.f;
            if (n0 + m < NCTX) v = swb[m*64 + g];
            bufA[m*65 + g] = v;
        }
        const float* ob = outp + (size_t)(b*8 + h)*64*64;
        #pragma unroll
        for (int p = 0; p < 16; ++p) {
            int idx = tid + p*256;
            int g = idx >> 6, c = idx & 63;
            bufB[g*65 + c] = ob[idx];
        }
        __syncthreads();
        float acc[4][4] = {};
        for (int g = 0; g < 64; ++g) {
            float a[4], bv[4];
            #pragma unroll
            for (int i = 0; i < 4; ++i) a[i] = bufA[(ty + 16*i)*65 + g];
            #pragma unroll
            for (int j = 0; j < 4; ++j) bv[j] = bufB[g*65 + tx + 16*j];
            #pragma unroll
            for (int i = 0; i < 4; ++i)
                #pragma unroll
                for (int j = 0; j < 4; ++j) acc[i][j] += a[i]*bv[j];
        }
        __syncthreads();
        #pragma unroll
        for (int i = 0; i < 4; ++i)
            #pragma unroll
            for (int j = 0; j < 4; ++j)
                outx[(ty + 16*i)*513 + h*64 + tx + 16*j] = acc[i][j];
    }
    __syncthreads();

    // ---- phase 2: out[b, n0+m, :] = outx[m, :] @ W^T + bias
    for (int nc = 0; nc < 4; ++nc) {
        int nbase = nc*128;
        float acc[4][8] = {};
        for (int kt = 0; kt < 32; ++kt) {
            int k0 = kt*16;
            #pragma unroll
            for (int p = 0; p < 8; ++p) {
                int idx = tid + p*256;
                int n = idx >> 4, kk = idx & 15;
                bufA[kk*129 + n] = W[(nbase + n)*512 + k0 + kk];
            }
            __syncthreads();
            #pragma unroll
            for (int kk = 0; kk < 16; ++kk) {
                float a[4], w[8];
                #pragma unroll
                for (int i = 0; i < 4; ++i) a[i] = outx[(ty + 16*i)*513 + k0 + kk];
                #pragma unroll
                for (int j = 0; j < 8; ++j) w[j] = bufA[kk*129 + tx + 16*j];
                #pragma unroll
                for (int i = 0; i < 4; ++i)
                    #pragma unroll
                    for (int j = 0; j < 8; ++j) acc[i][j] += a[i]*w[j];
            }
            __syncthreads();
        }
        #pragma unroll
        for (int i = 0; i < 4; ++i) {
            int m = ty + 16*i;
            if (n0 + m < NCTX) {
                size_t ro = ((size_t)b*NCTX + n0 + m)*512 + nbase;
                #pragma unroll
                for (int j = 0; j < 8; ++j) {
                    int n = tx + 16*j;
                    out[ro + n] = acc[i][j] + bias[nbase + n];
                }
            }
        }
    }
}

// ---------------------------------------------------------------------------
extern "C" void kernel_launch(void* const* d_in, const int* in_sizes, int n_in,
                              void* d_out, int out_size) {
    const float* st     = (const float*)d_in[0];
    const float* sw     = (const float*)d_in[1];
    const float* w_in   = (const float*)d_in[2];
    const float* conv_w = (const float*)d_in[3];
    const float* conv_b = (const float*)d_in[4];
    const float* dt_bias= (const float*)d_in[5];
    const float* A_log  = (const float*)d_in[6];
    const float* Dv     = (const float*)d_in[7];
    const float* fc_D_w = (const float*)d_in[8];
    const float* norm_w = (const float*)d_in[9];
    const float* w_out  = (const float*)d_in[10];
    const float* to_w   = (const float*)d_in[11];
    const float* to_b   = (const float*)d_in[12];

    float* out       = (float*)d_out;
    float* out_final = out;                                   // 16*3131*512
    float* out_inp   = out + (size_t)B16*NCTX*DM512;          // 16*8*64*64
    float* out_outp  = out_inp + (size_t)B16*8*64*64;         // 16*8*64*64

    float *pSu, *pSzx, *pSyn, *pSout;
    cudaGetSymbolAddress((void**)&pSu,  S_u);
    cudaGetSymbolAddress((void**)&pSzx, S_zx);
    cudaGetSymbolAddress((void**)&pSyn, S_yn);
    cudaGetSymbolAddress((void**)&pSout,S_out);

    // inp passthrough
    cudaMemcpyAsync(out_inp, st, sizeof(float)*B16*8*64*64, cudaMemcpyDeviceToDevice);

    k_transpose_u<<<B16*L64, 512>>>(st);

    // zxbcdt = u @ w_in^T  (1024 x 1042 x 512)
    k_gemm_xwt<<<dim3((DINPROJ + 63)/64, B16*L64/64), 256>>>(pSu, w_in, pSzx, B16*L64, DINPROJ, DM512);

    k_conv<<<B16*L64, 544>>>(conv_w, conv_b);
    k_scan<<<64, 256>>>(dt_bias, A_log);
    k_combine<<<B16*L64, 512>>>(fc_D_w, Dv, norm_w);

    // out = y @ w_out^T (1024 x 512 x 512)
    k_gemm_xwt<<<dim3(DM512/64, B16*L64/64), 256>>>(pSyn, w_out, pSout, B16*L64, DM512, DM512);

    k_permute<<<B16*L64, 512>>>(out_outp);

    // fused einsum + final projection
    int smem_bytes = (64*513 + 2*64*65) * (int)sizeof(float);   // ~164.6 KB
    cudaFuncSetAttribute(k_final, cudaFuncAttributeMaxDynamicSharedMemorySize, smem_bytes);
    k_final<<<dim3((NCTX + 63)/64, B16), 256, smem_bytes>>>(sw, out_outp, to_w, to_b, out_final);
}

// round 2
// speedup vs baseline: 1.2699x; 1.2699x over previous
#include <cuda_runtime.h>
#include <cuda_bf16.h>
#include <math.h>

// Problem constants
#define B16    16
#define L64    64
#define DM512  512
#define NH8    8
#define HD64   64
#define NCTX   3131
#define DINPROJ 1042
#define CONVDIM 514

// Scratch (static device arrays; allocation-free per harness rules)
__device__ float S_u  [B16*L64*DM512];
__device__ float S_zx [B16*L64*DINPROJ];
__device__ float S_x  [B16*L64*DM512];
__device__ float S_Bv [B16*L64];
__device__ float S_Cv [B16*L64];
__device__ float S_ys [2*B16*L64*DM512];
__device__ float S_yn [B16*L64*DM512];
__device__ float S_out[B16*L64*DM512];

// ---- packed f32x2 helpers (FFMA2) -----------------------------------------
__device__ __forceinline__ unsigned long long pk2(float x) {
    unsigned long long r;
    asm("mov.b64 %0, {%1, %1};" : "=l"(r) : "f"(x));
    return r;
}
__device__ __forceinline__ void upk2(unsigned long long v, float& lo, float& hi) {
    asm("mov.b64 {%0, %1}, %2;" : "=f"(lo), "=f"(hi) : "l"(v));
}
#define FMA2(d, a, b) asm("fma.rn.f32x2 %0, %1, %2, %0;" : "+l"(d) : "l"(a), "l"(b))

// ---------------------------------------------------------------------------
// u[b,g,h*64+c] = slice_token[b,h,g,c]
__global__ void k_transpose_u(const float* __restrict__ st) {
    int row = blockIdx.x;            // b*64+g
    int b = row >> 6, g = row & 63;
    int tid = threadIdx.x;           // 0..511
    int h = tid >> 6, c = tid & 63;
    S_u[row*DM512 + tid] = st[(((b*8 + h)*64) + g)*64 + c];
}

// ---------------------------------------------------------------------------
// Generic C[m,n] = sum_k A[m,k] * Bm[n,k]   (x @ W^T), M mult of 64, K mult of 16
// f32x2-packed inner product.
__global__ __launch_bounds__(256) void k_gemm_xwt(
    const float* __restrict__ A, const float* __restrict__ Bm,
    float* __restrict__ C, int M, int N, int K)
{
    __shared__ float As[16*65];
    __shared__ __align__(16) float Bs[16*66];
    unsigned long long* Bs64 = (unsigned long long*)Bs;
    int tid = threadIdx.x;
    int tx = tid & 15, ty = tid >> 4;
    int m0 = blockIdx.y * 64, n0 = blockIdx.x * 64;
    unsigned long long acc[4][2] = {};
    for (int k0 = 0; k0 < K; k0 += 16) {
        #pragma unroll
        for (int p = 0; p < 4; ++p) {
            int idx = tid + p*256;
            int m = idx >> 4, kk = idx & 15;
            As[kk*65 + m] = A[(m0 + m)*K + k0 + kk];
        }
        #pragma unroll
        for (int p = 0; p < 4; ++p) {
            int idx = tid + p*256;
            int n = idx >> 4, kk = idx & 15;
            float v = 0.f;
            if (n0 + n < N) v = Bm[(n0 + n)*K + k0 + kk];
            Bs[kk*66 + n] = v;
        }
        __syncthreads();
        #pragma unroll
        for (int kk = 0; kk < 16; ++kk) {
            unsigned long long a2[4], w2[2];
            #pragma unroll
            for (int i = 0; i < 4; ++i) a2[i] = pk2(As[kk*65 + ty + 16*i]);
            #pragma unroll
            for (int j = 0; j < 2; ++j) w2[j] = Bs64[kk*33 + tx + 16*j];
            #pragma unroll
            for (int i = 0; i < 4; ++i)
                #pragma unroll
                for (int j = 0; j < 2; ++j) FMA2(acc[i][j], a2[i], w2[j]);
        }
        __syncthreads();
    }
    #pragma unroll
    for (int i = 0; i < 4; ++i)
        #pragma unroll
        for (int j = 0; j < 2; ++j) {
            int n = n0 + 2*tx + 32*j;
            float lo, hi;
            upk2(acc[i][j], lo, hi);
            if (n < N)     C[(m0 + ty + 16*i)*N + n]     = lo;
            if (n + 1 < N) C[(m0 + ty + 16*i)*N + n + 1] = hi;
        }
}

// ---------------------------------------------------------------------------
// Depthwise causal conv (DCONV=3) + SiLU on channels 512..1025 of zxbcdt
__global__ void k_conv(const float* __restrict__ conv_w, const float* __restrict__ conv_b) {
    int row = blockIdx.x;        // b*64+t
    int t = row & 63;
    int c = threadIdx.x;
    if (c >= CONVDIM) return;
    float acc = conv_b[c];
    #pragma unroll
    for (int k = 0; k < 3; ++k) {
        int tt = t + k - 2;
        if (tt >= 0) acc += conv_w[c*3 + k] * S_zx[(row + (k - 2))*DINPROJ + 512 + c];
    }
    acc = acc / (1.f + expf(-acc));     // silu
    if (c < 512)       S_x[row*512 + c] = acc;
    else if (c == 512) S_Bv[row] = acc;
    else               S_Cv[row] = acc;
}

// ---------------------------------------------------------------------------
// Sequential scan over L=64 per (extended batch i in 0..31, channel d in 0..511).
// Stores shifted output directly: ys[i,t+1] = h_t * C_t, ys[i,0] = 0
__global__ void k_scan(const float* __restrict__ dt_bias, const float* __restrict__ A_log) {
    int gid = blockIdx.x * blockDim.x + threadIdx.x;   // 0..16383
    int i = gid >> 9;
    int d = gid & 511;
    int h = d >> 6;
    bool bw = (i >= 16);
    int b = bw ? i - 16 : i;
    float Ah = -expf(A_log[h]);
    float bias = dt_bias[h];
    int dtoff = bw ? (1026 + 8 + h) : (1026 + h);
    float hs = 0.f;
    S_ys[(i*64 + 0)*512 + d] = 0.f;
    for (int t = 0; t < 64; ++t) {
        int tt = bw ? (63 - t) : t;
        int row = b*64 + tt;
        float x  = S_x[row*512 + d];
        float Bc = S_Bv[row];
        float Cc = S_Cv[row];
        float v  = S_zx[row*DINPROJ + dtoff] + bias;
        float dt = (v > 20.f) ? v : log1pf(expf(v));
        float a  = expf(dt * Ah);
        hs = a*hs + dt*Bc*x;
        if (t < 63) S_ys[(i*64 + t + 1)*512 + d] = hs * Cc;
    }
}

// ---------------------------------------------------------------------------
// y = y_fw + y_bw + x*dcoef; y *= silu(z); RMSNorm * norm_w  -> S_yn
__global__ __launch_bounds__(512) void k_combine(
    const float* __restrict__ fc_D_w, const float* __restrict__ Dv,
    const float* __restrict__ norm_w)
{
    int row = blockIdx.x;            // b*64+t
    int b = row >> 6, t = row & 63;
    int d = threadIdx.x;
    int h = d >> 6;
    int lane = d & 31, wid = d >> 5;

    float x  = S_x[row*512 + d];
    float z  = S_zx[row*DINPROJ + d];
    float yf = S_ys[row*512 + d];
    float yb = S_ys[((16 + b)*64 + (63 - t))*512 + d];

    // dcoef[h] = sum_d x_d * fc_D_w[h,d]  (8 block reductions via shuffles)
    float px[8];
    #pragma unroll
    for (int hh = 0; hh < 8; ++hh) px[hh] = x * fc_D_w[hh*512 + d];
    #pragma unroll
    for (int off = 16; off; off >>= 1)
        #pragma unroll
        for (int hh = 0; hh < 8; ++hh) px[hh] += __shfl_xor_sync(0xffffffffu, px[hh], off);

    __shared__ float wsum[16][8];
    __shared__ float dcf[8];
    if (lane == 0) {
        #pragma unroll
        for (int hh = 0; hh < 8; ++hh) wsum[wid][hh] = px[hh];
    }
    __syncthreads();
    if (d < 8) {
        float s = 0.f;
        #pragma unroll
        for (int w = 0; w < 16; ++w) s += wsum[w][d];
        dcf[d] = s + Dv[d];
    }
    __syncthreads();

    float y = yf + yb + x * dcf[h];
    y *= z / (1.f + expf(-z));

    // RMS norm over 512
    float sq = y*y;
    #pragma unroll
    for (int off = 16; off; off >>= 1) sq += __shfl_xor_sync(0xffffffffu, sq, off);
    __shared__ float rsum[16];
    __shared__ float rscale;
    if (lane == 0) rsum[wid] = sq;
    __syncthreads();
    if (d == 0) {
        float s = 0.f;
        #pragma unroll
        for (int w = 0; w < 16; ++w) s += rsum[w];
        rscale = rsqrtf(s / 512.f + 1e-5f);
    }
    __syncthreads();
    S_yn[row*512 + d] = y * rscale * norm_w[d];
}

// ---------------------------------------------------------------------------
// outp[b,h,g,c] = S_out[b*64+g, h*64+c]
__global__ void k_permute(float* __restrict__ outp) {
    int row = blockIdx.x;            // b*64+g
    int b = row >> 6, g = row & 63;
    int tid = threadIdx.x;           // 0..511
    int h = tid >> 6, c = tid & 63;
    outp[(((b*8 + h)*64 + g)*64) + c] = S_out[row*512 + tid];
}

// ---------------------------------------------------------------------------
// Fused: out_x tile (einsum) staged in smem, then x @ to_out_w^T + bias.
// Packed f32x2 math throughout. Grid: (49, 16), 256 threads.
#define OUTX_LD   514            // floats per outx row (even for 8B alignment)
#define BUFB_LD   66             // floats per bufB row
#define BUFW_LD   130            // floats per phase-2 W row
__global__ __launch_bounds__(256) void k_final(
    const float* __restrict__ sw, const float* __restrict__ outp,
    const float* __restrict__ W, const float* __restrict__ bias,
    float* __restrict__ out)
{
    extern __shared__ float sm[];
    float* outx = sm;                        // [64][514]
    float* bufA = sm + 64*OUTX_LD;           // phase1: sw [64][65]; phase2: W [16][130]
    float* bufB = bufA + 64*65;              // phase1: outp [64][66]
    unsigned long long* outx64 = (unsigned long long*)outx;
    unsigned long long* bufB64 = (unsigned long long*)bufB;
    unsigned long long* bufW64 = (unsigned long long*)bufA;
    int tid = threadIdx.x;
    int tx = tid & 15, ty = tid >> 4;
    int n0 = blockIdx.x * 64;
    int b  = blockIdx.y;

    // ---- phase 1: outx[m][h*64+c] = sum_g sw[b,h,n0+m,g] * outp[b,h,g,c]
    for (int h = 0; h < 8; ++h) {
        const float* swb = sw + ((size_t)(b*8 + h)*NCTX + n0)*64;
        #pragma unroll
        for (int p = 0; p < 16; ++p) {
            int idx = tid + p*256;
            int m = idx >> 6, g = idx & 63;
            float v = 0.f;
            if (n0 + m < NCTX) v = swb[m*64 + g];
            bufA[m*65 + g] = v;
        }
        const float* ob = outp + (size_t)(b*8 + h)*64*64;
        #pragma unroll
        for (int p = 0; p < 16; ++p) {
            int idx = tid + p*256;
            int g = idx >> 6, c = idx & 63;
            bufB[g*BUFB_LD + c] = ob[idx];
        }
        __syncthreads();
        unsigned long long acc1[4][2] = {};
        #pragma unroll 8
        for (int g = 0; g < 64; ++g) {
            unsigned long long a2[4], w2[2];
            #pragma unroll
            for (int i = 0; i < 4; ++i) a2[i] = pk2(bufA[(ty + 16*i)*65 + g]);
            #pragma unroll
            for (int j = 0; j < 2; ++j) w2[j] = bufB64[g*(BUFB_LD/2) + tx + 16*j];
            #pragma unroll
            for (int i = 0; i < 4; ++i)
                #pragma unroll
                for (int j = 0; j < 2; ++j) FMA2(acc1[i][j], a2[i], w2[j]);
        }
        __syncthreads();
        #pragma unroll
        for (int i = 0; i < 4; ++i)
            #pragma unroll
            for (int j = 0; j < 2; ++j)
                outx64[(ty + 16*i)*(OUTX_LD/2) + h*32 + tx + 16*j] = acc1[i][j];
    }
    __syncthreads();

    // ---- phase 2: out[b, n0+m, :] = outx[m, :] @ W^T + bias
    for (int nc = 0; nc < 4; ++nc) {
        int nbase = nc*128;
        unsigned long long acc[4][4] = {};
        for (int kt = 0; kt < 32; ++kt) {
            int k0 = kt*16;
            #pragma unroll
            for (int p = 0; p < 8; ++p) {
                int idx = tid + p*256;
                int n = idx >> 4, kk = idx & 15;
                bufA[kk*BUFW_LD + n] = W[(nbase + n)*512 + k0 + kk];
            }
            __syncthreads();
            #pragma unroll
            for (int kk = 0; kk < 16; ++kk) {
                unsigned long long a2[4], w2[4];
                #pragma unroll
                for (int i = 0; i < 4; ++i) a2[i] = pk2(outx[(ty + 16*i)*OUTX_LD + k0 + kk]);
                #pragma unroll
                for (int j = 0; j < 4; ++j) w2[j] = bufW64[kk*(BUFW_LD/2) + tx + 16*j];
                #pragma unroll
                for (int i = 0; i < 4; ++i)
                    #pragma unroll
                    for (int j = 0; j < 4; ++j) FMA2(acc[i][j], a2[i], w2[j]);
            }
            __syncthreads();
        }
        #pragma unroll
        for (int i = 0; i < 4; ++i) {
            int m = ty + 16*i;
            if (n0 + m < NCTX) {
                size_t ro = ((size_t)b*NCTX + n0 + m)*512 + nbase;
                #pragma unroll
                for (int j = 0; j < 4; ++j) {
                    int n = 2*tx + 32*j;
                    float lo, hi;
                    upk2(acc[i][j], lo, hi);
                    float2 r;
                    r.x = lo + bias[nbase + n];
                    r.y = hi + bias[nbase + n + 1];
                    *(float2*)&out[ro + n] = r;
                }
            }
        }
    }
}

// ---------------------------------------------------------------------------
extern "C" void kernel_launch(void* const* d_in, const int* in_sizes, int n_in,
                              void* d_out, int out_size) {
    const float* st     = (const float*)d_in[0];
    const float* sw     = (const float*)d_in[1];
    const float* w_in   = (const float*)d_in[2];
    const float* conv_w = (const float*)d_in[3];
    const float* conv_b = (const float*)d_in[4];
    const float* dt_bias= (const float*)d_in[5];
    const float* A_log  = (const float*)d_in[6];
    const float* Dv     = (const float*)d_in[7];
    const float* fc_D_w = (const float*)d_in[8];
    const float* norm_w = (const float*)d_in[9];
    const float* w_out  = (const float*)d_in[10];
    const float* to_w   = (const float*)d_in[11];
    const float* to_b   = (const float*)d_in[12];

    float* out       = (float*)d_out;
    float* out_final = out;                                   // 16*3131*512
    float* out_inp   = out + (size_t)B16*NCTX*DM512;          // 16*8*64*64
    float* out_outp  = out_inp + (size_t)B16*8*64*64;         // 16*8*64*64

    float *pSu, *pSzx, *pSyn, *pSout;
    cudaGetSymbolAddress((void**)&pSu,  S_u);
    cudaGetSymbolAddress((void**)&pSzx, S_zx);
    cudaGetSymbolAddress((void**)&pSyn, S_yn);
    cudaGetSymbolAddress((void**)&pSout,S_out);

    // inp passthrough
    cudaMemcpyAsync(out_inp, st, sizeof(float)*B16*8*64*64, cudaMemcpyDeviceToDevice);

    k_transpose_u<<<B16*L64, 512>>>(st);

    // zxbcdt = u @ w_in^T  (1024 x 1042 x 512)
    k_gemm_xwt<<<dim3((DINPROJ + 63)/64, B16*L64/64), 256>>>(pSu, w_in, pSzx, B16*L64, DINPROJ, DM512);

    k_conv<<<B16*L64, 544>>>(conv_w, conv_b);
    k_scan<<<64, 256>>>(dt_bias, A_log);
    k_combine<<<B16*L64, 512>>>(fc_D_w, Dv, norm_w);

    // out = y @ w_out^T (1024 x 512 x 512)
    k_gemm_xwt<<<dim3(DM512/64, B16*L64/64), 256>>>(pSyn, w_out, pSout, B16*L64, DM512, DM512);

    k_permute<<<B16*L64, 512>>>(out_outp);

    // fused einsum + final projection
    int smem_bytes = (64*OUTX_LD + 64*65 + 64*BUFB_LD) * (int)sizeof(float);
    cudaFuncSetAttribute(k_final, cudaFuncAttributeMaxDynamicSharedMemorySize, smem_bytes);
    k_final<<<dim3((NCTX + 63)/64, B16), 256, smem_bytes>>>(sw, out_outp, to_w, to_b, out_final);
}

// round 4
// speedup vs baseline: 3.4606x; 2.7252x over previous
#include <cuda_runtime.h>
#include <cuda_bf16.h>
#include <math.h>
#include <stdint.h>

// Problem constants
#define B16    16
#define L64    64
#define DM512  512
#define NCTX   3131
#define DINPROJ 1042
#define CONVDIM 514
#define MROWS  50096            // 16*3131
#define MPAD   50176            // 392*128

// Scratch (static device arrays; zero-initialized, allocation-free)
__device__ float S_u  [B16*L64*DM512];
__device__ float S_zx [B16*L64*DINPROJ];
__device__ float S_x  [B16*L64*DM512];
__device__ float S_Bv [B16*L64];
__device__ float S_Cv [B16*L64];
__device__ float S_ys [2*B16*L64*DM512];
__device__ float S_yn [B16*L64*DM512];
__device__ float S_out[B16*L64*DM512];
__device__ __nv_bfloat16 S_Ahi[(size_t)MPAD*DM512];
__device__ __nv_bfloat16 S_Alo[(size_t)MPAD*DM512];
__device__ __nv_bfloat16 S_Whi[DM512*DM512];
__device__ __nv_bfloat16 S_Wlo[DM512*DM512];

// ---- packed f32x2 helpers (FFMA2) -----------------------------------------
__device__ __forceinline__ unsigned long long pk2(float x) {
    unsigned long long r;
    asm("mov.b64 %0, {%1, %1};" : "=l"(r) : "f"(x));
    return r;
}
__device__ __forceinline__ void upk2(unsigned long long v, float& lo, float& hi) {
    asm("mov.b64 {%0, %1}, %2;" : "=f"(lo), "=f"(hi) : "l"(v));
}
#define FMA2(d, a, b) asm("fma.rn.f32x2 %0, %1, %2, %0;" : "+l"(d) : "l"(a), "l"(b))

// ---- mma.sync helpers ------------------------------------------------------
__device__ __forceinline__ void mma16816(float* c, const uint32_t* a, const uint32_t* b) {
    asm volatile(
        "mma.sync.aligned.m16n8k16.row.col.f32.bf16.bf16.f32 "
        "{%0,%1,%2,%3}, {%4,%5,%6,%7}, {%8,%9}, {%0,%1,%2,%3};"
        : "+f"(c[0]), "+f"(c[1]), "+f"(c[2]), "+f"(c[3])
        : "r"(a[0]), "r"(a[1]), "r"(a[2]), "r"(a[3]), "r"(b[0]), "r"(b[1]));
}
__device__ __forceinline__ void bsplit(float v, __nv_bfloat16& h, __nv_bfloat16& l) {
    h = __float2bfloat16(v);
    l = __float2bfloat16(v - __bfloat162float(h));
}
__device__ __forceinline__ void bsplit2(float v0, float v1, uint32_t& hh, uint32_t& ll) {
    __nv_bfloat16 h0, l0, h1, l1;
    bsplit(v0, h0, l0);
    bsplit(v1, h1, l1);
    __nv_bfloat162 H; H.x = h0; H.y = h1;
    __nv_bfloat162 L; L.x = l0; L.y = l1;
    hh = *(uint32_t*)&H;
    ll = *(uint32_t*)&L;
}

// ---- cp.async helpers ------------------------------------------------------
__device__ __forceinline__ void cp16(void* dst, const void* src) {
    uint32_t d = (uint32_t)__cvta_generic_to_shared(dst);
    asm volatile("cp.async.cg.shared.global [%0], [%1], 16;" :: "r"(d), "l"(src));
}
#define CP_COMMIT() asm volatile("cp.async.commit_group;" ::: "memory")
#define CP_WAIT1()  asm volatile("cp.async.wait_group 1;" ::: "memory")
#define CP_WAIT0()  asm volatile("cp.async.wait_group 0;" ::: "memory")

// ---------------------------------------------------------------------------
// u[b,g,h*64+c] = slice_token[b,h,g,c]
__global__ void k_transpose_u(const float* __restrict__ st) {
    int row = blockIdx.x;
    int b = row >> 6, g = row & 63;
    int tid = threadIdx.x;
    int h = tid >> 6, c = tid & 63;
    S_u[row*DM512 + tid] = st[(((b*8 + h)*64) + g)*64 + c];
}

// ---------------------------------------------------------------------------
// Generic C[m,n] = sum_k A[m,k] * Bm[n,k]  (FFMA2)
__global__ __launch_bounds__(256) void k_gemm_xwt(
    const float* __restrict__ A, const float* __restrict__ Bm,
    float* __restrict__ C, int M, int N, int K)
{
    __shared__ float As[16*65];
    __shared__ __align__(16) float Bs[16*66];
    unsigned long long* Bs64 = (unsigned long long*)Bs;
    int tid = threadIdx.x;
    int tx = tid & 15, ty = tid >> 4;
    int m0 = blockIdx.y * 64, n0 = blockIdx.x * 64;
    unsigned long long acc[4][2] = {};
    for (int k0 = 0; k0 < K; k0 += 16) {
        #pragma unroll
        for (int p = 0; p < 4; ++p) {
            int idx = tid + p*256;
            int m = idx >> 4, kk = idx & 15;
            As[kk*65 + m] = A[(m0 + m)*K + k0 + kk];
        }
        #pragma unroll
        for (int p = 0; p < 4; ++p) {
            int idx = tid + p*256;
            int n = idx >> 4, kk = idx & 15;
            float v = 0.f;
            if (n0 + n < N) v = Bm[(n0 + n)*K + k0 + kk];
            Bs[kk*66 + n] = v;
        }
        __syncthreads();
        #pragma unroll
        for (int kk = 0; kk < 16; ++kk) {
            unsigned long long a2[4], w2[2];
            #pragma unroll
            for (int i = 0; i < 4; ++i) a2[i] = pk2(As[kk*65 + ty + 16*i]);
            #pragma unroll
            for (int j = 0; j < 2; ++j) w2[j] = Bs64[kk*33 + tx + 16*j];
            #pragma unroll
            for (int i = 0; i < 4; ++i)
                #pragma unroll
                for (int j = 0; j < 2; ++j) FMA2(acc[i][j], a2[i], w2[j]);
        }
        __syncthreads();
    }
    #pragma unroll
    for (int i = 0; i < 4; ++i)
        #pragma unroll
        for (int j = 0; j < 2; ++j) {
            int n = n0 + 2*tx + 32*j;
            float lo, hi;
            upk2(acc[i][j], lo, hi);
            if (n < N)     C[(m0 + ty + 16*i)*N + n]     = lo;
            if (n + 1 < N) C[(m0 + ty + 16*i)*N + n + 1] = hi;
        }
}

// ---------------------------------------------------------------------------
__global__ void k_conv(const float* __restrict__ conv_w, const float* __restrict__ conv_b) {
    int row = blockIdx.x;
    int t = row & 63;
    int c = threadIdx.x;
    if (c >= CONVDIM) return;
    float acc = conv_b[c];
    #pragma unroll
    for (int k = 0; k < 3; ++k) {
        int tt = t + k - 2;
        if (tt >= 0) acc += conv_w[c*3 + k] * S_zx[(row + (k - 2))*DINPROJ + 512 + c];
    }
    acc = acc / (1.f + expf(-acc));
    if (c < 512)       S_x[row*512 + c] = acc;
    else if (c == 512) S_Bv[row] = acc;
    else               S_Cv[row] = acc;
}

// ---------------------------------------------------------------------------
__global__ void k_scan(const float* __restrict__ dt_bias, const float* __restrict__ A_log) {
    int gid = blockIdx.x * blockDim.x + threadIdx.x;
    int i = gid >> 9;
    int d = gid & 511;
    int h = d >> 6;
    bool bw = (i >= 16);
    int b = bw ? i - 16 : i;
    float Ah = -expf(A_log[h]);
    float bias = dt_bias[h];
    int dtoff = bw ? (1026 + 8 + h) : (1026 + h);
    float hs = 0.f;
    S_ys[(i*64 + 0)*512 + d] = 0.f;
    for (int t = 0; t < 64; ++t) {
        int tt = bw ? (63 - t) : t;
        int row = b*64 + tt;
        float x  = S_x[row*512 + d];
        float Bc = S_Bv[row];
        float Cc = S_Cv[row];
        float v  = S_zx[row*DINPROJ + dtoff] + bias;
        float dt = (v > 20.f) ? v : log1pf(expf(v));
        float a  = expf(dt * Ah);
        hs = a*hs + dt*Bc*x;
        if (t < 63) S_ys[(i*64 + t + 1)*512 + d] = hs * Cc;
    }
}

// ---------------------------------------------------------------------------
__global__ __launch_bounds__(512) void k_combine(
    const float* __restrict__ fc_D_w, const float* __restrict__ Dv,
    const float* __restrict__ norm_w)
{
    int row = blockIdx.x;
    int b = row >> 6, t = row & 63;
    int d = threadIdx.x;
    int h = d >> 6;
    int lane = d & 31, wid = d >> 5;

    float x  = S_x[row*512 + d];
    float z  = S_zx[row*DINPROJ + d];
    float yf = S_ys[row*512 + d];
    float yb = S_ys[((16 + b)*64 + (63 - t))*512 + d];

    float px[8];
    #pragma unroll
    for (int hh = 0; hh < 8; ++hh) px[hh] = x * fc_D_w[hh*512 + d];
    #pragma unroll
    for (int off = 16; off; off >>= 1)
        #pragma unroll
        for (int hh = 0; hh < 8; ++hh) px[hh] += __shfl_xor_sync(0xffffffffu, px[hh], off);

    __shared__ float wsum[16][8];
    __shared__ float dcf[8];
    if (lane == 0) {
        #pragma unroll
        for (int hh = 0; hh < 8; ++hh) wsum[wid][hh] = px[hh];
    }
    __syncthreads();
    if (d < 8) {
        float s = 0.f;
        #pragma unroll
        for (int w = 0; w < 16; ++w) s += wsum[w][d];
        dcf[d] = s + Dv[d];
    }
    __syncthreads();

    float y = yf + yb + x * dcf[h];
    y *= z / (1.f + expf(-z));

    float sq = y*y;
    #pragma unroll
    for (int off = 16; off; off >>= 1) sq += __shfl_xor_sync(0xffffffffu, sq, off);
    __shared__ float rsum[16];
    __shared__ float rscale;
    if (lane == 0) rsum[wid] = sq;
    __syncthreads();
    if (d == 0) {
        float s = 0.f;
        #pragma unroll
        for (int w = 0; w < 16; ++w) s += rsum[w];
        rscale = rsqrtf(s / 512.f + 1e-5f);
    }
    __syncthreads();
    S_yn[row*512 + d] = y * rscale * norm_w[d];
}

// ---------------------------------------------------------------------------
__global__ void k_permute(float* __restrict__ outp) {
    int row = blockIdx.x;
    int b = row >> 6, g = row & 63;
    int tid = threadIdx.x;
    int h = tid >> 6, c = tid & 63;
    outp[(((b*8 + h)*64 + g)*64) + c] = S_out[row*512 + tid];
}

// ---------------------------------------------------------------------------
// Pre-split to_out_w into bf16 hi/lo
__global__ void k_prepW(const float* __restrict__ W) {
    int i = blockIdx.x * blockDim.x + threadIdx.x;
    float v = W[i];
    __nv_bfloat16 h, l;
    bsplit(v, h, l);
    S_Whi[i] = h;
    S_Wlo[i] = l;
}

// ---------------------------------------------------------------------------
// Einsum via mma.sync split-bf16:
// outx[r=b*NCTX+n][h*64+c] = sum_g sw[b,h,n,g] * S_out[(b*64+g)*512 + h*64+c]
// Writes split bf16 into S_Ahi/S_Alo. Grid (25, 16), 256 threads (8 warps).
// Warp grid 4x2: warp tile 32 rows x 32 cols of the per-head 128x64 output.
// smem (bf16, stride 72): Ah[128][72] @0, Al @18432, Bh[64][72] @36864, Bl @46080
#define ES_SMEM 55296
__global__ __launch_bounds__(256) void k_einsum_mma(const float* __restrict__ sw) {
    extern __shared__ __nv_bfloat16 smE[];
    __nv_bfloat16* Ah = smE;
    __nv_bfloat16* Al = smE + 128*72;
    __nv_bfloat16* Bh = smE + 2*128*72;
    __nv_bfloat16* Bl = Bh + 64*72;

    int tid = threadIdx.x;
    int wid = tid >> 5, lane = tid & 31;
    int warp_m = wid & 3, warp_n = wid >> 2;
    int lr = lane >> 2;          // 0..7
    int lk = (lane & 3) * 2;     // 0,2,4,6
    int n0 = blockIdx.x * 128;
    int b  = blockIdx.y;
    size_t rbase = (size_t)b * NCTX + n0;

    for (int h = 0; h < 8; ++h) {
        __syncthreads();
        // stage A = sw[b,h,n0+m,g]  (128 x 64)
        const float* swb = sw + ((size_t)(b*8 + h)*NCTX + n0)*64;
        #pragma unroll
        for (int p = 0; p < 32; ++p) {
            int idx = tid + p*256;
            int m = idx >> 6, g = idx & 63;
            float v = 0.f;
            if (n0 + m < NCTX) v = swb[m*64 + g];
            __nv_bfloat16 vh, vl;
            bsplit(v, vh, vl);
            Ah[m*72 + g] = vh;
            Al[m*72 + g] = vl;
        }
        // stage B[c][g] = S_out[(b*64+g)*512 + h*64 + c]  (64 x 64, transposed)
        #pragma unroll
        for (int p = 0; p < 16; ++p) {
            int idx = tid + p*256;
            int g = idx >> 6, c = idx & 63;
            float v = S_out[(size_t)(b*64 + g)*512 + h*64 + c];
            __nv_bfloat16 vh, vl;
            bsplit(v, vh, vl);
            Bh[c*72 + g] = vh;
            Bl[c*72 + g] = vl;
        }
        __syncthreads();

        float acc[2][4][4];
        #pragma unroll
        for (int mt = 0; mt < 2; ++mt)
            #pragma unroll
            for (int nt = 0; nt < 4; ++nt)
                #pragma unroll
                for (int q = 0; q < 4; ++q) acc[mt][nt][q] = 0.f;

        #pragma unroll
        for (int ks = 0; ks < 4; ++ks) {
            int k0 = ks*16;
            uint32_t ah[2][4], al[2][4], bh[4][2], bl[4][2];
            #pragma unroll
            for (int mt = 0; mt < 2; ++mt) {
                int rb = warp_m*32 + mt*16 + lr;
                const __nv_bfloat16* pa = &Ah[rb*72 + k0 + lk];
                ah[mt][0] = *(const uint32_t*)pa;
                ah[mt][1] = *(const uint32_t*)(pa + 8*72);
                ah[mt][2] = *(const uint32_t*)(pa + 8);
                ah[mt][3] = *(const uint32_t*)(pa + 8*72 + 8);
                const __nv_bfloat16* pl = &Al[rb*72 + k0 + lk];
                al[mt][0] = *(const uint32_t*)pl;
                al[mt][1] = *(const uint32_t*)(pl + 8*72);
                al[mt][2] = *(const uint32_t*)(pl + 8);
                al[mt][3] = *(const uint32_t*)(pl + 8*72 + 8);
            }
            #pragma unroll
            for (int nt = 0; nt < 4; ++nt) {
                int nb = warp_n*32 + nt*8 + lr;
                const __nv_bfloat16* pb = &Bh[nb*72 + k0 + lk];
                bh[nt][0] = *(const uint32_t*)pb;
                bh[nt][1] = *(const uint32_t*)(pb + 8);
                const __nv_bfloat16* pl = &Bl[nb*72 + k0 + lk];
                bl[nt][0] = *(const uint32_t*)pl;
                bl[nt][1] = *(const uint32_t*)(pl + 8);
            }
            #pragma unroll
            for (int mt = 0; mt < 2; ++mt)
                #pragma unroll
                for (int nt = 0; nt < 4; ++nt) {
                    mma16816(acc[mt][nt], ah[mt], bh[nt]);
                    mma16816(acc[mt][nt], ah[mt], bl[nt]);
                    mma16816(acc[mt][nt], al[mt], bh[nt]);
                }
        }

        // epilogue: split accumulators -> S_Ahi/S_Alo
        #pragma unroll
        for (int mt = 0; mt < 2; ++mt) {
            int m = warp_m*32 + mt*16 + lr;
            #pragma unroll
            for (int nt = 0; nt < 4; ++nt) {
                int col = h*64 + warp_n*32 + nt*8 + lk;
                if (n0 + m < NCTX) {
                    uint32_t hh, ll;
                    bsplit2(acc[mt][nt][0], acc[mt][nt][1], hh, ll);
                    *(uint32_t*)&S_Ahi[(rbase + m)*512 + col] = hh;
                    *(uint32_t*)&S_Alo[(rbase + m)*512 + col] = ll;
                }
                if (n0 + m + 8 < NCTX) {
                    uint32_t hh, ll;
                    bsplit2(acc[mt][nt][2], acc[mt][nt][3], hh, ll);
                    *(uint32_t*)&S_Ahi[(rbase + m + 8)*512 + col] = hh;
                    *(uint32_t*)&S_Alo[(rbase + m + 8)*512 + col] = ll;
                }
            }
        }
    }
}

// ---------------------------------------------------------------------------
// Final GEMM: out[r, :] = A[r, :] @ W^T + bias   (mma.sync split-bf16)
// Grid (392, 4), 256 threads (8 warps). BM=128, BN=128, BK=32, 16 k-chunks,
// cp.async double-buffered. Warp grid 2x4: warp tile 64 rows x 32 cols.
// smem per buffer (bf16, stride 40): Ah 128x40, Al, Wh 128x40, Wl = 40960 B; x2.
#define GM_SMEM 81920
__global__ __launch_bounds__(256) void k_gemm_mma(
    const float* __restrict__ bias, float* __restrict__ out)
{
    extern __shared__ __nv_bfloat16 smG[];
    int tid = threadIdx.x;
    int wid = tid >> 5, lane = tid & 31;
    int warp_m = wid & 1, warp_n = wid >> 1;
    int lr = lane >> 2;
    int lk = (lane & 3) * 2;
    int tile = blockIdx.x;
    int n0 = blockIdx.y * 128;
    size_t rbase = (size_t)tile * 128;

    const int BUF = 4*128*40;    // bf16 elems per buffer (Ah,Al,Wh,Wl)
    int m_st = tid >> 2;         // 0..63 (+64 on second pass)
    int kp_st = tid & 3;

    // stage(kc, buf): 8 cp.async per thread
    auto stage = [&](int kc, int buf) {
        __nv_bfloat16* Ah = smG + buf*BUF;
        __nv_bfloat16* Al = Ah + 128*40;
        __nv_bfloat16* Wh = Al + 128*40;
        __nv_bfloat16* Wl = Wh + 128*40;
        int kofs = kc*32 + kp_st*8;
        #pragma unroll
        for (int p = 0; p < 2; ++p) {
            int m = m_st + p*64;
            size_t ga = (rbase + m)*512 + kofs;
            cp16(&Ah[m*40 + kp_st*8], &S_Ahi[ga]);
            cp16(&Al[m*40 + kp_st*8], &S_Alo[ga]);
            size_t gw = (size_t)(n0 + m)*512 + kofs;
            cp16(&Wh[m*40 + kp_st*8], &S_Whi[gw]);
            cp16(&Wl[m*40 + kp_st*8], &S_Wlo[gw]);
        }
    };

    float acc[4][4][4];
    #pragma unroll
    for (int mt = 0; mt < 4; ++mt)
        #pragma unroll
        for (int nt = 0; nt < 4; ++nt)
            #pragma unroll
            for (int q = 0; q < 4; ++q) acc[mt][nt][q] = 0.f;

    stage(0, 0);
    CP_COMMIT();

    for (int kc = 0; kc < 16; ++kc) {
        int cur = kc & 1;
        if (kc < 15) { stage(kc + 1, cur ^ 1); CP_COMMIT(); CP_WAIT1(); }
        else         { CP_WAIT0(); }
        __syncthreads();

        __nv_bfloat16* Ah = smG + cur*BUF;
        __nv_bfloat16* Al = Ah + 128*40;
        __nv_bfloat16* Wh = Al + 128*40;
        __nv_bfloat16* Wl = Wh + 128*40;

        #pragma unroll
        for (int ks = 0; ks < 2; ++ks) {
            int k0 = ks*16;
            uint32_t ah[4][4], al[4][4], bh[4][2], bl[4][2];
            #pragma unroll
            for (int mt = 0; mt < 4; ++mt) {
                int rb = warp_m*64 + mt*16 + lr;
                const __nv_bfloat16* pa = &Ah[rb*40 + k0 + lk];
                ah[mt][0] = *(const uint32_t*)pa;
                ah[mt][1] = *(const uint32_t*)(pa + 8*40);
                ah[mt][2] = *(const uint32_t*)(pa + 8);
                ah[mt][3] = *(const uint32_t*)(pa + 8*40 + 8);
                const __nv_bfloat16* pl = &Al[rb*40 + k0 + lk];
                al[mt][0] = *(const uint32_t*)pl;
                al[mt][1] = *(const uint32_t*)(pl + 8*40);
                al[mt][2] = *(const uint32_t*)(pl + 8);
                al[mt][3] = *(const uint32_t*)(pl + 8*40 + 8);
            }
            #pragma unroll
            for (int nt = 0; nt < 4; ++nt) {
                int nb = warp_n*32 + nt*8 + lr;
                const __nv_bfloat16* pb = &Wh[nb*40 + k0 + lk];
                bh[nt][0] = *(const uint32_t*)pb;
                bh[nt][1] = *(const uint32_t*)(pb + 8);
                const __nv_bfloat16* pl = &Wl[nb*40 + k0 + lk];
                bl[nt][0] = *(const uint32_t*)pl;
                bl[nt][1] = *(const uint32_t*)(pl + 8);
            }
            #pragma unroll
            for (int mt = 0; mt < 4; ++mt)
                #pragma unroll
                for (int nt = 0; nt < 4; ++nt) {
                    mma16816(acc[mt][nt], ah[mt], bh[nt]);
                    mma16816(acc[mt][nt], ah[mt], bl[nt]);
                    mma16816(acc[mt][nt], al[mt], bh[nt]);
                }
        }
        __syncthreads();
    }

    // epilogue
    #pragma unroll
    for (int mt = 0; mt < 4; ++mt) {
        int m = warp_m*64 + mt*16 + lr;
        #pragma unroll
        for (int nt = 0; nt < 4; ++nt) {
            int col = n0 + warp_n*32 + nt*8 + lk;
            float b0 = __ldg(&bias[col]);
            float b1 = __ldg(&bias[col + 1]);
            size_t r = rbase + m;
            if (r < MROWS) {
                float2 v;
                v.x = acc[mt][nt][0] + b0;
                v.y = acc[mt][nt][1] + b1;
                *(float2*)&out[r*512 + col] = v;
            }
            if (r + 8 < MROWS) {
                float2 v;
                v.x = acc[mt][nt][2] + b0;
                v.y = acc[mt][nt][3] + b1;
                *(float2*)&out[(r + 8)*512 + col] = v;
            }
        }
    }
}

// ---------------------------------------------------------------------------
extern "C" void kernel_launch(void* const* d_in, const int* in_sizes, int n_in,
                              void* d_out, int out_size) {
    const float* st     = (const float*)d_in[0];
    const float* sw     = (const float*)d_in[1];
    const float* w_in   = (const float*)d_in[2];
    const float* conv_w = (const float*)d_in[3];
    const float* conv_b = (const float*)d_in[4];
    const float* dt_bias= (const float*)d_in[5];
    const float* A_log  = (const float*)d_in[6];
    const float* Dv     = (const float*)d_in[7];
    const float* fc_D_w = (const float*)d_in[8];
    const float* norm_w = (const float*)d_in[9];
    const float* w_out  = (const float*)d_in[10];
    const float* to_w   = (const float*)d_in[11];
    const float* to_b   = (const float*)d_in[12];

    float* out       = (float*)d_out;
    float* out_final = out;
    float* out_inp   = out + (size_t)B16*NCTX*DM512;
    float* out_outp  = out_inp + (size_t)B16*8*64*64;

    float *pSu, *pSzx, *pSyn, *pSout;
    cudaGetSymbolAddress((void**)&pSu,  S_u);
    cudaGetSymbolAddress((void**)&pSzx, S_zx);
    cudaGetSymbolAddress((void**)&pSyn, S_yn);
    cudaGetSymbolAddress((void**)&pSout,S_out);

    cudaMemcpyAsync(out_inp, st, sizeof(float)*B16*8*64*64, cudaMemcpyDeviceToDevice);

    k_transpose_u<<<B16*L64, 512>>>(st);
    k_gemm_xwt<<<dim3((DINPROJ + 63)/64, B16*L64/64), 256>>>(pSu, w_in, pSzx, B16*L64, DINPROJ, DM512);
    k_conv<<<B16*L64, 544>>>(conv_w, conv_b);
    k_scan<<<64, 256>>>(dt_bias, A_log);
    k_combine<<<B16*L64, 512>>>(fc_D_w, Dv, norm_w);
    k_gemm_xwt<<<dim3(DM512/64, B16*L64/64), 256>>>(pSyn, w_out, pSout, B16*L64, DM512, DM512);
    k_permute<<<B16*L64, 512>>>(out_outp);

    k_prepW<<<DM512, DM512>>>(to_w);

    cudaFuncSetAttribute(k_einsum_mma, cudaFuncAttributeMaxDynamicSharedMemorySize, ES_SMEM);
    k_einsum_mma<<<dim3((NCTX + 127)/128, B16), 256, ES_SMEM>>>(sw);

    cudaFuncSetAttribute(k_gemm_mma, cudaFuncAttributeMaxDynamicSharedMemorySize, GM_SMEM);
    k_gemm_mma<<<dim3(MPAD/128, 4), 256, GM_SMEM>>>(to_b, out_final);
}

// round 5
// speedup vs baseline: 4.2598x; 1.2309x over previous
#include <cuda_runtime.h>
#include <cuda_bf16.h>
#include <math.h>
#include <stdint.h>

// Problem constants
#define B16    16
#define L64    64
#define DM512  512
#define NCTX   3131
#define DINPROJ 1042
#define CONVDIM 514
#define MROWS  50096            // 16*3131

// Scratch (static device arrays; zero-initialized, allocation-free)
__device__ float S_zx [B16*L64*DINPROJ];
__device__ float S_x  [B16*L64*DM512];
__device__ float S_Bv [B16*L64];
__device__ float S_Cv [B16*L64];
__device__ float S_ys [2*B16*L64*DM512];
__device__ float S_out[B16*L64*DM512];
// split-bf16 operands
__device__ __nv_bfloat16 S_uhi [B16*L64*DM512];
__device__ __nv_bfloat16 S_ulo [B16*L64*DM512];
__device__ __nv_bfloat16 S_ynhi[B16*L64*DM512];
__device__ __nv_bfloat16 S_ynlo[B16*L64*DM512];
__device__ __nv_bfloat16 S_W1hi[1152*DM512];   // w_in padded rows (zero pad)
__device__ __nv_bfloat16 S_W1lo[1152*DM512];
__device__ __nv_bfloat16 S_W2hi[DM512*DM512];  // w_out
__device__ __nv_bfloat16 S_W2lo[DM512*DM512];
__device__ __nv_bfloat16 S_Whi [DM512*DM512];  // to_out_w
__device__ __nv_bfloat16 S_Wlo [DM512*DM512];
__device__ __nv_bfloat16 S_Pthi[(size_t)B16*DM512*DM512];  // Pt[b][d][hg]
__device__ __nv_bfloat16 S_Ptlo[(size_t)B16*DM512*DM512];

// ---- helpers ---------------------------------------------------------------
__device__ __forceinline__ void mma16816(float* c, const uint32_t* a, const uint32_t* b) {
    asm volatile(
        "mma.sync.aligned.m16n8k16.row.col.f32.bf16.bf16.f32 "
        "{%0,%1,%2,%3}, {%4,%5,%6,%7}, {%8,%9}, {%0,%1,%2,%3};"
        : "+f"(c[0]), "+f"(c[1]), "+f"(c[2]), "+f"(c[3])
        : "r"(a[0]), "r"(a[1]), "r"(a[2]), "r"(a[3]), "r"(b[0]), "r"(b[1]));
}
__device__ __forceinline__ void bsplit(float v, __nv_bfloat16& h, __nv_bfloat16& l) {
    h = __float2bfloat16(v);
    l = __float2bfloat16(v - __bfloat162float(h));
}
__device__ __forceinline__ void bsplit2(float v0, float v1, uint32_t& hh, uint32_t& ll) {
    __nv_bfloat16 h0, l0, h1, l1;
    bsplit(v0, h0, l0);
    bsplit(v1, h1, l1);
    __nv_bfloat162 H; H.x = h0; H.y = h1;
    __nv_bfloat162 L; L.x = l0; L.y = l1;
    hh = *(uint32_t*)&H;
    ll = *(uint32_t*)&L;
}
__device__ __forceinline__ void cp16(void* dst, const void* src) {
    uint32_t d = (uint32_t)__cvta_generic_to_shared(dst);
    asm volatile("cp.async.cg.shared.global [%0], [%1], 16;" :: "r"(d), "l"(src));
}
#define CP_COMMIT() asm volatile("cp.async.commit_group;" ::: "memory")
#define CP_WAIT1()  asm volatile("cp.async.wait_group 1;" ::: "memory")
#define CP_WAIT0()  asm volatile("cp.async.wait_group 0;" ::: "memory")

// ---------------------------------------------------------------------------
// split source fp32 -> bf16 hi/lo
__global__ void k_split(const float* __restrict__ src,
                        __nv_bfloat16* __restrict__ hi,
                        __nv_bfloat16* __restrict__ lo, int n) {
    int i = blockIdx.x * blockDim.x + threadIdx.x;
    if (i >= n) return;
    __nv_bfloat16 h, l;
    bsplit(src[i], h, l);
    hi[i] = h;
    lo[i] = l;
}

// ---------------------------------------------------------------------------
// u[b,g,h*64+c] = slice_token[b,h,g,c]  -> split bf16
__global__ void k_transpose_u(const float* __restrict__ st) {
    int row = blockIdx.x;            // b*64+g
    int b = row >> 6, g = row & 63;
    int tid = threadIdx.x;           // 0..511
    int h = tid >> 6, c = tid & 63;
    float v = st[(((b*8 + h)*64) + g)*64 + c];
    __nv_bfloat16 vh, vl;
    bsplit(v, vh, vl);
    S_uhi[row*DM512 + tid] = vh;
    S_ulo[row*DM512 + tid] = vl;
}

// ---------------------------------------------------------------------------
// Presplit GEMM: C[m,n] = sum_k A[m,k]*B[n,k], A/B split bf16, M=1024, K=512.
// Grid (M/128, ceil(N/128)); BK=32 double-buffered cp.async, 8 warps 64x32.
#define GS_SMEM 81920
__global__ __launch_bounds__(256) void k_gemm_sp(
    const __nv_bfloat16* __restrict__ Ahi, const __nv_bfloat16* __restrict__ Alo,
    const __nv_bfloat16* __restrict__ Bhi, const __nv_bfloat16* __restrict__ Blo,
    float* __restrict__ C, int N)
{
    extern __shared__ __nv_bfloat16 smG[];
    int tid = threadIdx.x;
    int wid = tid >> 5, lane = tid & 31;
    int warp_m = wid & 1, warp_n = wid >> 1;
    int lr = lane >> 2;
    int lk = (lane & 3) * 2;
    size_t rbase = (size_t)blockIdx.x * 128;
    int n0 = blockIdx.y * 128;

    const int BUF = 4*128*40;
    int m_st = tid >> 2;
    int kp_st = tid & 3;

    auto stage = [&](int kc, int buf) {
        __nv_bfloat16* Ah = smG + buf*BUF;
        __nv_bfloat16* Al = Ah + 128*40;
        __nv_bfloat16* Wh = Al + 128*40;
        __nv_bfloat16* Wl = Wh + 128*40;
        int kofs = kc*32 + kp_st*8;
        #pragma unroll
        for (int p = 0; p < 2; ++p) {
            int m = m_st + p*64;
            size_t ga = (rbase + m)*512 + kofs;
            cp16(&Ah[m*40 + kp_st*8], &Ahi[ga]);
            cp16(&Al[m*40 + kp_st*8], &Alo[ga]);
            size_t gw = (size_t)(n0 + m)*512 + kofs;
            cp16(&Wh[m*40 + kp_st*8], &Bhi[gw]);
            cp16(&Wl[m*40 + kp_st*8], &Blo[gw]);
        }
    };

    float acc[4][4][4];
    #pragma unroll
    for (int mt = 0; mt < 4; ++mt)
        #pragma unroll
        for (int nt = 0; nt < 4; ++nt)
            #pragma unroll
            for (int q = 0; q < 4; ++q) acc[mt][nt][q] = 0.f;

    stage(0, 0);
    CP_COMMIT();

    for (int kc = 0; kc < 16; ++kc) {
        int cur = kc & 1;
        if (kc < 15) { stage(kc + 1, cur ^ 1); CP_COMMIT(); CP_WAIT1(); }
        else         { CP_WAIT0(); }
        __syncthreads();

        __nv_bfloat16* Ah = smG + cur*BUF;
        __nv_bfloat16* Al = Ah + 128*40;
        __nv_bfloat16* Wh = Al + 128*40;
        __nv_bfloat16* Wl = Wh + 128*40;

        #pragma unroll
        for (int ks = 0; ks < 2; ++ks) {
            int k0 = ks*16;
            uint32_t ah[4][4], al[4][4], bh[4][2], bl[4][2];
            #pragma unroll
            for (int mt = 0; mt < 4; ++mt) {
                int rb = warp_m*64 + mt*16 + lr;
                const __nv_bfloat16* pa = &Ah[rb*40 + k0 + lk];
                ah[mt][0] = *(const uint32_t*)pa;
                ah[mt][1] = *(const uint32_t*)(pa + 8*40);
                ah[mt][2] = *(const uint32_t*)(pa + 8);
                ah[mt][3] = *(const uint32_t*)(pa + 8*40 + 8);
                const __nv_bfloat16* pl = &Al[rb*40 + k0 + lk];
                al[mt][0] = *(const uint32_t*)pl;
                al[mt][1] = *(const uint32_t*)(pl + 8*40);
                al[mt][2] = *(const uint32_t*)(pl + 8);
                al[mt][3] = *(const uint32_t*)(pl + 8*40 + 8);
            }
            #pragma unroll
            for (int nt = 0; nt < 4; ++nt) {
                int nb = warp_n*32 + nt*8 + lr;
                const __nv_bfloat16* pb = &Wh[nb*40 + k0 + lk];
                bh[nt][0] = *(const uint32_t*)pb;
                bh[nt][1] = *(const uint32_t*)(pb + 8);
                const __nv_bfloat16* pl = &Wl[nb*40 + k0 + lk];
                bl[nt][0] = *(const uint32_t*)pl;
                bl[nt][1] = *(const uint32_t*)(pl + 8);
            }
            #pragma unroll
            for (int mt = 0; mt < 4; ++mt)
                #pragma unroll
                for (int nt = 0; nt < 4; ++nt) {
                    mma16816(acc[mt][nt], ah[mt], bh[nt]);
                    mma16816(acc[mt][nt], ah[mt], bl[nt]);
                    mma16816(acc[mt][nt], al[mt], bh[nt]);
                }
        }
        __syncthreads();
    }

    #pragma unroll
    for (int mt = 0; mt < 4; ++mt) {
        int m = warp_m*64 + mt*16 + lr;
        #pragma unroll
        for (int nt = 0; nt < 4; ++nt) {
            int col = n0 + warp_n*32 + nt*8 + lk;
            if (col < N) {   // N even, pair fits
                size_t r = rbase + m;
                float2 v0;
                v0.x = acc[mt][nt][0];
                v0.y = acc[mt][nt][1];
                *(float2*)&C[r*N + col] = v0;
                float2 v1;
                v1.x = acc[mt][nt][2];
                v1.y = acc[mt][nt][3];
                *(float2*)&C[(r + 8)*N + col] = v1;
            }
        }
    }
}

// ---------------------------------------------------------------------------
__global__ void k_conv(const float* __restrict__ conv_w, const float* __restrict__ conv_b) {
    int row = blockIdx.x;
    int t = row & 63;
    int c = threadIdx.x;
    if (c >= CONVDIM) return;
    float acc = conv_b[c];
    #pragma unroll
    for (int k = 0; k < 3; ++k) {
        int tt = t + k - 2;
        if (tt >= 0) acc += conv_w[c*3 + k] * S_zx[(row + (k - 2))*DINPROJ + 512 + c];
    }
    acc = acc / (1.f + expf(-acc));
    if (c < 512)       S_x[row*512 + c] = acc;
    else if (c == 512) S_Bv[row] = acc;
    else               S_Cv[row] = acc;
}

// ---------------------------------------------------------------------------
// Scan with smem staging: 32 CTAs (one per extended batch), 512 threads.
#define SC_SMEM (64*512*4 + 512*4 + 128*4)
__global__ __launch_bounds__(512) void k_scan(
    const float* __restrict__ dt_bias, const float* __restrict__ A_log)
{
    extern __shared__ float smS[];
    float* xs  = smS;              // [64][512]
    float* dts = smS + 64*512;     // [64][8]
    float* Bs  = dts + 512;        // [64]
    float* Cs  = Bs + 64;          // [64]

    int i = blockIdx.x;
    int d = threadIdx.x;
    bool bw = (i >= 16);
    int b = bw ? i - 16 : i;

    #pragma unroll
    for (int p = 0; p < 16; ++p) {
        int idx = d + p*512;
        int row = idx >> 7;
        int c4 = (idx & 127) * 4;
        cp16(&xs[row*512 + c4], &S_x[(b*64 + row)*512 + c4]);
    }
    {
        int row = d >> 3, hh = d & 7;
        dts[d] = S_zx[(b*64 + row)*DINPROJ + 1026 + (bw ? 8 : 0) + hh];
    }
    if (d < 64) { Bs[d] = S_Bv[b*64 + d]; Cs[d] = S_Cv[b*64 + d]; }
    CP_COMMIT();
    CP_WAIT0();
    __syncthreads();

    int h = d >> 6;
    float Ah = -expf(A_log[h]);
    float bias = dt_bias[h];
    float hs = 0.f;
    S_ys[(i*64)*512 + d] = 0.f;
    #pragma unroll 4
    for (int t = 0; t < 64; ++t) {
        int tt = bw ? (63 - t) : t;
        float x  = xs[tt*512 + d];
        float v  = dts[tt*8 + h] + bias;
        float dt = (v > 20.f) ? v : log1pf(expf(v));
        float a  = expf(dt * Ah);
        hs = a*hs + dt*Bs[tt]*x;
        if (t < 63) S_ys[(i*64 + t + 1)*512 + d] = hs * Cs[tt];
    }
}

// ---------------------------------------------------------------------------
// combine -> split bf16 S_ynhi/lo
__global__ __launch_bounds__(512) void k_combine(
    const float* __restrict__ fc_D_w, const float* __restrict__ Dv,
    const float* __restrict__ norm_w)
{
    int row = blockIdx.x;
    int b = row >> 6, t = row & 63;
    int d = threadIdx.x;
    int h = d >> 6;
    int lane = d & 31, wid = d >> 5;

    float x  = S_x[row*512 + d];
    float z  = S_zx[row*DINPROJ + d];
    float yf = S_ys[row*512 + d];
    float yb = S_ys[((16 + b)*64 + (63 - t))*512 + d];

    float px[8];
    #pragma unroll
    for (int hh = 0; hh < 8; ++hh) px[hh] = x * fc_D_w[hh*512 + d];
    #pragma unroll
    for (int off = 16; off; off >>= 1)
        #pragma unroll
        for (int hh = 0; hh < 8; ++hh) px[hh] += __shfl_xor_sync(0xffffffffu, px[hh], off);

    __shared__ float wsum[16][8];
    __shared__ float dcf[8];
    if (lane == 0) {
        #pragma unroll
        for (int hh = 0; hh < 8; ++hh) wsum[wid][hh] = px[hh];
    }
    __syncthreads();
    if (d < 8) {
        float s = 0.f;
        #pragma unroll
        for (int w = 0; w < 16; ++w) s += wsum[w][d];
        dcf[d] = s + Dv[d];
    }
    __syncthreads();

    float y = yf + yb + x * dcf[h];
    y *= z / (1.f + expf(-z));

    float sq = y*y;
    #pragma unroll
    for (int off = 16; off; off >>= 1) sq += __shfl_xor_sync(0xffffffffu, sq, off);
    __shared__ float rsum[16];
    __shared__ float rscale;
    if (lane == 0) rsum[wid] = sq;
    __syncthreads();
    if (d == 0) {
        float s = 0.f;
        #pragma unroll
        for (int w = 0; w < 16; ++w) s += rsum[w];
        rscale = rsqrtf(s / 512.f + 1e-5f);
    }
    __syncthreads();
    float yn = y * rscale * norm_w[d];
    __nv_bfloat16 vh, vl;
    bsplit(yn, vh, vl);
    S_ynhi[row*512 + d] = vh;
    S_ynlo[row*512 + d] = vl;
}

// ---------------------------------------------------------------------------
__global__ void k_permute(float* __restrict__ outp) {
    int row = blockIdx.x;
    int b = row >> 6, g = row & 63;
    int tid = threadIdx.x;
    int h = tid >> 6, c = tid & 63;
    outp[(((b*8 + h)*64 + g)*64) + c] = S_out[row*512 + tid];
}

// ---------------------------------------------------------------------------
// prepP: Pt[b][d][h*64+g] = sum_c to_w[d, h*64+c] * S_out[(b*64+g)*512 + h*64+c]
// Grid (128 = b*8+h, 4 = dtile), 256 threads. Split-bf16 mma, split output.
// smem: Ah[128][72], Al, Bh[64][72], Bl  -> (2*128 + 2*64)*72*2 = 55296 B
#define PP_SMEM 55296
__global__ __launch_bounds__(256) void k_prepP() {
    extern __shared__ __nv_bfloat16 smP[];
    __nv_bfloat16* Ahs = smP;
    __nv_bfloat16* Als = smP + 128*72;
    __nv_bfloat16* Bhs = smP + 2*128*72;
    __nv_bfloat16* Bls = Bhs + 64*72;

    int tid = threadIdx.x;
    int wid = tid >> 5, lane = tid & 31;
    int warp_m = wid & 1, warp_n = wid >> 1;     // 2 x 4
    int lr = lane >> 2;
    int lk = (lane & 3) * 2;
    int bh = blockIdx.x;
    int b = bh >> 3, h = bh & 7;
    int dbase = blockIdx.y * 128;

    // stage A (to_w split): rows d, k = c
    {
        int r = tid >> 1, half = tid & 1;
        #pragma unroll
        for (int q0 = 0; q0 < 4; ++q0) {
            int q = half*4 + q0;
            size_t src = (size_t)(dbase + r)*512 + h*64 + q*8;
            cp16(&Ahs[r*72 + q*8], &S_Whi[src]);
            cp16(&Als[r*72 + q*8], &S_Wlo[src]);
        }
    }
    // stage B: Bs[g][c] from S_out (convert+split)
    #pragma unroll
    for (int p = 0; p < 16; ++p) {
        int idx = tid + p*256;
        int g = idx >> 6, c = idx & 63;
        float v = S_out[(size_t)(b*64 + g)*512 + h*64 + c];
        __nv_bfloat16 vh, vl;
        bsplit(v, vh, vl);
        Bhs[g*72 + c] = vh;
        Bls[g*72 + c] = vl;
    }
    CP_COMMIT();
    CP_WAIT0();
    __syncthreads();

    float acc[4][2][4];
    #pragma unroll
    for (int mt = 0; mt < 4; ++mt)
        #pragma unroll
        for (int nt = 0; nt < 2; ++nt)
            #pragma unroll
            for (int q = 0; q < 4; ++q) acc[mt][nt][q] = 0.f;

    #pragma unroll
    for (int ks = 0; ks < 4; ++ks) {
        int k0 = ks*16;
        uint32_t ah[4][4], al[4][4], bhf[2][2], blf[2][2];
        #pragma unroll
        for (int mt = 0; mt < 4; ++mt) {
            int rb = warp_m*64 + mt*16 + lr;
            const __nv_bfloat16* pa = &Ahs[rb*72 + k0 + lk];
            ah[mt][0] = *(const uint32_t*)pa;
            ah[mt][1] = *(const uint32_t*)(pa + 8*72);
            ah[mt][2] = *(const uint32_t*)(pa + 8);
            ah[mt][3] = *(const uint32_t*)(pa + 8*72 + 8);
            const __nv_bfloat16* pl = &Als[rb*72 + k0 + lk];
            al[mt][0] = *(const uint32_t*)pl;
            al[mt][1] = *(const uint32_t*)(pl + 8*72);
            al[mt][2] = *(const uint32_t*)(pl + 8);
            al[mt][3] = *(const uint32_t*)(pl + 8*72 + 8);
        }
        #pragma unroll
        for (int nt = 0; nt < 2; ++nt) {
            int nb = warp_n*16 + nt*8 + lr;
            const __nv_bfloat16* pb = &Bhs[nb*72 + k0 + lk];
            bhf[nt][0] = *(const uint32_t*)pb;
            bhf[nt][1] = *(const uint32_t*)(pb + 8);
            const __nv_bfloat16* pl = &Bls[nb*72 + k0 + lk];
            blf[nt][0] = *(const uint32_t*)pl;
            blf[nt][1] = *(const uint32_t*)(pl + 8);
        }
        #pragma unroll
        for (int mt = 0; mt < 4; ++mt)
            #pragma unroll
            for (int nt = 0; nt < 2; ++nt) {
                mma16816(acc[mt][nt], ah[mt], bhf[nt]);
                mma16816(acc[mt][nt], ah[mt], blf[nt]);
                mma16816(acc[mt][nt], al[mt], bhf[nt]);
            }
    }

    // epilogue: split to S_Pthi/S_Ptlo
    #pragma unroll
    for (int mt = 0; mt < 4; ++mt) {
        int m = warp_m*64 + mt*16 + lr;
        #pragma unroll
        for (int nt = 0; nt < 2; ++nt) {
            int coln = warp_n*16 + nt*8 + lk;
            size_t base = ((size_t)b*512 + dbase + m)*512 + h*64 + coln;
            uint32_t hh, ll;
            bsplit2(acc[mt][nt][0], acc[mt][nt][1], hh, ll);
            *(uint32_t*)&S_Pthi[base] = hh;
            *(uint32_t*)&S_Ptlo[base] = ll;
            bsplit2(acc[mt][nt][2], acc[mt][nt][3], hh, ll);
            *(uint32_t*)&S_Pthi[base + 8*512] = hh;
            *(uint32_t*)&S_Ptlo[base + 8*512] = ll;
        }
    }
}

// ---------------------------------------------------------------------------
// Big GEMM: out[b, n, dbase+col] = sum_hg sw[b,h,n,g] * Pt[b][d][hg] + bias[d]
// Grid (25 m-tiles, 16 b, 4 dchunk), 256 threads. A converted+split on the fly.
#define BM_SMEM 81920
__global__ __launch_bounds__(256) void k_bigmma(
    const float* __restrict__ sw, const float* __restrict__ bias,
    float* __restrict__ out)
{
    extern __shared__ __nv_bfloat16 smB[];
    int tid = threadIdx.x;
    int wid = tid >> 5, lane = tid & 31;
    int warp_m = wid & 1, warp_n = wid >> 1;
    int lr = lane >> 2;
    int lk = (lane & 3) * 2;
    int n0 = blockIdx.x * 128;
    int b  = blockIdx.y;
    int dbase = blockIdx.z * 128;

    const int BUF = 4*128*40;
    int arow = tid >> 1;         // 0..127
    int ahalf = tid & 1;         // which 16-float half of the 32-k window
    int brow = tid >> 1;
    int bhalf = tid & 1;

    // A ldg: sw fp32, 16 floats for (row, half) at chunk kc
    float4 rg[4];
    auto ldgA = [&](int kc) {
        int h = kc >> 1;
        int g0 = (kc & 1)*32 + ahalf*16;
        if (n0 + arow < NCTX) {
            const float4* p = (const float4*)(sw + ((size_t)(b*8 + h)*NCTX + n0 + arow)*64 + g0);
            rg[0] = p[0]; rg[1] = p[1]; rg[2] = p[2]; rg[3] = p[3];
        } else {
            rg[0] = rg[1] = rg[2] = rg[3] = make_float4(0.f, 0.f, 0.f, 0.f);
        }
    };
    auto stsA = [&](int buf) {
        __nv_bfloat16* Ah = smB + buf*BUF;
        __nv_bfloat16* Al = Ah + 128*40;
        uint32_t hp[8], lp[8];
        #pragma unroll
        for (int q = 0; q < 4; ++q) {
            bsplit2(rg[q].x, rg[q].y, hp[2*q],     lp[2*q]);
            bsplit2(rg[q].z, rg[q].w, hp[2*q + 1], lp[2*q + 1]);
        }
        uint4* dh = (uint4*)&Ah[arow*40 + ahalf*16];
        dh[0] = make_uint4(hp[0], hp[1], hp[2], hp[3]);
        dh[1] = make_uint4(hp[4], hp[5], hp[6], hp[7]);
        uint4* dl = (uint4*)&Al[arow*40 + ahalf*16];
        dl[0] = make_uint4(lp[0], lp[1], lp[2], lp[3]);
        dl[1] = make_uint4(lp[4], lp[5], lp[6], lp[7]);
    };
    auto stageB = [&](int kc, int buf) {
        __nv_bfloat16* Wh = smB + buf*BUF + 2*128*40;
        __nv_bfloat16* Wl = Wh + 128*40;
        size_t src = ((size_t)b*512 + dbase + brow)*512 + kc*32 + bhalf*16;
        cp16(&Wh[brow*40 + bhalf*16],     &S_Pthi[src]);
        cp16(&Wh[brow*40 + bhalf*16 + 8], &S_Pthi[src + 8]);
        cp16(&Wl[brow*40 + bhalf*16],     &S_Ptlo[src]);
        cp16(&Wl[brow*40 + bhalf*16 + 8], &S_Ptlo[src + 8]);
    };

    float acc[4][4][4];
    #pragma unroll
    for (int mt = 0; mt < 4; ++mt)
        #pragma unroll
        for (int nt = 0; nt < 4; ++nt)
            #pragma unroll
            for (int q = 0; q < 4; ++q) acc[mt][nt][q] = 0.f;

    ldgA(0);
    stsA(0);
    stageB(0, 0);
    CP_COMMIT();

    for (int kc = 0; kc < 16; ++kc) {
        int cur = kc & 1;
        if (kc < 15) { ldgA(kc + 1); stageB(kc + 1, cur ^ 1); CP_COMMIT(); CP_WAIT1(); }
        else         { CP_WAIT0(); }
        __syncthreads();

        __nv_bfloat16* Ah = smB + cur*BUF;
        __nv_bfloat16* Al = Ah + 128*40;
        __nv_bfloat16* Wh = Al + 128*40;
        __nv_bfloat16* Wl = Wh + 128*40;

        #pragma unroll
        for (int ks = 0; ks < 2; ++ks) {
            int k0 = ks*16;
            uint32_t ah[4][4], al[4][4], bh[4][2], bl[4][2];
            #pragma unroll
            for (int mt = 0; mt < 4; ++mt) {
                int rb = warp_m*64 + mt*16 + lr;
                const __nv_bfloat16* pa = &Ah[rb*40 + k0 + lk];
                ah[mt][0] = *(const uint32_t*)pa;
                ah[mt][1] = *(const uint32_t*)(pa + 8*40);
                ah[mt][2] = *(const uint32_t*)(pa + 8);
                ah[mt][3] = *(const uint32_t*)(pa + 8*40 + 8);
                const __nv_bfloat16* pl = &Al[rb*40 + k0 + lk];
                al[mt][0] = *(const uint32_t*)pl;
                al[mt][1] = *(const uint32_t*)(pl + 8*40);
                al[mt][2] = *(const uint32_t*)(pl + 8);
                al[mt][3] = *(const uint32_t*)(pl + 8*40 + 8);
            }
            #pragma unroll
            for (int nt = 0; nt < 4; ++nt) {
                int nb = warp_n*32 + nt*8 + lr;
                const __nv_bfloat16* pb = &Wh[nb*40 + k0 + lk];
                bh[nt][0] = *(const uint32_t*)pb;
                bh[nt][1] = *(const uint32_t*)(pb + 8);
                const __nv_bfloat16* pl = &Wl[nb*40 + k0 + lk];
                bl[nt][0] = *(const uint32_t*)pl;
                bl[nt][1] = *(const uint32_t*)(pl + 8);
            }
            #pragma unroll
            for (int mt = 0; mt < 4; ++mt)
                #pragma unroll
                for (int nt = 0; nt < 4; ++nt) {
                    mma16816(acc[mt][nt], ah[mt], bh[nt]);
                    mma16816(acc[mt][nt], ah[mt], bl[nt]);
                    mma16816(acc[mt][nt], al[mt], bh[nt]);
                }
        }
        if (kc < 15) stsA(cur ^ 1);
    }

    // epilogue
    #pragma unroll
    for (int mt = 0; mt < 4; ++mt) {
        int m = warp_m*64 + mt*16 + lr;
        #pragma unroll
        for (int nt = 0; nt < 4; ++nt) {
            int col = dbase + warp_n*32 + nt*8 + lk;
            float b0 = __ldg(&bias[col]);
            float b1 = __ldg(&bias[col + 1]);
            if (n0 + m < NCTX) {
                size_t r = (size_t)b*NCTX + n0 + m;
                float2 v;
                v.x = acc[mt][nt][0] + b0;
                v.y = acc[mt][nt][1] + b1;
                *(float2*)&out[r*512 + col] = v;
            }
            if (n0 + m + 8 < NCTX) {
                size_t r = (size_t)b*NCTX + n0 + m + 8;
                float2 v;
                v.x = acc[mt][nt][2] + b0;
                v.y = acc[mt][nt][3] + b1;
                *(float2*)&out[r*512 + col] = v;
            }
        }
    }
}

// ---------------------------------------------------------------------------
extern "C" void kernel_launch(void* const* d_in, const int* in_sizes, int n_in,
                              void* d_out, int out_size) {
    const float* st     = (const float*)d_in[0];
    const float* sw     = (const float*)d_in[1];
    const float* w_in   = (const float*)d_in[2];
    const float* conv_w = (const float*)d_in[3];
    const float* conv_b = (const float*)d_in[4];
    const float* dt_bias= (const float*)d_in[5];
    const float* A_log  = (const float*)d_in[6];
    const float* Dv     = (const float*)d_in[7];
    const float* fc_D_w = (const float*)d_in[8];
    const float* norm_w = (const float*)d_in[9];
    const float* w_out  = (const float*)d_in[10];
    const float* to_w   = (const float*)d_in[11];
    const float* to_b   = (const float*)d_in[12];

    float* out       = (float*)d_out;
    float* out_final = out;
    float* out_inp   = out + (size_t)B16*NCTX*DM512;
    float* out_outp  = out_inp + (size_t)B16*8*64*64;

    float *pSzx, *pSout;
    __nv_bfloat16 *pUh, *pUl, *pYh, *pYl, *pW1h, *pW1l, *pW2h, *pW2l, *pWh, *pWl;
    cudaGetSymbolAddress((void**)&pSzx, S_zx);
    cudaGetSymbolAddress((void**)&pSout, S_out);
    cudaGetSymbolAddress((void**)&pUh, S_uhi);
    cudaGetSymbolAddress((void**)&pUl, S_ulo);
    cudaGetSymbolAddress((void**)&pYh, S_ynhi);
    cudaGetSymbolAddress((void**)&pYl, S_ynlo);
    cudaGetSymbolAddress((void**)&pW1h, S_W1hi);
    cudaGetSymbolAddress((void**)&pW1l, S_W1lo);
    cudaGetSymbolAddress((void**)&pW2h, S_W2hi);
    cudaGetSymbolAddress((void**)&pW2l, S_W2lo);
    cudaGetSymbolAddress((void**)&pWh, S_Whi);
    cudaGetSymbolAddress((void**)&pWl, S_Wlo);

    cudaMemcpyAsync(out_inp, st, sizeof(float)*B16*8*64*64, cudaMemcpyDeviceToDevice);

    // split weights
    k_split<<<(DINPROJ*DM512 + 511)/512, 512>>>(w_in,  pW1h, pW1l, DINPROJ*DM512);
    k_split<<<(DM512*DM512 + 511)/512, 512>>>(w_out, pW2h, pW2l, DM512*DM512);
    k_split<<<(DM512*DM512 + 511)/512, 512>>>(to_w,  pWh,  pWl,  DM512*DM512);

    k_transpose_u<<<B16*L64, 512>>>(st);

    cudaFuncSetAttribute(k_gemm_sp, cudaFuncAttributeMaxDynamicSharedMemorySize, GS_SMEM);
    // in-proj: [1024 x 1042 x 512]
    k_gemm_sp<<<dim3(8, 9), 256, GS_SMEM>>>(pUh, pUl, pW1h, pW1l, pSzx, DINPROJ);

    k_conv<<<B16*L64, 544>>>(conv_w, conv_b);

    cudaFuncSetAttribute(k_scan, cudaFuncAttributeMaxDynamicSharedMemorySize, SC_SMEM);
    k_scan<<<32, 512, SC_SMEM>>>(dt_bias, A_log);

    k_combine<<<B16*L64, 512>>>(fc_D_w, Dv, norm_w);

    // out-proj: [1024 x 512 x 512]
    k_gemm_sp<<<dim3(8, 4), 256, GS_SMEM>>>(pYh, pYl, pW2h, pW2l, pSout, DM512);

    k_permute<<<B16*L64, 512>>>(out_outp);

    cudaFuncSetAttribute(k_prepP, cudaFuncAttributeMaxDynamicSharedMemorySize, PP_SMEM);
    k_prepP<<<dim3(128, 4), 256, PP_SMEM>>>();

    cudaFuncSetAttribute(k_bigmma, cudaFuncAttributeMaxDynamicSharedMemorySize, BM_SMEM);
    k_bigmma<<<dim3((NCTX + 127)/128, B16, 4), 256, BM_SMEM>>>(sw, to_b, out_final);
}

// round 6
// speedup vs baseline: 4.9508x; 1.1622x over previous
#include <cuda_runtime.h>
#include <cuda_bf16.h>
#include <math.h>
#include <stdint.h>

// Problem constants
#define B16    16
#define L64    64
#define DM512  512
#define NCTX   3131
#define DINPROJ 1042
#define CONVDIM 514
#define MROWS  50096            // 16*3131

// Scratch (static device arrays; zero-initialized, allocation-free)
__device__ float S_zx [B16*L64*DINPROJ];
__device__ float S_x  [B16*L64*DM512];
__device__ float S_Bv [B16*L64];
__device__ float S_Cv [B16*L64];
__device__ float S_ys [2*B16*L64*DM512];
__device__ float S_out[B16*L64*DM512];
// split-bf16 operands (pre-pipeline)
__device__ __nv_bfloat16 S_uhi [B16*L64*DM512];
__device__ __nv_bfloat16 S_ulo [B16*L64*DM512];
__device__ __nv_bfloat16 S_ynhi[B16*L64*DM512];
__device__ __nv_bfloat16 S_ynlo[B16*L64*DM512];
__device__ __nv_bfloat16 S_W1hi[1152*DM512];
__device__ __nv_bfloat16 S_W1lo[1152*DM512];
__device__ __nv_bfloat16 S_W2hi[DM512*DM512];
__device__ __nv_bfloat16 S_W2lo[DM512*DM512];
__device__ __nv_bfloat16 S_Whi [DM512*DM512];
__device__ __nv_bfloat16 S_Wlo [DM512*DM512];
// Pt fp32 (tf32-pre-rounded): Pt[b][d][hg]
__device__ float S_Pt[(size_t)B16*DM512*DM512];

// ---- helpers ---------------------------------------------------------------
__device__ __forceinline__ void mma16816(float* c, const uint32_t* a, const uint32_t* b) {
    asm volatile(
        "mma.sync.aligned.m16n8k16.row.col.f32.bf16.bf16.f32 "
        "{%0,%1,%2,%3}, {%4,%5,%6,%7}, {%8,%9}, {%0,%1,%2,%3};"
        : "+f"(c[0]), "+f"(c[1]), "+f"(c[2]), "+f"(c[3])
        : "r"(a[0]), "r"(a[1]), "r"(a[2]), "r"(a[3]), "r"(b[0]), "r"(b[1]));
}
__device__ __forceinline__ void mma_tf32(float* c, const uint32_t* a, const uint32_t* b) {
    asm volatile(
        "mma.sync.aligned.m16n8k8.row.col.f32.tf32.tf32.f32 "
        "{%0,%1,%2,%3}, {%4,%5,%6,%7}, {%8,%9}, {%0,%1,%2,%3};"
        : "+f"(c[0]), "+f"(c[1]), "+f"(c[2]), "+f"(c[3])
        : "r"(a[0]), "r"(a[1]), "r"(a[2]), "r"(a[3]), "r"(b[0]), "r"(b[1]));
}
__device__ __forceinline__ float to_tf32(float x) {
    uint32_t r;
    asm("cvt.rna.tf32.f32 %0, %1;" : "=r"(r) : "f"(x));
    return __uint_as_float(r);
}
__device__ __forceinline__ void bsplit(float v, __nv_bfloat16& h, __nv_bfloat16& l) {
    h = __float2bfloat16(v);
    l = __float2bfloat16(v - __bfloat162float(h));
}
__device__ __forceinline__ void cp16(void* dst, const void* src) {
    uint32_t d = (uint32_t)__cvta_generic_to_shared(dst);
    asm volatile("cp.async.cg.shared.global [%0], [%1], 16;" :: "r"(d), "l"(src));
}
#define CP_COMMIT() asm volatile("cp.async.commit_group;" ::: "memory")
#define CP_WAIT1()  asm volatile("cp.async.wait_group 1;" ::: "memory")
#define CP_WAIT0()  asm volatile("cp.async.wait_group 0;" ::: "memory")

// ---------------------------------------------------------------------------
__global__ void k_split(const float* __restrict__ src,
                        __nv_bfloat16* __restrict__ hi,
                        __nv_bfloat16* __restrict__ lo, int n) {
    int i = blockIdx.x * blockDim.x + threadIdx.x;
    if (i >= n) return;
    __nv_bfloat16 h, l;
    bsplit(src[i], h, l);
    hi[i] = h;
    lo[i] = l;
}

// ---------------------------------------------------------------------------
__global__ void k_transpose_u(const float* __restrict__ st) {
    int row = blockIdx.x;
    int b = row >> 6, g = row & 63;
    int tid = threadIdx.x;
    int h = tid >> 6, c = tid & 63;
    float v = st[(((b*8 + h)*64) + g)*64 + c];
    __nv_bfloat16 vh, vl;
    bsplit(v, vh, vl);
    S_uhi[row*DM512 + tid] = vh;
    S_ulo[row*DM512 + tid] = vl;
}

// ---------------------------------------------------------------------------
// Presplit GEMM: C[m,n] = sum_k A[m,k]*B[n,k], split bf16, M=1024, K=512
#define GS_SMEM 81920
__global__ __launch_bounds__(256) void k_gemm_sp(
    const __nv_bfloat16* __restrict__ Ahi, const __nv_bfloat16* __restrict__ Alo,
    const __nv_bfloat16* __restrict__ Bhi, const __nv_bfloat16* __restrict__ Blo,
    float* __restrict__ C, int N)
{
    extern __shared__ __nv_bfloat16 smG[];
    int tid = threadIdx.x;
    int wid = tid >> 5, lane = tid & 31;
    int warp_m = wid & 1, warp_n = wid >> 1;
    int lr = lane >> 2;
    int lk = (lane & 3) * 2;
    size_t rbase = (size_t)blockIdx.x * 128;
    int n0 = blockIdx.y * 128;

    const int BUF = 4*128*40;
    int m_st = tid >> 2;
    int kp_st = tid & 3;

    auto stage = [&](int kc, int buf) {
        __nv_bfloat16* Ah = smG + buf*BUF;
        __nv_bfloat16* Al = Ah + 128*40;
        __nv_bfloat16* Wh = Al + 128*40;
        __nv_bfloat16* Wl = Wh + 128*40;
        int kofs = kc*32 + kp_st*8;
        #pragma unroll
        for (int p = 0; p < 2; ++p) {
            int m = m_st + p*64;
            size_t ga = (rbase + m)*512 + kofs;
            cp16(&Ah[m*40 + kp_st*8], &Ahi[ga]);
            cp16(&Al[m*40 + kp_st*8], &Alo[ga]);
            size_t gw = (size_t)(n0 + m)*512 + kofs;
            cp16(&Wh[m*40 + kp_st*8], &Bhi[gw]);
            cp16(&Wl[m*40 + kp_st*8], &Blo[gw]);
        }
    };

    float acc[4][4][4];
    #pragma unroll
    for (int mt = 0; mt < 4; ++mt)
        #pragma unroll
        for (int nt = 0; nt < 4; ++nt)
            #pragma unroll
            for (int q = 0; q < 4; ++q) acc[mt][nt][q] = 0.f;

    stage(0, 0);
    CP_COMMIT();

    for (int kc = 0; kc < 16; ++kc) {
        int cur = kc & 1;
        if (kc < 15) { stage(kc + 1, cur ^ 1); CP_COMMIT(); CP_WAIT1(); }
        else         { CP_WAIT0(); }
        __syncthreads();

        __nv_bfloat16* Ah = smG + cur*BUF;
        __nv_bfloat16* Al = Ah + 128*40;
        __nv_bfloat16* Wh = Al + 128*40;
        __nv_bfloat16* Wl = Wh + 128*40;

        #pragma unroll
        for (int ks = 0; ks < 2; ++ks) {
            int k0 = ks*16;
            uint32_t ah[4][4], al[4][4], bh[4][2], bl[4][2];
            #pragma unroll
            for (int mt = 0; mt < 4; ++mt) {
                int rb = warp_m*64 + mt*16 + lr;
                const __nv_bfloat16* pa = &Ah[rb*40 + k0 + lk];
                ah[mt][0] = *(const uint32_t*)pa;
                ah[mt][1] = *(const uint32_t*)(pa + 8*40);
                ah[mt][2] = *(const uint32_t*)(pa + 8);
                ah[mt][3] = *(const uint32_t*)(pa + 8*40 + 8);
                const __nv_bfloat16* pl = &Al[rb*40 + k0 + lk];
                al[mt][0] = *(const uint32_t*)pl;
                al[mt][1] = *(const uint32_t*)(pl + 8*40);
                al[mt][2] = *(const uint32_t*)(pl + 8);
                al[mt][3] = *(const uint32_t*)(pl + 8*40 + 8);
            }
            #pragma unroll
            for (int nt = 0; nt < 4; ++nt) {
                int nb = warp_n*32 + nt*8 + lr;
                const __nv_bfloat16* pb = &Wh[nb*40 + k0 + lk];
                bh[nt][0] = *(const uint32_t*)pb;
                bh[nt][1] = *(const uint32_t*)(pb + 8);
                const __nv_bfloat16* pl = &Wl[nb*40 + k0 + lk];
                bl[nt][0] = *(const uint32_t*)pl;
                bl[nt][1] = *(const uint32_t*)(pl + 8);
            }
            #pragma unroll
            for (int mt = 0; mt < 4; ++mt)
                #pragma unroll
                for (int nt = 0; nt < 4; ++nt) {
                    mma16816(acc[mt][nt], ah[mt], bh[nt]);
                    mma16816(acc[mt][nt], ah[mt], bl[nt]);
                    mma16816(acc[mt][nt], al[mt], bh[nt]);
                }
        }
        __syncthreads();
    }

    #pragma unroll
    for (int mt = 0; mt < 4; ++mt) {
        int m = warp_m*64 + mt*16 + lr;
        #pragma unroll
        for (int nt = 0; nt < 4; ++nt) {
            int col = n0 + warp_n*32 + nt*8 + lk;
            if (col < N) {
                size_t r = rbase + m;
                float2 v0;
                v0.x = acc[mt][nt][0];
                v0.y = acc[mt][nt][1];
                *(float2*)&C[r*N + col] = v0;
                float2 v1;
                v1.x = acc[mt][nt][2];
                v1.y = acc[mt][nt][3];
                *(float2*)&C[(r + 8)*N + col] = v1;
            }
        }
    }
}

// ---------------------------------------------------------------------------
__global__ void k_conv(const float* __restrict__ conv_w, const float* __restrict__ conv_b) {
    int row = blockIdx.x;
    int t = row & 63;
    int c = threadIdx.x;
    if (c >= CONVDIM) return;
    float acc = conv_b[c];
    #pragma unroll
    for (int k = 0; k < 3; ++k) {
        int tt = t + k - 2;
        if (tt >= 0) acc += conv_w[c*3 + k] * S_zx[(row + (k - 2))*DINPROJ + 512 + c];
    }
    acc = acc / (1.f + expf(-acc));
    if (c < 512)       S_x[row*512 + c] = acc;
    else if (c == 512) S_Bv[row] = acc;
    else               S_Cv[row] = acc;
}

// ---------------------------------------------------------------------------
#define SC_SMEM (64*512*4 + 512*4 + 128*4)
__global__ __launch_bounds__(512) void k_scan(
    const float* __restrict__ dt_bias, const float* __restrict__ A_log)
{
    extern __shared__ float smS[];
    float* xs  = smS;
    float* dts = smS + 64*512;
    float* Bs  = dts + 512;
    float* Cs  = Bs + 64;

    int i = blockIdx.x;
    int d = threadIdx.x;
    bool bw = (i >= 16);
    int b = bw ? i - 16 : i;

    #pragma unroll
    for (int p = 0; p < 16; ++p) {
        int idx = d + p*512;
        int row = idx >> 7;
        int c4 = (idx & 127) * 4;
        cp16(&xs[row*512 + c4], &S_x[(b*64 + row)*512 + c4]);
    }
    {
        int row = d >> 3, hh = d & 7;
        dts[d] = S_zx[(b*64 + row)*DINPROJ + 1026 + (bw ? 8 : 0) + hh];
    }
    if (d < 64) { Bs[d] = S_Bv[b*64 + d]; Cs[d] = S_Cv[b*64 + d]; }
    CP_COMMIT();
    CP_WAIT0();
    __syncthreads();

    int h = d >> 6;
    float Ah = -expf(A_log[h]);
    float bias = dt_bias[h];
    float hs = 0.f;
    S_ys[(i*64)*512 + d] = 0.f;
    #pragma unroll 4
    for (int t = 0; t < 64; ++t) {
        int tt = bw ? (63 - t) : t;
        float x  = xs[tt*512 + d];
        float v  = dts[tt*8 + h] + bias;
        float dt = (v > 20.f) ? v : log1pf(expf(v));
        float a  = expf(dt * Ah);
        hs = a*hs + dt*Bs[tt]*x;
        if (t < 63) S_ys[(i*64 + t + 1)*512 + d] = hs * Cs[tt];
    }
}

// ---------------------------------------------------------------------------
__global__ __launch_bounds__(512) void k_combine(
    const float* __restrict__ fc_D_w, const float* __restrict__ Dv,
    const float* __restrict__ norm_w)
{
    int row = blockIdx.x;
    int b = row >> 6, t = row & 63;
    int d = threadIdx.x;
    int h = d >> 6;
    int lane = d & 31, wid = d >> 5;

    float x  = S_x[row*512 + d];
    float z  = S_zx[row*DINPROJ + d];
    float yf = S_ys[row*512 + d];
    float yb = S_ys[((16 + b)*64 + (63 - t))*512 + d];

    float px[8];
    #pragma unroll
    for (int hh = 0; hh < 8; ++hh) px[hh] = x * fc_D_w[hh*512 + d];
    #pragma unroll
    for (int off = 16; off; off >>= 1)
        #pragma unroll
        for (int hh = 0; hh < 8; ++hh) px[hh] += __shfl_xor_sync(0xffffffffu, px[hh], off);

    __shared__ float wsum[16][8];
    __shared__ float dcf[8];
    if (lane == 0) {
        #pragma unroll
        for (int hh = 0; hh < 8; ++hh) wsum[wid][hh] = px[hh];
    }
    __syncthreads();
    if (d < 8) {
        float s = 0.f;
        #pragma unroll
        for (int w = 0; w < 16; ++w) s += wsum[w][d];
        dcf[d] = s + Dv[d];
    }
    __syncthreads();

    float y = yf + yb + x * dcf[h];
    y *= z / (1.f + expf(-z));

    float sq = y*y;
    #pragma unroll
    for (int off = 16; off; off >>= 1) sq += __shfl_xor_sync(0xffffffffu, sq, off);
    __shared__ float rsum[16];
    __shared__ float rscale;
    if (lane == 0) rsum[wid] = sq;
    __syncthreads();
    if (d == 0) {
        float s = 0.f;
        #pragma unroll
        for (int w = 0; w < 16; ++w) s += rsum[w];
        rscale = rsqrtf(s / 512.f + 1e-5f);
    }
    __syncthreads();
    float yn = y * rscale * norm_w[d];
    __nv_bfloat16 vh, vl;
    bsplit(yn, vh, vl);
    S_ynhi[row*512 + d] = vh;
    S_ynlo[row*512 + d] = vl;
}

// ---------------------------------------------------------------------------
__global__ void k_permute(float* __restrict__ outp) {
    int row = blockIdx.x;
    int b = row >> 6, g = row & 63;
    int tid = threadIdx.x;
    int h = tid >> 6, c = tid & 63;
    outp[(((b*8 + h)*64 + g)*64) + c] = S_out[row*512 + tid];
}

// ---------------------------------------------------------------------------
// prepP: Pt[b][d][h*64+g] = sum_c to_w[d, h*64+c] * S_out[(b*64+g)*512 + h*64+c]
// Split-bf16 mma; epilogue writes tf32-rounded fp32 into S_Pt.
#define PP_SMEM 55296
__global__ __launch_bounds__(256) void k_prepP() {
    extern __shared__ __nv_bfloat16 smP[];
    __nv_bfloat16* Ahs = smP;
    __nv_bfloat16* Als = smP + 128*72;
    __nv_bfloat16* Bhs = smP + 2*128*72;
    __nv_bfloat16* Bls = Bhs + 64*72;

    int tid = threadIdx.x;
    int wid = tid >> 5, lane = tid & 31;
    int warp_m = wid & 1, warp_n = wid >> 1;
    int lr = lane >> 2;
    int lk = (lane & 3) * 2;
    int bh = blockIdx.x;
    int b = bh >> 3, h = bh & 7;
    int dbase = blockIdx.y * 128;

    {
        int r = tid >> 1, half = tid & 1;
        #pragma unroll
        for (int q0 = 0; q0 < 4; ++q0) {
            int q = half*4 + q0;
            size_t src = (size_t)(dbase + r)*512 + h*64 + q*8;
            cp16(&Ahs[r*72 + q*8], &S_Whi[src]);
            cp16(&Als[r*72 + q*8], &S_Wlo[src]);
        }
    }
    #pragma unroll
    for (int p = 0; p < 16; ++p) {
        int idx = tid + p*256;
        int g = idx >> 6, c = idx & 63;
        float v = S_out[(size_t)(b*64 + g)*512 + h*64 + c];
        __nv_bfloat16 vh, vl;
        bsplit(v, vh, vl);
        Bhs[g*72 + c] = vh;
        Bls[g*72 + c] = vl;
    }
    CP_COMMIT();
    CP_WAIT0();
    __syncthreads();

    float acc[4][2][4];
    #pragma unroll
    for (int mt = 0; mt < 4; ++mt)
        #pragma unroll
        for (int nt = 0; nt < 2; ++nt)
            #pragma unroll
            for (int q = 0; q < 4; ++q) acc[mt][nt][q] = 0.f;

    #pragma unroll
    for (int ks = 0; ks < 4; ++ks) {
        int k0 = ks*16;
        uint32_t ah[4][4], al[4][4], bhf[2][2], blf[2][2];
        #pragma unroll
        for (int mt = 0; mt < 4; ++mt) {
            int rb = warp_m*64 + mt*16 + lr;
            const __nv_bfloat16* pa = &Ahs[rb*72 + k0 + lk];
            ah[mt][0] = *(const uint32_t*)pa;
            ah[mt][1] = *(const uint32_t*)(pa + 8*72);
            ah[mt][2] = *(const uint32_t*)(pa + 8);
            ah[mt][3] = *(const uint32_t*)(pa + 8*72 + 8);
            const __nv_bfloat16* pl = &Als[rb*72 + k0 + lk];
            al[mt][0] = *(const uint32_t*)pl;
            al[mt][1] = *(const uint32_t*)(pl + 8*72);
            al[mt][2] = *(const uint32_t*)(pl + 8);
            al[mt][3] = *(const uint32_t*)(pl + 8*72 + 8);
        }
        #pragma unroll
        for (int nt = 0; nt < 2; ++nt) {
            int nb = warp_n*16 + nt*8 + lr;
            const __nv_bfloat16* pb = &Bhs[nb*72 + k0 + lk];
            bhf[nt][0] = *(const uint32_t*)pb;
            bhf[nt][1] = *(const uint32_t*)(pb + 8);
            const __nv_bfloat16* pl = &Bls[nb*72 + k0 + lk];
            blf[nt][0] = *(const uint32_t*)pl;
            blf[nt][1] = *(const uint32_t*)(pl + 8);
        }
        #pragma unroll
        for (int mt = 0; mt < 4; ++mt)
            #pragma unroll
            for (int nt = 0; nt < 2; ++nt) {
                mma16816(acc[mt][nt], ah[mt], bhf[nt]);
                mma16816(acc[mt][nt], ah[mt], blf[nt]);
                mma16816(acc[mt][nt], al[mt], bhf[nt]);
            }
    }

    // epilogue: tf32-round, write fp32 Pt
    #pragma unroll
    for (int mt = 0; mt < 4; ++mt) {
        int m = warp_m*64 + mt*16 + lr;
        #pragma unroll
        for (int nt = 0; nt < 2; ++nt) {
            int coln = warp_n*16 + nt*8 + lk;
            size_t base = ((size_t)b*512 + dbase + m)*512 + h*64 + coln;
            float2 v0;
            v0.x = to_tf32(acc[mt][nt][0]);
            v0.y = to_tf32(acc[mt][nt][1]);
            *(float2*)&S_Pt[base] = v0;
            float2 v1;
            v1.x = to_tf32(acc[mt][nt][2]);
            v1.y = to_tf32(acc[mt][nt][3]);
            *(float2*)&S_Pt[base + 8*512] = v1;
        }
    }
}

// ---------------------------------------------------------------------------
// Big GEMM (tf32): out[b, n, dbase+col] = sum_hg sw[b,h,n,g]*Pt[b][d][hg] + bias
// Grid (100 = mtile*4+dchunk, 16 b), 256 threads. BK=32 double-buffered.
// smem fp32 stride 36: A[128][36], B[128][36] per buffer = 36864 B; x2 = 73728.
#define BM_SMEM 73728
__global__ __launch_bounds__(256) void k_bigmma(
    const float* __restrict__ sw, const float* __restrict__ bias,
    float* __restrict__ out)
{
    extern __shared__ float smB[];
    int tid = threadIdx.x;
    int wid = tid >> 5, lane = tid & 31;
    int warp_m = wid & 1, warp_n = wid >> 1;
    int lr = lane >> 2;
    int lq = lane & 3;
    int dc = blockIdx.x & 3;
    int mt0 = blockIdx.x >> 2;
    int n0 = mt0 * 128;
    int b  = blockIdx.y;
    int dbase = dc * 128;

    const int BUF = 2*128*36;    // floats per buffer (A + B)
    int arow = tid >> 1;         // 0..127
    int ahalf = tid & 1;

    float4 rg[4];
    auto ldgA = [&](int kc) {
        int h = kc >> 1;
        int g0 = (kc & 1)*32 + ahalf*16;
        if (n0 + arow < NCTX) {
            const float4* p = (const float4*)(sw + ((size_t)(b*8 + h)*NCTX + n0 + arow)*64 + g0);
            rg[0] = p[0]; rg[1] = p[1]; rg[2] = p[2]; rg[3] = p[3];
        } else {
            rg[0] = rg[1] = rg[2] = rg[3] = make_float4(0.f, 0.f, 0.f, 0.f);
        }
    };
    auto stsA = [&](int buf) {
        float* As = smB + buf*BUF;
        float4* dst = (float4*)&As[arow*36 + ahalf*16];
        #pragma unroll
        for (int q = 0; q < 4; ++q) {
            float4 v = rg[q];
            v.x = to_tf32(v.x); v.y = to_tf32(v.y);
            v.z = to_tf32(v.z); v.w = to_tf32(v.w);
            dst[q] = v;
        }
    };
    auto stageB = [&](int kc, int buf) {
        float* Bs = smB + buf*BUF + 128*36;
        #pragma unroll
        for (int p = 0; p < 4; ++p) {
            int idx = tid + p*256;
            int row = idx >> 3, q = idx & 7;
            size_t src = ((size_t)b*512 + dbase + row)*512 + kc*32 + q*4;
            cp16(&Bs[row*36 + q*4], &S_Pt[src]);
        }
    };

    float acc[4][4][4];
    #pragma unroll
    for (int mt = 0; mt < 4; ++mt)
        #pragma unroll
        for (int nt = 0; nt < 4; ++nt)
            #pragma unroll
            for (int q = 0; q < 4; ++q) acc[mt][nt][q] = 0.f;

    ldgA(0);
    stsA(0);
    stageB(0, 0);
    CP_COMMIT();

    for (int kc = 0; kc < 16; ++kc) {
        int cur = kc & 1;
        if (kc < 15) { ldgA(kc + 1); stageB(kc + 1, cur ^ 1); CP_COMMIT(); CP_WAIT1(); }
        else         { CP_WAIT0(); }
        __syncthreads();

        float* As = smB + cur*BUF;
        float* Bs = As + 128*36;

        #pragma unroll
        for (int ks = 0; ks < 4; ++ks) {
            int k0 = ks*8;
            uint32_t af[4][4], bf[4][2];
            #pragma unroll
            for (int mt = 0; mt < 4; ++mt) {
                int rb = warp_m*64 + mt*16 + lr;
                const float* pa = &As[rb*36 + k0 + lq];
                af[mt][0] = __float_as_uint(pa[0]);
                af[mt][1] = __float_as_uint(pa[8*36]);
                af[mt][2] = __float_as_uint(pa[4]);
                af[mt][3] = __float_as_uint(pa[8*36 + 4]);
            }
            #pragma unroll
            for (int nt = 0; nt < 4; ++nt) {
                int nb = warp_n*32 + nt*8 + lr;
                const float* pb = &Bs[nb*36 + k0 + lq];
                bf[nt][0] = __float_as_uint(pb[0]);
                bf[nt][1] = __float_as_uint(pb[4]);
            }
            #pragma unroll
            for (int mt = 0; mt < 4; ++mt)
                #pragma unroll
                for (int nt = 0; nt < 4; ++nt)
                    mma_tf32(acc[mt][nt], af[mt], bf[nt]);
        }
        if (kc < 15) stsA(cur ^ 1);
    }

    // epilogue
    #pragma unroll
    for (int mt = 0; mt < 4; ++mt) {
        int m = warp_m*64 + mt*16 + lr;
        #pragma unroll
        for (int nt = 0; nt < 4; ++nt) {
            int col = dbase + warp_n*32 + nt*8 + lq*2;
            float b0 = __ldg(&bias[col]);
            float b1 = __ldg(&bias[col + 1]);
            if (n0 + m < NCTX) {
                size_t r = (size_t)b*NCTX + n0 + m;
                float2 v;
                v.x = acc[mt][nt][0] + b0;
                v.y = acc[mt][nt][1] + b1;
                *(float2*)&out[r*512 + col] = v;
            }
            if (n0 + m + 8 < NCTX) {
                size_t r = (size_t)b*NCTX + n0 + m + 8;
                float2 v;
                v.x = acc[mt][nt][2] + b0;
                v.y = acc[mt][nt][3] + b1;
                *(float2*)&out[r*512 + col] = v;
            }
        }
    }
}

// ---------------------------------------------------------------------------
extern "C" void kernel_launch(void* const* d_in, const int* in_sizes, int n_in,
                              void* d_out, int out_size) {
    const float* st     = (const float*)d_in[0];
    const float* sw     = (const float*)d_in[1];
    const float* w_in   = (const float*)d_in[2];
    const float* conv_w = (const float*)d_in[3];
    const float* conv_b = (const float*)d_in[4];
    const float* dt_bias= (const float*)d_in[5];
    const float* A_log  = (const float*)d_in[6];
    const float* Dv     = (const float*)d_in[7];
    const float* fc_D_w = (const float*)d_in[8];
    const float* norm_w = (const float*)d_in[9];
    const float* w_out  = (const float*)d_in[10];
    const float* to_w   = (const float*)d_in[11];
    const float* to_b   = (const float*)d_in[12];

    float* out       = (float*)d_out;
    float* out_final = out;
    float* out_inp   = out + (size_t)B16*NCTX*DM512;
    float* out_outp  = out_inp + (size_t)B16*8*64*64;

    float *pSzx, *pSout;
    __nv_bfloat16 *pUh, *pUl, *pYh, *pYl, *pW1h, *pW1l, *pW2h, *pW2l, *pWh, *pWl;
    cudaGetSymbolAddress((void**)&pSzx, S_zx);
    cudaGetSymbolAddress((void**)&pSout, S_out);
    cudaGetSymbolAddress((void**)&pUh, S_uhi);
    cudaGetSymbolAddress((void**)&pUl, S_ulo);
    cudaGetSymbolAddress((void**)&pYh, S_ynhi);
    cudaGetSymbolAddress((void**)&pYl, S_ynlo);
    cudaGetSymbolAddress((void**)&pW1h, S_W1hi);
    cudaGetSymbolAddress((void**)&pW1l, S_W1lo);
    cudaGetSymbolAddress((void**)&pW2h, S_W2hi);
    cudaGetSymbolAddress((void**)&pW2l, S_W2lo);
    cudaGetSymbolAddress((void**)&pWh, S_Whi);
    cudaGetSymbolAddress((void**)&pWl, S_Wlo);

    cudaMemcpyAsync(out_inp, st, sizeof(float)*B16*8*64*64, cudaMemcpyDeviceToDevice);

    k_split<<<(DINPROJ*DM512 + 511)/512, 512>>>(w_in,  pW1h, pW1l, DINPROJ*DM512);
    k_split<<<(DM512*DM512 + 511)/512, 512>>>(w_out, pW2h, pW2l, DM512*DM512);
    k_split<<<(DM512*DM512 + 511)/512, 512>>>(to_w,  pWh,  pWl,  DM512*DM512);

    k_transpose_u<<<B16*L64, 512>>>(st);

    cudaFuncSetAttribute(k_gemm_sp, cudaFuncAttributeMaxDynamicSharedMemorySize, GS_SMEM);
    k_gemm_sp<<<dim3(8, 9), 256, GS_SMEM>>>(pUh, pUl, pW1h, pW1l, pSzx, DINPROJ);

    k_conv<<<B16*L64, 544>>>(conv_w, conv_b);

    cudaFuncSetAttribute(k_scan, cudaFuncAttributeMaxDynamicSharedMemorySize, SC_SMEM);
    k_scan<<<32, 512, SC_SMEM>>>(dt_bias, A_log);

    k_combine<<<B16*L64, 512>>>(fc_D_w, Dv, norm_w);

    k_gemm_sp<<<dim3(8, 4), 256, GS_SMEM>>>(pYh, pYl, pW2h, pW2l, pSout, DM512);

    k_permute<<<B16*L64, 512>>>(out_outp);

    cudaFuncSetAttribute(k_prepP, cudaFuncAttributeMaxDynamicSharedMemorySize, PP_SMEM);
    k_prepP<<<dim3(128, 4), 256, PP_SMEM>>>();

    cudaFuncSetAttribute(k_bigmma, cudaFuncAttributeMaxDynamicSharedMemorySize, BM_SMEM);
    k_bigmma<<<dim3(4*((NCTX + 127)/128), B16), 256, BM_SMEM>>>(sw, to_b, out_final);
}

// round 9
// speedup vs baseline: 5.0121x; 1.0124x over previous
#include <cuda_runtime.h>
#include <cuda_bf16.h>
#include <math.h>
#include <stdint.h>

// Problem constants
#define B16    16
#define L64    64
#define DM512  512
#define NCTX   3131
#define DINPROJ 1042
#define CONVDIM 514
#define MROWS  50096            // 16*3131

// Scratch (static device arrays; zero-initialized, allocation-free)
__device__ float S_zx [B16*L64*DINPROJ];
__device__ float S_x  [B16*L64*DM512];
__device__ float S_Bv [B16*L64];
__device__ float S_Cv [B16*L64];
__device__ float S_ys [2*B16*L64*DM512];
__device__ float S_out[B16*L64*DM512];
// split-bf16 operands (pre-pipeline)
__device__ __nv_bfloat16 S_uhi [B16*L64*DM512];
__device__ __nv_bfloat16 S_ulo [B16*L64*DM512];
__device__ __nv_bfloat16 S_ynhi[B16*L64*DM512];
__device__ __nv_bfloat16 S_ynlo[B16*L64*DM512];
__device__ __nv_bfloat16 S_W1hi[1152*DM512];
__device__ __nv_bfloat16 S_W1lo[1152*DM512];
__device__ __nv_bfloat16 S_W2hi[DM512*DM512];
__device__ __nv_bfloat16 S_W2lo[DM512*DM512];
__device__ __nv_bfloat16 S_Whi [DM512*DM512];
__device__ __nv_bfloat16 S_Wlo [DM512*DM512];
// Pt fp32 (tf32-pre-rounded): Pt[b][d][hg], natural layout
__device__ float S_Pt[(size_t)B16*DM512*DM512];

// ---- helpers ---------------------------------------------------------------
__device__ __forceinline__ void mma16816(float* c, const uint32_t* a, const uint32_t* b) {
    asm volatile(
        "mma.sync.aligned.m16n8k16.row.col.f32.bf16.bf16.f32 "
        "{%0,%1,%2,%3}, {%4,%5,%6,%7}, {%8,%9}, {%0,%1,%2,%3};"
        : "+f"(c[0]), "+f"(c[1]), "+f"(c[2]), "+f"(c[3])
        : "r"(a[0]), "r"(a[1]), "r"(a[2]), "r"(a[3]), "r"(b[0]), "r"(b[1]));
}
__device__ __forceinline__ void mma_tf32(float* c, const uint32_t* a, const uint32_t* b) {
    asm volatile(
        "mma.sync.aligned.m16n8k8.row.col.f32.tf32.tf32.f32 "
        "{%0,%1,%2,%3}, {%4,%5,%6,%7}, {%8,%9}, {%0,%1,%2,%3};"
        : "+f"(c[0]), "+f"(c[1]), "+f"(c[2]), "+f"(c[3])
        : "r"(a[0]), "r"(a[1]), "r"(a[2]), "r"(a[3]), "r"(b[0]), "r"(b[1]));
}
__device__ __forceinline__ float to_tf32(float x) {
    uint32_t r;
    asm("cvt.rna.tf32.f32 %0, %1;" : "=r"(r) : "f"(x));
    return __uint_as_float(r);
}
__device__ __forceinline__ void bsplit(float v, __nv_bfloat16& h, __nv_bfloat16& l) {
    h = __float2bfloat16(v);
    l = __float2bfloat16(v - __bfloat162float(h));
}
__device__ __forceinline__ void cp16(void* dst, const void* src) {
    uint32_t d = (uint32_t)__cvta_generic_to_shared(dst);
    asm volatile("cp.async.cg.shared.global [%0], [%1], 16;" :: "r"(d), "l"(src));
}
#define CP_COMMIT() asm volatile("cp.async.commit_group;" ::: "memory")
#define CP_WAIT1()  asm volatile("cp.async.wait_group 1;" ::: "memory")
#define CP_WAIT0()  asm volatile("cp.async.wait_group 0;" ::: "memory")

// ---------------------------------------------------------------------------
// One launch splits all 3 weight matrices into bf16 hi/lo.
__global__ void k_split3(const float* __restrict__ w_in,
                         const float* __restrict__ w_out,
                         const float* __restrict__ to_w) {
    int i = blockIdx.x * blockDim.x + threadIdx.x;
    if (i < DINPROJ*DM512) {
        __nv_bfloat16 h, l;
        bsplit(w_in[i], h, l);
        S_W1hi[i] = h; S_W1lo[i] = l;
    }
    if (i < DM512*DM512) {
        __nv_bfloat16 h, l;
        bsplit(w_out[i], h, l);
        S_W2hi[i] = h; S_W2lo[i] = l;
        bsplit(to_w[i], h, l);
        S_Whi[i] = h; S_Wlo[i] = l;
    }
}

// ---------------------------------------------------------------------------
// u transpose + split, and inp passthrough (same layout as st)
__global__ void k_transpose_u(const float* __restrict__ st, float* __restrict__ out_inp) {
    int row = blockIdx.x;
    int b = row >> 6, g = row & 63;
    int tid = threadIdx.x;
    int h = tid >> 6, c = tid & 63;
    size_t si = (((size_t)(b*8 + h)*64) + g)*64 + c;
    float v = st[si];
    out_inp[si] = v;
    __nv_bfloat16 vh, vl;
    bsplit(v, vh, vl);
    S_uhi[row*DM512 + tid] = vh;
    S_ulo[row*DM512 + tid] = vl;
}

// ---------------------------------------------------------------------------
// Presplit GEMM: C[m,n] = sum_k A[m,k]*B[n,k], split bf16, M=1024, K=512
#define GS_SMEM 81920
__global__ __launch_bounds__(256) void k_gemm_sp(
    const __nv_bfloat16* __restrict__ Ahi, const __nv_bfloat16* __restrict__ Alo,
    const __nv_bfloat16* __restrict__ Bhi, const __nv_bfloat16* __restrict__ Blo,
    float* __restrict__ C, int N)
{
    extern __shared__ __nv_bfloat16 smG[];
    int tid = threadIdx.x;
    int wid = tid >> 5, lane = tid & 31;
    int warp_m = wid & 1, warp_n = wid >> 1;
    int lr = lane >> 2;
    int lk = (lane & 3) * 2;
    size_t rbase = (size_t)blockIdx.x * 128;
    int n0 = blockIdx.y * 128;

    const int BUF = 4*128*40;
    int m_st = tid >> 2;
    int kp_st = tid & 3;

    auto stage = [&](int kc, int buf) {
        __nv_bfloat16* Ah = smG + buf*BUF;
        __nv_bfloat16* Al = Ah + 128*40;
        __nv_bfloat16* Wh = Al + 128*40;
        __nv_bfloat16* Wl = Wh + 128*40;
        int kofs = kc*32 + kp_st*8;
        #pragma unroll
        for (int p = 0; p < 2; ++p) {
            int m = m_st + p*64;
            size_t ga = (rbase + m)*512 + kofs;
            cp16(&Ah[m*40 + kp_st*8], &Ahi[ga]);
            cp16(&Al[m*40 + kp_st*8], &Alo[ga]);
            size_t gw = (size_t)(n0 + m)*512 + kofs;
            cp16(&Wh[m*40 + kp_st*8], &Bhi[gw]);
            cp16(&Wl[m*40 + kp_st*8], &Blo[gw]);
        }
    };

    float acc[4][4][4];
    #pragma unroll
    for (int mt = 0; mt < 4; ++mt)
        #pragma unroll
        for (int nt = 0; nt < 4; ++nt)
            #pragma unroll
            for (int q = 0; q < 4; ++q) acc[mt][nt][q] = 0.f;

    stage(0, 0);
    CP_COMMIT();

    for (int kc = 0; kc < 16; ++kc) {
        int cur = kc & 1;
        if (kc < 15) { stage(kc + 1, cur ^ 1); CP_COMMIT(); CP_WAIT1(); }
        else         { CP_WAIT0(); }
        __syncthreads();

        __nv_bfloat16* Ah = smG + cur*BUF;
        __nv_bfloat16* Al = Ah + 128*40;
        __nv_bfloat16* Wh = Al + 128*40;
        __nv_bfloat16* Wl = Wh + 128*40;

        #pragma unroll
        for (int ks = 0; ks < 2; ++ks) {
            int k0 = ks*16;
            uint32_t ah[4][4], al[4][4], bh[4][2], bl[4][2];
            #pragma unroll
            for (int mt = 0; mt < 4; ++mt) {
                int rb = warp_m*64 + mt*16 + lr;
                const __nv_bfloat16* pa = &Ah[rb*40 + k0 + lk];
                ah[mt][0] = *(const uint32_t*)pa;
                ah[mt][1] = *(const uint32_t*)(pa + 8*40);
                ah[mt][2] = *(const uint32_t*)(pa + 8);
                ah[mt][3] = *(const uint32_t*)(pa + 8*40 + 8);
                const __nv_bfloat16* pl = &Al[rb*40 + k0 + lk];
                al[mt][0] = *(const uint32_t*)pl;
                al[mt][1] = *(const uint32_t*)(pl + 8*40);
                al[mt][2] = *(const uint32_t*)(pl + 8);
                al[mt][3] = *(const uint32_t*)(pl + 8*40 + 8);
            }
            #pragma unroll
            for (int nt = 0; nt < 4; ++nt) {
                int nb = warp_n*32 + nt*8 + lr;
                const __nv_bfloat16* pb = &Wh[nb*40 + k0 + lk];
                bh[nt][0] = *(const uint32_t*)pb;
                bh[nt][1] = *(const uint32_t*)(pb + 8);
                const __nv_bfloat16* pl = &Wl[nb*40 + k0 + lk];
                bl[nt][0] = *(const uint32_t*)pl;
                bl[nt][1] = *(const uint32_t*)(pl + 8);
            }
            #pragma unroll
            for (int mt = 0; mt < 4; ++mt)
                #pragma unroll
                for (int nt = 0; nt < 4; ++nt) {
                    mma16816(acc[mt][nt], ah[mt], bh[nt]);
                    mma16816(acc[mt][nt], ah[mt], bl[nt]);
                    mma16816(acc[mt][nt], al[mt], bh[nt]);
                }
        }
        __syncthreads();
    }

    #pragma unroll
    for (int mt = 0; mt < 4; ++mt) {
        int m = warp_m*64 + mt*16 + lr;
        #pragma unroll
        for (int nt = 0; nt < 4; ++nt) {
            int col = n0 + warp_n*32 + nt*8 + lk;
            if (col < N) {
                size_t r = rbase + m;
                float2 v0;
                v0.x = acc[mt][nt][0];
                v0.y = acc[mt][nt][1];
                *(float2*)&C[r*N + col] = v0;
                float2 v1;
                v1.x = acc[mt][nt][2];
                v1.y = acc[mt][nt][3];
                *(float2*)&C[(r + 8)*N + col] = v1;
            }
        }
    }
}

// ---------------------------------------------------------------------------
__global__ void k_conv(const float* __restrict__ conv_w, const float* __restrict__ conv_b) {
    int row = blockIdx.x;
    int t = row & 63;
    int c = threadIdx.x;
    if (c >= CONVDIM) return;
    float acc = conv_b[c];
    #pragma unroll
    for (int k = 0; k < 3; ++k) {
        int tt = t + k - 2;
        if (tt >= 0) acc += conv_w[c*3 + k] * S_zx[(row + (k - 2))*DINPROJ + 512 + c];
    }
    acc = acc / (1.f + expf(-acc));
    if (c < 512)       S_x[row*512 + c] = acc;
    else if (c == 512) S_Bv[row] = acc;
    else               S_Cv[row] = acc;
}

// ---------------------------------------------------------------------------
#define SC_SMEM (64*512*4 + 512*4 + 128*4)
__global__ __launch_bounds__(512) void k_scan(
    const float* __restrict__ dt_bias, const float* __restrict__ A_log)
{
    extern __shared__ float smS[];
    float* xs  = smS;
    float* dts = smS + 64*512;
    float* Bs  = dts + 512;
    float* Cs  = Bs + 64;

    int i = blockIdx.x;
    int d = threadIdx.x;
    bool bw = (i >= 16);
    int b = bw ? i - 16 : i;

    #pragma unroll
    for (int p = 0; p < 16; ++p) {
        int idx = d + p*512;
        int row = idx >> 7;
        int c4 = (idx & 127) * 4;
        cp16(&xs[row*512 + c4], &S_x[(b*64 + row)*512 + c4]);
    }
    {
        int row = d >> 3, hh = d & 7;
        dts[d] = S_zx[(b*64 + row)*DINPROJ + 1026 + (bw ? 8 : 0) + hh];
    }
    if (d < 64) { Bs[d] = S_Bv[b*64 + d]; Cs[d] = S_Cv[b*64 + d]; }
    CP_COMMIT();
    CP_WAIT0();
    __syncthreads();

    int h = d >> 6;
    float Ah = -expf(A_log[h]);
    float bias = dt_bias[h];
    float hs = 0.f;
    S_ys[(i*64)*512 + d] = 0.f;
    #pragma unroll 4
    for (int t = 0; t < 64; ++t) {
        int tt = bw ? (63 - t) : t;
        float x  = xs[tt*512 + d];
        float v  = dts[tt*8 + h] + bias;
        float dt = (v > 20.f) ? v : log1pf(expf(v));
        float a  = expf(dt * Ah);
        hs = a*hs + dt*Bs[tt]*x;
        if (t < 63) S_ys[(i*64 + t + 1)*512 + d] = hs * Cs[tt];
    }
}

// ---------------------------------------------------------------------------
__global__ __launch_bounds__(512) void k_combine(
    const float* __restrict__ fc_D_w, const float* __restrict__ Dv,
    const float* __restrict__ norm_w)
{
    int row = blockIdx.x;
    int b = row >> 6, t = row & 63;
    int d = threadIdx.x;
    int h = d >> 6;
    int lane = d & 31, wid = d >> 5;

    float x  = S_x[row*512 + d];
    float z  = S_zx[row*DINPROJ + d];
    float yf = S_ys[row*512 + d];
    float yb = S_ys[((16 + b)*64 + (63 - t))*512 + d];

    float px[8];
    #pragma unroll
    for (int hh = 0; hh < 8; ++hh) px[hh] = x * fc_D_w[hh*512 + d];
    #pragma unroll
    for (int off = 16; off; off >>= 1)
        #pragma unroll
        for (int hh = 0; hh < 8; ++hh) px[hh] += __shfl_xor_sync(0xffffffffu, px[hh], off);

    __shared__ float wsum[16][8];
    __shared__ float dcf[8];
    if (lane == 0) {
        #pragma unroll
        for (int hh = 0; hh < 8; ++hh) wsum[wid][hh] = px[hh];
    }
    __syncthreads();
    if (d < 8) {
        float s = 0.f;
        #pragma unroll
        for (int w = 0; w < 16; ++w) s += wsum[w][d];
        dcf[d] = s + Dv[d];
    }
    __syncthreads();

    float y = yf + yb + x * dcf[h];
    y *= z / (1.f + expf(-z));

    float sq = y*y;
    #pragma unroll
    for (int off = 16; off; off >>= 1) sq += __shfl_xor_sync(0xffffffffu, sq, off);
    __shared__ float rsum[16];
    __shared__ float rscale;
    if (lane == 0) rsum[wid] = sq;
    __syncthreads();
    if (d == 0) {
        float s = 0.f;
        #pragma unroll
        for (int w = 0; w < 16; ++w) s += rsum[w];
        rscale = rsqrtf(s / 512.f + 1e-5f);
    }
    __syncthreads();
    float yn = y * rscale * norm_w[d];
    __nv_bfloat16 vh, vl;
    bsplit(yn, vh, vl);
    S_ynhi[row*512 + d] = vh;
    S_ynlo[row*512 + d] = vl;
}

// ---------------------------------------------------------------------------
__global__ void k_permute(float* __restrict__ outp) {
    int row = blockIdx.x;
    int b = row >> 6, g = row & 63;
    int tid = threadIdx.x;
    int h = tid >> 6, c = tid & 63;
    outp[(((b*8 + h)*64 + g)*64) + c] = S_out[row*512 + tid];
}

// ---------------------------------------------------------------------------
// prepP: Pt[b][d][h*64+g] = sum_c to_w[d, h*64+c] * S_out[(b*64+g)*512 + h*64+c]
// Split-bf16 mma; epilogue writes tf32-rounded fp32 into S_Pt (natural layout).
#define PP_SMEM 55296
__global__ __launch_bounds__(256) void k_prepP() {
    extern __shared__ __nv_bfloat16 smP[];
    __nv_bfloat16* Ahs = smP;
    __nv_bfloat16* Als = smP + 128*72;
    __nv_bfloat16* Bhs = smP + 2*128*72;
    __nv_bfloat16* Bls = Bhs + 64*72;

    int tid = threadIdx.x;
    int wid = tid >> 5, lane = tid & 31;
    int warp_m = wid & 1, warp_n = wid >> 1;
    int lr = lane >> 2;
    int lk = (lane & 3) * 2;
    int bh = blockIdx.x;
    int b = bh >> 3, h = bh & 7;
    int dbase = blockIdx.y * 128;

    {
        int r = tid >> 1, half = tid & 1;
        #pragma unroll
        for (int q0 = 0; q0 < 4; ++q0) {
            int q = half*4 + q0;
            size_t src = (size_t)(dbase + r)*512 + h*64 + q*8;
            cp16(&Ahs[r*72 + q*8], &S_Whi[src]);
            cp16(&Als[r*72 + q*8], &S_Wlo[src]);
        }
    }
    #pragma unroll
    for (int p = 0; p < 16; ++p) {
        int idx = tid + p*256;
        int g = idx >> 6, c = idx & 63;
        float v = S_out[(size_t)(b*64 + g)*512 + h*64 + c];
        __nv_bfloat16 vh, vl;
        bsplit(v, vh, vl);
        Bhs[g*72 + c] = vh;
        Bls[g*72 + c] = vl;
    }
    CP_COMMIT();
    CP_WAIT0();
    __syncthreads();

    float acc[4][2][4];
    #pragma unroll
    for (int mt = 0; mt < 4; ++mt)
        #pragma unroll
        for (int nt = 0; nt < 2; ++nt)
            #pragma unroll
            for (int q = 0; q < 4; ++q) acc[mt][nt][q] = 0.f;

    #pragma unroll
    for (int ks = 0; ks < 4; ++ks) {
        int k0 = ks*16;
        uint32_t ah[4][4], al[4][4], bhf[2][2], blf[2][2];
        #pragma unroll
        for (int mt = 0; mt < 4; ++mt) {
            int rb = warp_m*64 + mt*16 + lr;
            const __nv_bfloat16* pa = &Ahs[rb*72 + k0 + lk];
            ah[mt][0] = *(const uint32_t*)pa;
            ah[mt][1] = *(const uint32_t*)(pa + 8*72);
            ah[mt][2] = *(const uint32_t*)(pa + 8);
            ah[mt][3] = *(const uint32_t*)(pa + 8*72 + 8);
            const __nv_bfloat16* pl = &Als[rb*72 + k0 + lk];
            al[mt][0] = *(const uint32_t*)pl;
            al[mt][1] = *(const uint32_t*)(pl + 8*72);
            al[mt][2] = *(const uint32_t*)(pl + 8);
            al[mt][3] = *(const uint32_t*)(pl + 8*72 + 8);
        }
        #pragma unroll
        for (int nt = 0; nt < 2; ++nt) {
            int nb = warp_n*16 + nt*8 + lr;
            const __nv_bfloat16* pb = &Bhs[nb*72 + k0 + lk];
            bhf[nt][0] = *(const uint32_t*)pb;
            bhf[nt][1] = *(const uint32_t*)(pb + 8);
            const __nv_bfloat16* pl = &Bls[nb*72 + k0 + lk];
            blf[nt][0] = *(const uint32_t*)pl;
            blf[nt][1] = *(const uint32_t*)(pl + 8);
        }
        #pragma unroll
        for (int mt = 0; mt < 4; ++mt)
            #pragma unroll
            for (int nt = 0; nt < 2; ++nt) {
                mma16816(acc[mt][nt], ah[mt], bhf[nt]);
                mma16816(acc[mt][nt], ah[mt], blf[nt]);
                mma16816(acc[mt][nt], al[mt], bhf[nt]);
            }
    }

    // epilogue: tf32-round, write fp32 Pt (natural layout)
    #pragma unroll
    for (int mt = 0; mt < 4; ++mt) {
        int m = warp_m*64 + mt*16 + lr;
        #pragma unroll
        for (int nt = 0; nt < 2; ++nt) {
            int coln = warp_n*16 + nt*8 + lk;
            size_t base = ((size_t)b*512 + dbase + m)*512 + h*64 + coln;
            float2 v0;
            v0.x = to_tf32(acc[mt][nt][0]);
            v0.y = to_tf32(acc[mt][nt][1]);
            *(float2*)&S_Pt[base] = v0;
            float2 v1;
            v1.x = to_tf32(acc[mt][nt][2]);
            v1.y = to_tf32(acc[mt][nt][3]);
            *(float2*)&S_Pt[base + 8*512] = v1;
        }
    }
}

// ---------------------------------------------------------------------------
// Big GEMM (tf32): out[b, n, dbase+col] = sum_hg sw[b,h,n,g]*Pt[b][d][hg] + bias
// Grid (100 = mtile*4+dchunk, 16 b), 256 threads. BK=32 double-buffered.
// smem fp32 stride 36: A[128][36], B[128][36] per buffer = 36864 B; x2 = 73728.
#define BM_SMEM 73728
__global__ __launch_bounds__(256) void k_bigmma(
    const float* __restrict__ sw, const float* __restrict__ bias,
    float* __restrict__ out)
{
    extern __shared__ float smB[];
    int tid = threadIdx.x;
    int wid = tid >> 5, lane = tid & 31;
    int warp_m = wid & 1, warp_n = wid >> 1;
    int lr = lane >> 2;
    int lq = lane & 3;
    int dc = blockIdx.x & 3;
    int mt0 = blockIdx.x >> 2;
    int n0 = mt0 * 128;
    int b  = blockIdx.y;
    int dbase = dc * 128;

    const int BUF = 2*128*36;    // floats per buffer (A + B)
    int arow = tid >> 1;         // 0..127
    int ahalf = tid & 1;

    float4 rg[4];
    auto ldgA = [&](int kc) {
        int h = kc >> 1;
        int g0 = (kc & 1)*32 + ahalf*16;
        if (n0 + arow < NCTX) {
            const float4* p = (const float4*)(sw + ((size_t)(b*8 + h)*NCTX + n0 + arow)*64 + g0);
            rg[0] = p[0]; rg[1] = p[1]; rg[2] = p[2]; rg[3] = p[3];
        } else {
            rg[0] = rg[1] = rg[2] = rg[3] = make_float4(0.f, 0.f, 0.f, 0.f);
        }
    };
    auto stsA = [&](int buf) {
        float* As = smB + buf*BUF;
        float4* dst = (float4*)&As[arow*36 + ahalf*16];
        #pragma unroll
        for (int q = 0; q < 4; ++q) {
            float4 v = rg[q];
            v.x = to_tf32(v.x); v.y = to_tf32(v.y);
            v.z = to_tf32(v.z); v.w = to_tf32(v.w);
            dst[q] = v;
        }
    };
    auto stageB = [&](int kc, int buf) {
        float* Bs = smB + buf*BUF + 128*36;
        #pragma unroll
        for (int p = 0; p < 4; ++p) {
            int idx = tid + p*256;
            int row = idx >> 3, q = idx & 7;
            size_t src = ((size_t)b*512 + dbase + row)*512 + kc*32 + q*4;
            cp16(&Bs[row*36 + q*4], &S_Pt[src]);
        }
    };

    float acc[4][4][4];
    #pragma unroll
    for (int mt = 0; mt < 4; ++mt)
        #pragma unroll
        for (int nt = 0; nt < 4; ++nt)
            #pragma unroll
            for (int q = 0; q < 4; ++q) acc[mt][nt][q] = 0.f;

    ldgA(0);
    stsA(0);
    stageB(0, 0);
    CP_COMMIT();

    for (int kc = 0; kc < 16; ++kc) {
        int cur = kc & 1;
        if (kc < 15) { ldgA(kc + 1); stageB(kc + 1, cur ^ 1); CP_COMMIT(); CP_WAIT1(); }
        else         { CP_WAIT0(); }
        __syncthreads();

        float* As = smB + cur*BUF;
        float* Bs = As + 128*36;

        #pragma unroll
        for (int ks = 0; ks < 4; ++ks) {
            int k0 = ks*8;
            uint32_t af[4][4], bf[4][2];
            #pragma unroll
            for (int mt = 0; mt < 4; ++mt) {
                int rb = warp_m*64 + mt*16 + lr;
                const float* pa = &As[rb*36 + k0 + lq];
                af[mt][0] = __float_as_uint(pa[0]);
                af[mt][1] = __float_as_uint(pa[8*36]);
                af[mt][2] = __float_as_uint(pa[4]);
                af[mt][3] = __float_as_uint(pa[8*36 + 4]);
            }
            #pragma unroll
            for (int nt = 0; nt < 4; ++nt) {
                int nb = warp_n*32 + nt*8 + lr;
                const float* pb = &Bs[nb*36 + k0 + lq];
                bf[nt][0] = __float_as_uint(pb[0]);
                bf[nt][1] = __float_as_uint(pb[4]);
            }
            #pragma unroll
            for (int mt = 0; mt < 4; ++mt)
                #pragma unroll
                for (int nt = 0; nt < 4; ++nt)
                    mma_tf32(acc[mt][nt], af[mt], bf[nt]);
        }
        if (kc < 15) stsA(cur ^ 1);
    }

    // epilogue
    #pragma unroll
    for (int mt = 0; mt < 4; ++mt) {
        int m = warp_m*64 + mt*16 + lr;
        #pragma unroll
        for (int nt = 0; nt < 4; ++nt) {
            int col = dbase + warp_n*32 + nt*8 + lq*2;
            float b0 = __ldg(&bias[col]);
            float b1 = __ldg(&bias[col + 1]);
            if (n0 + m < NCTX) {
                size_t r = (size_t)b*NCTX + n0 + m;
                float2 v;
                v.x = acc[mt][nt][0] + b0;
                v.y = acc[mt][nt][1] + b1;
                *(float2*)&out[r*512 + col] = v;
            }
            if (n0 + m + 8 < NCTX) {
                size_t r = (size_t)b*NCTX + n0 + m + 8;
                float2 v;
                v.x = acc[mt][nt][2] + b0;
                v.y = acc[mt][nt][3] + b1;
                *(float2*)&out[r*512 + col] = v;
            }
        }
    }
}

// ---------------------------------------------------------------------------
extern "C" void kernel_launch(void* const* d_in, const int* in_sizes, int n_in,
                              void* d_out, int out_size) {
    const float* st     = (const float*)d_in[0];
    const float* sw     = (const float*)d_in[1];
    const float* w_in   = (const float*)d_in[2];
    const float* conv_w = (const float*)d_in[3];
    const float* conv_b = (const float*)d_in[4];
    const float* dt_bias= (const float*)d_in[5];
    const float* A_log  = (const float*)d_in[6];
    const float* Dv     = (const float*)d_in[7];
    const float* fc_D_w = (const float*)d_in[8];
    const float* norm_w = (const float*)d_in[9];
    const float* w_out  = (const float*)d_in[10];
    const float* to_w   = (const float*)d_in[11];
    const float* to_b   = (const float*)d_in[12];

    float* out       = (float*)d_out;
    float* out_final = out;
    float* out_inp   = out + (size_t)B16*NCTX*DM512;
    float* out_outp  = out_inp + (size_t)B16*8*64*64;

    float *pSzx, *pSout;
    __nv_bfloat16 *pUh, *pUl, *pYh, *pYl, *pW1h, *pW1l, *pW2h, *pW2l;
    cudaGetSymbolAddress((void**)&pSzx, S_zx);
    cudaGetSymbolAddress((void**)&pSout, S_out);
    cudaGetSymbolAddress((void**)&pUh, S_uhi);
    cudaGetSymbolAddress((void**)&pUl, S_ulo);
    cudaGetSymbolAddress((void**)&pYh, S_ynhi);
    cudaGetSymbolAddress((void**)&pYl, S_ynlo);
    cudaGetSymbolAddress((void**)&pW1h, S_W1hi);
    cudaGetSymbolAddress((void**)&pW1l, S_W1lo);
    cudaGetSymbolAddress((void**)&pW2h, S_W2hi);
    cudaGetSymbolAddress((void**)&pW2l, S_W2lo);

    k_split3<<<(DINPROJ*DM512 + 511)/512, 512>>>(w_in, w_out, to_w);

    k_transpose_u<<<B16*L64, 512>>>(st, out_inp);

    cudaFuncSetAttribute(k_gemm_sp, cudaFuncAttributeMaxDynamicSharedMemorySize, GS_SMEM);
    k_gemm_sp<<<dim3(8, 9), 256, GS_SMEM>>>(pUh, pUl, pW1h, pW1l, pSzx, DINPROJ);

    k_conv<<<B16*L64, 544>>>(conv_w, conv_b);

    cudaFuncSetAttribute(k_scan, cudaFuncAttributeMaxDynamicSharedMemorySize, SC_SMEM);
    k_scan<<<32, 512, SC_SMEM>>>(dt_bias, A_log);

    k_combine<<<B16*L64, 512>>>(fc_D_w, Dv, norm_w);

    k_gemm_sp<<<dim3(8, 4), 256, GS_SMEM>>>(pYh, pYl, pW2h, pW2l, pSout, DM512);

    k_permute<<<B16*L64, 512>>>(out_outp);

    cudaFuncSetAttribute(k_prepP, cudaFuncAttributeMaxDynamicSharedMemorySize, PP_SMEM);
    k_prepP<<<dim3(128, 4), 256, PP_SMEM>>>();

    cudaFuncSetAttribute(k_bigmma, cudaFuncAttributeMaxDynamicSharedMemorySize, BM_SMEM);
    k_bigmma<<<dim3(4*((NCTX + 127)/128), B16), 256, BM_SMEM>>>(sw, to_b, out_final);
}

// round 11
// speedup vs baseline: 5.0460x; 1.0068x over previous
#include <cuda_runtime.h>
#include <cuda_bf16.h>
#include <math.h>
#include <stdint.h>

// Problem constants
#define B16    16
#define L64    64
#define DM512  512
#define NCTX   3131
#define DINPROJ 1042
#define CONVDIM 514
#define MROWS  50096            // 16*3131

// Scratch (static device arrays; zero-initialized, allocation-free)
__device__ float S_zx [B16*L64*DINPROJ];
__device__ float S_x  [B16*L64*DM512];
__device__ float S_ys [2*B16*L64*DM512];
__device__ float S_out[B16*L64*DM512];
// split-bf16 operands (pre-pipeline)
__device__ __nv_bfloat16 S_uhi [B16*L64*DM512];
__device__ __nv_bfloat16 S_ulo [B16*L64*DM512];
__device__ __nv_bfloat16 S_ynhi[B16*L64*DM512];
__device__ __nv_bfloat16 S_ynlo[B16*L64*DM512];
__device__ __nv_bfloat16 S_W1hi[1152*DM512];
__device__ __nv_bfloat16 S_W1lo[1152*DM512];
__device__ __nv_bfloat16 S_W2hi[DM512*DM512];
__device__ __nv_bfloat16 S_W2lo[DM512*DM512];
__device__ __nv_bfloat16 S_Whi [DM512*DM512];
__device__ __nv_bfloat16 S_Wlo [DM512*DM512];
// Pt fp32 (tf32-pre-rounded): Pt[b][d][hg], natural layout
__device__ float S_Pt[(size_t)B16*DM512*DM512];

// ---- helpers ---------------------------------------------------------------
__device__ __forceinline__ void mma16816(float* c, const uint32_t* a, const uint32_t* b) {
    asm volatile(
        "mma.sync.aligned.m16n8k16.row.col.f32.bf16.bf16.f32 "
        "{%0,%1,%2,%3}, {%4,%5,%6,%7}, {%8,%9}, {%0,%1,%2,%3};"
        : "+f"(c[0]), "+f"(c[1]), "+f"(c[2]), "+f"(c[3])
        : "r"(a[0]), "r"(a[1]), "r"(a[2]), "r"(a[3]), "r"(b[0]), "r"(b[1]));
}
__device__ __forceinline__ void mma_tf32(float* c, const uint32_t* a, const uint32_t* b) {
    asm volatile(
        "mma.sync.aligned.m16n8k8.row.col.f32.tf32.tf32.f32 "
        "{%0,%1,%2,%3}, {%4,%5,%6,%7}, {%8,%9}, {%0,%1,%2,%3};"
        : "+f"(c[0]), "+f"(c[1]), "+f"(c[2]), "+f"(c[3])
        : "r"(a[0]), "r"(a[1]), "r"(a[2]), "r"(a[3]), "r"(b[0]), "r"(b[1]));
}
__device__ __forceinline__ float to_tf32(float x) {
    uint32_t r;
    asm("cvt.rna.tf32.f32 %0, %1;" : "=r"(r) : "f"(x));
    return __uint_as_float(r);
}
__device__ __forceinline__ uint32_t to_tf32b(float x) {
    uint32_t r;
    asm("cvt.rna.tf32.f32 %0, %1;" : "=r"(r) : "f"(x));
    return r;
}
__device__ __forceinline__ void bsplit(float v, __nv_bfloat16& h, __nv_bfloat16& l) {
    h = __float2bfloat16(v);
    l = __float2bfloat16(v - __bfloat162float(h));
}
__device__ __forceinline__ void cp16(void* dst, const void* src) {
    uint32_t d = (uint32_t)__cvta_generic_to_shared(dst);
    asm volatile("cp.async.cg.shared.global [%0], [%1], 16;" :: "r"(d), "l"(src));
}
// predicated 16B cp.async: src_size=0 zero-fills dst (OOB rows)
__device__ __forceinline__ void cp16p(void* dst, const void* src, bool pred) {
    uint32_t d = (uint32_t)__cvta_generic_to_shared(dst);
    int sz = pred ? 16 : 0;
    asm volatile("cp.async.cg.shared.global [%0], [%1], 16, %2;" :: "r"(d), "l"(src), "r"(sz));
}
__device__ __forceinline__ void cp8(void* dst, const void* src) {
    uint32_t d = (uint32_t)__cvta_generic_to_shared(dst);
    asm volatile("cp.async.ca.shared.global [%0], [%1], 8;" :: "r"(d), "l"(src));
}
#define CP_COMMIT() asm volatile("cp.async.commit_group;" ::: "memory")
#define CP_WAIT1()  asm volatile("cp.async.wait_group 1;" ::: "memory")
#define CP_WAIT0()  asm volatile("cp.async.wait_group 0;" ::: "memory")

// ---------------------------------------------------------------------------
// One launch splits all 3 weight matrices into bf16 hi/lo.
__global__ void k_split3(const float* __restrict__ w_in,
                         const float* __restrict__ w_out,
                         const float* __restrict__ to_w) {
    int i = blockIdx.x * blockDim.x + threadIdx.x;
    if (i < DINPROJ*DM512) {
        __nv_bfloat16 h, l;
        bsplit(w_in[i], h, l);
        S_W1hi[i] = h; S_W1lo[i] = l;
    }
    if (i < DM512*DM512) {
        __nv_bfloat16 h, l;
        bsplit(w_out[i], h, l);
        S_W2hi[i] = h; S_W2lo[i] = l;
        bsplit(to_w[i], h, l);
        S_Whi[i] = h; S_Wlo[i] = l;
    }
}

// ---------------------------------------------------------------------------
// u transpose + split, and inp passthrough (same layout as st)
__global__ void k_transpose_u(const float* __restrict__ st, float* __restrict__ out_inp) {
    int row = blockIdx.x;
    int b = row >> 6, g = row & 63;
    int tid = threadIdx.x;
    int h = tid >> 6, c = tid & 63;
    size_t si = (((size_t)(b*8 + h)*64) + g)*64 + c;
    float v = st[si];
    out_inp[si] = v;
    __nv_bfloat16 vh, vl;
    bsplit(v, vh, vl);
    S_uhi[row*DM512 + tid] = vh;
    S_ulo[row*DM512 + tid] = vl;
}

// ---------------------------------------------------------------------------
// Presplit GEMM: C[m,n] = sum_k A[m,k]*B[n,k], split bf16, M=1024, K=512
#define GS_SMEM 81920
__global__ __launch_bounds__(256) void k_gemm_sp(
    const __nv_bfloat16* __restrict__ Ahi, const __nv_bfloat16* __restrict__ Alo,
    const __nv_bfloat16* __restrict__ Bhi, const __nv_bfloat16* __restrict__ Blo,
    float* __restrict__ C, int N)
{
    extern __shared__ __nv_bfloat16 smG[];
    int tid = threadIdx.x;
    int wid = tid >> 5, lane = tid & 31;
    int warp_m = wid & 1, warp_n = wid >> 1;
    int lr = lane >> 2;
    int lk = (lane & 3) * 2;
    size_t rbase = (size_t)blockIdx.x * 128;
    int n0 = blockIdx.y * 128;

    const int BUF = 4*128*40;
    int m_st = tid >> 2;
    int kp_st = tid & 3;

    auto stage = [&](int kc, int buf) {
        __nv_bfloat16* Ah = smG + buf*BUF;
        __nv_bfloat16* Al = Ah + 128*40;
        __nv_bfloat16* Wh = Al + 128*40;
        __nv_bfloat16* Wl = Wh + 128*40;
        int kofs = kc*32 + kp_st*8;
        #pragma unroll
        for (int p = 0; p < 2; ++p) {
            int m = m_st + p*64;
            size_t ga = (rbase + m)*512 + kofs;
            cp16(&Ah[m*40 + kp_st*8], &Ahi[ga]);
            cp16(&Al[m*40 + kp_st*8], &Alo[ga]);
            size_t gw = (size_t)(n0 + m)*512 + kofs;
            cp16(&Wh[m*40 + kp_st*8], &Bhi[gw]);
            cp16(&Wl[m*40 + kp_st*8], &Blo[gw]);
        }
    };

    float acc[4][4][4];
    #pragma unroll
    for (int mt = 0; mt < 4; ++mt)
        #pragma unroll
        for (int nt = 0; nt < 4; ++nt)
            #pragma unroll
            for (int q = 0; q < 4; ++q) acc[mt][nt][q] = 0.f;

    stage(0, 0);
    CP_COMMIT();

    for (int kc = 0; kc < 16; ++kc) {
        int cur = kc & 1;
        if (kc < 15) { stage(kc + 1, cur ^ 1); CP_COMMIT(); CP_WAIT1(); }
        else         { CP_WAIT0(); }
        __syncthreads();

        __nv_bfloat16* Ah = smG + cur*BUF;
        __nv_bfloat16* Al = Ah + 128*40;
        __nv_bfloat16* Wh = Al + 128*40;
        __nv_bfloat16* Wl = Wh + 128*40;

        #pragma unroll
        for (int ks = 0; ks < 2; ++ks) {
            int k0 = ks*16;
            uint32_t ah[4][4], al[4][4], bh[4][2], bl[4][2];
            #pragma unroll
            for (int mt = 0; mt < 4; ++mt) {
                int rb = warp_m*64 + mt*16 + lr;
                const __nv_bfloat16* pa = &Ah[rb*40 + k0 + lk];
                ah[mt][0] = *(const uint32_t*)pa;
                ah[mt][1] = *(const uint32_t*)(pa + 8*40);
                ah[mt][2] = *(const uint32_t*)(pa + 8);
                ah[mt][3] = *(const uint32_t*)(pa + 8*40 + 8);
                const __nv_bfloat16* pl = &Al[rb*40 + k0 + lk];
                al[mt][0] = *(const uint32_t*)pl;
                al[mt][1] = *(const uint32_t*)(pl + 8*40);
                al[mt][2] = *(const uint32_t*)(pl + 8);
                al[mt][3] = *(const uint32_t*)(pl + 8*40 + 8);
            }
            #pragma unroll
            for (int nt = 0; nt < 4; ++nt) {
                int nb = warp_n*32 + nt*8 + lr;
                const __nv_bfloat16* pb = &Wh[nb*40 + k0 + lk];
                bh[nt][0] = *(const uint32_t*)pb;
                bh[nt][1] = *(const uint32_t*)(pb + 8);
                const __nv_bfloat16* pl = &Wl[nb*40 + k0 + lk];
                bl[nt][0] = *(const uint32_t*)pl;
                bl[nt][1] = *(const uint32_t*)(pl + 8);
            }
            #pragma unroll
            for (int mt = 0; mt < 4; ++mt)
                #pragma unroll
                for (int nt = 0; nt < 4; ++nt) {
                    mma16816(acc[mt][nt], ah[mt], bh[nt]);
                    mma16816(acc[mt][nt], ah[mt], bl[nt]);
                    mma16816(acc[mt][nt], al[mt], bh[nt]);
                }
        }
        __syncthreads();
    }

    #pragma unroll
    for (int mt = 0; mt < 4; ++mt) {
        int m = warp_m*64 + mt*16 + lr;
        #pragma unroll
        for (int nt = 0; nt < 4; ++nt) {
            int col = n0 + warp_n*32 + nt*8 + lk;
            if (col < N) {
                size_t r = rbase + m;
                float2 v0;
                v0.x = acc[mt][nt][0];
                v0.y = acc[mt][nt][1];
                *(float2*)&C[r*N + col] = v0;
                float2 v1;
                v1.x = acc[mt][nt][2];
                v1.y = acc[mt][nt][3];
                *(float2*)&C[(r + 8)*N + col] = v1;
            }
        }
    }
}

// ---------------------------------------------------------------------------
// Fused conv + scan. Grid 32 (one CTA per extended batch i), 512 threads.
// Stages zx cols [512, 1026) (x + B + C channels) in smem via 8B cp.async,
// computes depthwise conv + SiLU inline, then the sequential scan.
// fw CTAs (i<16) also store S_x for k_combine.
#define ZS_LD 516
#define SC_SMEM (64*ZS_LD*4 + 512*4 + 128*4)
__global__ __launch_bounds__(512) void k_scanc(
    const float* __restrict__ conv_w, const float* __restrict__ conv_b,
    const float* __restrict__ dt_bias, const float* __restrict__ A_log)
{
    extern __shared__ float smS[];
    float* zs  = smS;              // [64][516]: conv input, cols 512..1025
    float* dts = smS + 64*ZS_LD;   // [64][8]
    float* Bs  = dts + 512;        // [64]
    float* Cs  = Bs + 64;          // [64]

    int i = blockIdx.x;
    int d = threadIdx.x;
    bool bw = (i >= 16);
    int b = bw ? i - 16 : i;

    // stage zs: 64 rows x 514 cols -> 64 x 257 float2 via cp8 (16B misaligned
    // because DINPROJ=1042 is not a multiple of 4)
    for (int p = 0; p < 33; ++p) {
        int idx = d + p*512;
        if (idx < 64*257) {
            int row = idx / 257, pr = idx - row*257;
            cp8(&zs[row*ZS_LD + pr*2],
                &S_zx[(size_t)(b*64 + row)*DINPROJ + 512 + pr*2]);
        }
    }
    {
        int row = d >> 3, hh = d & 7;
        dts[d] = S_zx[(b*64 + row)*DINPROJ + 1026 + (bw ? 8 : 0) + hh];
    }
    CP_COMMIT();
    CP_WAIT0();
    __syncthreads();

    // B / C channels: conv + silu (parallel over t)
    if (d < 64) {
        int t = d;
        float acc = conv_b[512];
        #pragma unroll
        for (int k = 0; k < 3; ++k) {
            int tt = t + k - 2;
            if (tt >= 0) acc += conv_w[512*3 + k] * zs[tt*ZS_LD + 512];
        }
        Bs[t] = acc / (1.f + expf(-acc));
    } else if (d < 128) {
        int t = d - 64;
        float acc = conv_b[513];
        #pragma unroll
        for (int k = 0; k < 3; ++k) {
            int tt = t + k - 2;
            if (tt >= 0) acc += conv_w[513*3 + k] * zs[tt*ZS_LD + 513];
        }
        Cs[t] = acc / (1.f + expf(-acc));
    }
    __syncthreads();

    int h = d >> 6;
    float Ah   = -expf(A_log[h]);
    float bias = dt_bias[h];
    float cb = conv_b[d];
    float w0 = conv_w[d*3], w1 = conv_w[d*3 + 1], w2 = conv_w[d*3 + 2];
    float hs = 0.f;
    S_ys[(i*64)*512 + d] = 0.f;
    #pragma unroll 4
    for (int t = 0; t < 64; ++t) {
        int tt = bw ? (63 - t) : t;
        float z0  = zs[tt*ZS_LD + d];
        float zm1 = (tt >= 1) ? zs[(tt - 1)*ZS_LD + d] : 0.f;
        float zm2 = (tt >= 2) ? zs[(tt - 2)*ZS_LD + d] : 0.f;
        float cv = cb + w0*zm2 + w1*zm1 + w2*z0;
        float x  = cv / (1.f + expf(-cv));
        if (!bw) S_x[(b*64 + tt)*512 + d] = x;
        float v  = dts[tt*8 + h] + bias;
        float dt = (v > 20.f) ? v : log1pf(expf(v));
        float a  = expf(dt * Ah);
        hs = a*hs + dt*Bs[tt]*x;
        if (t < 63) S_ys[(i*64 + t + 1)*512 + d] = hs * Cs[tt];
    }
}

// ---------------------------------------------------------------------------
__global__ __launch_bounds__(512) void k_combine(
    const float* __restrict__ fc_D_w, const float* __restrict__ Dv,
    const float* __restrict__ norm_w)
{
    int row = blockIdx.x;
    int b = row >> 6, t = row & 63;
    int d = threadIdx.x;
    int h = d >> 6;
    int lane = d & 31, wid = d >> 5;

    float x  = S_x[row*512 + d];
    float z  = S_zx[row*DINPROJ + d];
    float yf = S_ys[row*512 + d];
    float yb = S_ys[((16 + b)*64 + (63 - t))*512 + d];

    float px[8];
    #pragma unroll
    for (int hh = 0; hh < 8; ++hh) px[hh] = x * fc_D_w[hh*512 + d];
    #pragma unroll
    for (int off = 16; off; off >>= 1)
        #pragma unroll
        for (int hh = 0; hh < 8; ++hh) px[hh] += __shfl_xor_sync(0xffffffffu, px[hh], off);

    __shared__ float wsum[16][8];
    __shared__ float dcf[8];
    if (lane == 0) {
        #pragma unroll
        for (int hh = 0; hh < 8; ++hh) wsum[wid][hh] = px[hh];
    }
    __syncthreads();
    if (d < 8) {
        float s = 0.f;
        #pragma unroll
        for (int w = 0; w < 16; ++w) s += wsum[w][d];
        dcf[d] = s + Dv[d];
    }
    __syncthreads();

    float y = yf + yb + x * dcf[h];
    y *= z / (1.f + expf(-z));

    float sq = y*y;
    #pragma unroll
    for (int off = 16; off; off >>= 1) sq += __shfl_xor_sync(0xffffffffu, sq, off);
    __shared__ float rsum[16];
    __shared__ float rscale;
    if (lane == 0) rsum[wid] = sq;
    __syncthreads();
    if (d == 0) {
        float s = 0.f;
        #pragma unroll
        for (int w = 0; w < 16; ++w) s += rsum[w];
        rscale = rsqrtf(s / 512.f + 1e-5f);
    }
    __syncthreads();
    float yn = y * rscale * norm_w[d];
    __nv_bfloat16 vh, vl;
    bsplit(yn, vh, vl);
    S_ynhi[row*512 + d] = vh;
    S_ynlo[row*512 + d] = vl;
}

// ---------------------------------------------------------------------------
// prepP: Pt[b][d][h*64+g] = sum_c to_w[d, h*64+c] * S_out[(b*64+g)*512 + h*64+c]
// Split-bf16 mma; epilogue writes tf32-rounded fp32 into S_Pt.
// Also emits the outp output (dbase==0 CTAs) while staging B — replaces k_permute.
#define PP_SMEM 55296
__global__ __launch_bounds__(256) void k_prepP(float* __restrict__ out_outp) {
    extern __shared__ __nv_bfloat16 smP[];
    __nv_bfloat16* Ahs = smP;
    __nv_bfloat16* Als = smP + 128*72;
    __nv_bfloat16* Bhs = smP + 2*128*72;
    __nv_bfloat16* Bls = Bhs + 64*72;

    int tid = threadIdx.x;
    int wid = tid >> 5, lane = tid & 31;
    int warp_m = wid & 1, warp_n = wid >> 1;
    int lr = lane >> 2;
    int lk = (lane & 3) * 2;
    int bh = blockIdx.x;
    int b = bh >> 3, h = bh & 7;
    int dbase = blockIdx.y * 128;

    {
        int r = tid >> 1, half = tid & 1;
        #pragma unroll
        for (int q0 = 0; q0 < 4; ++q0) {
            int q = half*4 + q0;
            size_t src = (size_t)(dbase + r)*512 + h*64 + q*8;
            cp16(&Ahs[r*72 + q*8], &S_Whi[src]);
            cp16(&Als[r*72 + q*8], &S_Wlo[src]);
        }
    }
    #pragma unroll
    for (int p = 0; p < 16; ++p) {
        int idx = tid + p*256;
        int g = idx >> 6, c = idx & 63;
        float v = S_out[(size_t)(b*64 + g)*512 + h*64 + c];
        if (dbase == 0) out_outp[(((b*8 + h)*64 + g)*64) + c] = v;
        __nv_bfloat16 vh, vl;
        bsplit(v, vh, vl);
        Bhs[g*72 + c] = vh;
        Bls[g*72 + c] = vl;
    }
    CP_COMMIT();
    CP_WAIT0();
    __syncthreads();

    float acc[4][2][4];
    #pragma unroll
    for (int mt = 0; mt < 4; ++mt)
        #pragma unroll
        for (int nt = 0; nt < 2; ++nt)
            #pragma unroll
            for (int q = 0; q < 4; ++q) acc[mt][nt][q] = 0.f;

    #pragma unroll
    for (int ks = 0; ks < 4; ++ks) {
        int k0 = ks*16;
        uint32_t ah[4][4], al[4][4], bhf[2][2], blf[2][2];
        #pragma unroll
        for (int mt = 0; mt < 4; ++mt) {
            int rb = warp_m*64 + mt*16 + lr;
            const __nv_bfloat16* pa = &Ahs[rb*72 + k0 + lk];
            ah[mt][0] = *(const uint32_t*)pa;
            ah[mt][1] = *(const uint32_t*)(pa + 8*72);
            ah[mt][2] = *(const uint32_t*)(pa + 8);
            ah[mt][3] = *(const uint32_t*)(pa + 8*72 + 8);
            const __nv_bfloat16* pl = &Als[rb*72 + k0 + lk];
            al[mt][0] = *(const uint32_t*)pl;
            al[mt][1] = *(const uint32_t*)(pl + 8*72);
            al[mt][2] = *(const uint32_t*)(pl + 8);
            al[mt][3] = *(const uint32_t*)(pl + 8*72 + 8);
        }
        #pragma unroll
        for (int nt = 0; nt < 2; ++nt) {
            int nb = warp_n*16 + nt*8 + lr;
            const __nv_bfloat16* pb = &Bhs[nb*72 + k0 + lk];
            bhf[nt][0] = *(const uint32_t*)pb;
            bhf[nt][1] = *(const uint32_t*)(pb + 8);
            const __nv_bfloat16* pl = &Bls[nb*72 + k0 + lk];
            blf[nt][0] = *(const uint32_t*)pl;
            blf[nt][1] = *(const uint32_t*)(pl + 8);
        }
        #pragma unroll
        for (int mt = 0; mt < 4; ++mt)
            #pragma unroll
            for (int nt = 0; nt < 2; ++nt) {
                mma16816(acc[mt][nt], ah[mt], bhf[nt]);
                mma16816(acc[mt][nt], ah[mt], blf[nt]);
                mma16816(acc[mt][nt], al[mt], bhf[nt]);
            }
    }

    #pragma unroll
    for (int mt = 0; mt < 4; ++mt) {
        int m = warp_m*64 + mt*16 + lr;
        #pragma unroll
        for (int nt = 0; nt < 2; ++nt) {
            int coln = warp_n*16 + nt*8 + lk;
            size_t base = ((size_t)b*512 + dbase + m)*512 + h*64 + coln;
            float2 v0;
            v0.x = to_tf32(acc[mt][nt][0]);
            v0.y = to_tf32(acc[mt][nt][1]);
            *(float2*)&S_Pt[base] = v0;
            float2 v1;
            v1.x = to_tf32(acc[mt][nt][2]);
            v1.y = to_tf32(acc[mt][nt][3]);
            *(float2*)&S_Pt[base + 8*512] = v1;
        }
    }
}

// ---------------------------------------------------------------------------
// Big GEMM (tf32, 3-stage all-cp.async pipeline):
// out[b, n, dbase+col] = sum_hg sw[b,h,n,g]*Pt[b][d][hg] + bias
// Grid (100 = mtile*4+dchunk, 16 b), 256 threads. BK=32, prefetch distance 2.
// A staged as raw fp32 (cvt.rna.tf32 at fragment load); B pre-rounded in S_Pt.
// smem: 3 stages x (A[128][36] + B[128][36]) fp32 = 110592 B; 2 CTAs/SM.
#define BM_BUF  (2*128*36)
#define BM_SMEM (3*BM_BUF*4)
__global__ __launch_bounds__(256, 2) void k_bigmma(
    const float* __restrict__ sw, const float* __restrict__ bias,
    float* __restrict__ out)
{
    extern __shared__ float smB[];
    int tid = threadIdx.x;
    int wid = tid >> 5, lane = tid & 31;
    int warp_m = wid & 1, warp_n = wid >> 1;
    int lr = lane >> 2;
    int lq = lane & 3;
    int dc = blockIdx.x & 3;
    int mt0 = blockIdx.x >> 2;
    int n0 = mt0 * 128;
    int b  = blockIdx.y;
    int dbase = dc * 128;

    int arow = tid >> 1;         // 0..127
    int ahalf = tid & 1;
    bool avalid = (n0 + arow) < NCTX;

    auto stageA = [&](int kc, int buf) {
        float* As = smB + buf*BM_BUF;
        int h = kc >> 1;
        int g0 = (kc & 1)*32 + ahalf*16;
        const float* src = sw + ((size_t)(b*8 + h)*NCTX + (avalid ? n0 + arow : 0))*64 + g0;
        float* dst = &As[arow*36 + ahalf*16];
        cp16p(dst,      src,      avalid);
        cp16p(dst + 4,  src + 4,  avalid);
        cp16p(dst + 8,  src + 8,  avalid);
        cp16p(dst + 12, src + 12, avalid);
    };
    auto stageB = [&](int kc, int buf) {
        float* Bs = smB + buf*BM_BUF + 128*36;
        #pragma unroll
        for (int p = 0; p < 4; ++p) {
            int idx = tid + p*256;
            int row = idx >> 3, q = idx & 7;
            size_t src = ((size_t)b*512 + dbase + row)*512 + kc*32 + q*4;
            cp16(&Bs[row*36 + q*4], &S_Pt[src]);
        }
    };

    float acc[4][4][4];
    #pragma unroll
    for (int mt = 0; mt < 4; ++mt)
        #pragma unroll
        for (int nt = 0; nt < 4; ++nt)
            #pragma unroll
            for (int q = 0; q < 4; ++q) acc[mt][nt][q] = 0.f;

    stageA(0, 0); stageB(0, 0); CP_COMMIT();
    stageA(1, 1); stageB(1, 1); CP_COMMIT();

    for (int kc = 0; kc < 16; ++kc) {
        if (kc < 15) { CP_WAIT1(); }
        else         { CP_WAIT0(); }
        __syncthreads();
        if (kc + 2 < 16) {
            int nb = (kc + 2) % 3;
            stageA(kc + 2, nb);
            stageB(kc + 2, nb);
            CP_COMMIT();
        }

        float* As = smB + (kc % 3)*BM_BUF;
        float* Bs = As + 128*36;

        #pragma unroll
        for (int ks = 0; ks < 4; ++ks) {
            int k0 = ks*8;
            uint32_t af[4][4], bf[4][2];
            #pragma unroll
            for (int mt = 0; mt < 4; ++mt) {
                int rb = warp_m*64 + mt*16 + lr;
                const float* pa = &As[rb*36 + k0 + lq];
                af[mt][0] = to_tf32b(pa[0]);
                af[mt][1] = to_tf32b(pa[8*36]);
                af[mt][2] = to_tf32b(pa[4]);
                af[mt][3] = to_tf32b(pa[8*36 + 4]);
            }
            #pragma unroll
            for (int nt = 0; nt < 4; ++nt) {
                int nb = warp_n*32 + nt*8 + lr;
                const float* pb = &Bs[nb*36 + k0 + lq];
                bf[nt][0] = __float_as_uint(pb[0]);
                bf[nt][1] = __float_as_uint(pb[4]);
            }
            #pragma unroll
            for (int mt = 0; mt < 4; ++mt)
                #pragma unroll
                for (int nt = 0; nt < 4; ++nt)
                    mma_tf32(acc[mt][nt], af[mt], bf[nt]);
        }
    }

    // epilogue
    #pragma unroll
    for (int mt = 0; mt < 4; ++mt) {
        int m = warp_m*64 + mt*16 + lr;
        #pragma unroll
        for (int nt = 0; nt < 4; ++nt) {
            int col = dbase + warp_n*32 + nt*8 + lq*2;
            float b0 = __ldg(&bias[col]);
            float b1 = __ldg(&bias[col + 1]);
            if (n0 + m < NCTX) {
                size_t r = (size_t)b*NCTX + n0 + m;
                float2 v;
                v.x = acc[mt][nt][0] + b0;
                v.y = acc[mt][nt][1] + b1;
                *(float2*)&out[r*512 + col] = v;
            }
            if (n0 + m + 8 < NCTX) {
                size_t r = (size_t)b*NCTX + n0 + m + 8;
                float2 v;
                v.x = acc[mt][nt][2] + b0;
                v.y = acc[mt][nt][3] + b1;
                *(float2*)&out[r*512 + col] = v;
            }
        }
    }
}

// ---------------------------------------------------------------------------
extern "C" void kernel_launch(void* const* d_in, const int* in_sizes, int n_in,
                              void* d_out, int out_size) {
    const float* st     = (const float*)d_in[0];
    const float* sw     = (const float*)d_in[1];
    const float* w_in   = (const float*)d_in[2];
    const float* conv_w = (const float*)d_in[3];
    const float* conv_b = (const float*)d_in[4];
    const float* dt_bias= (const float*)d_in[5];
    const float* A_log  = (const float*)d_in[6];
    const float* Dv     = (const float*)d_in[7];
    const float* fc_D_w = (const float*)d_in[8];
    const float* norm_w = (const float*)d_in[9];
    const float* w_out  = (const float*)d_in[10];
    const float* to_w   = (const float*)d_in[11];
    const float* to_b   = (const float*)d_in[12];

    float* out       = (float*)d_out;
    float* out_final = out;
    float* out_inp   = out + (size_t)B16*NCTX*DM512;
    float* out_outp  = out_inp + (size_t)B16*8*64*64;

    float *pSzx, *pSout;
    __nv_bfloat16 *pUh, *pUl, *pYh, *pYl, *pW1h, *pW1l, *pW2h, *pW2l;
    cudaGetSymbolAddress((void**)&pSzx, S_zx);
    cudaGetSymbolAddress((void**)&pSout, S_out);
    cudaGetSymbolAddress((void**)&pUh, S_uhi);
    cudaGetSymbolAddress((void**)&pUl, S_ulo);
    cudaGetSymbolAddress((void**)&pYh, S_ynhi);
    cudaGetSymbolAddress((void**)&pYl, S_ynlo);
    cudaGetSymbolAddress((void**)&pW1h, S_W1hi);
    cudaGetSymbolAddress((void**)&pW1l, S_W1lo);
    cudaGetSymbolAddress((void**)&pW2h, S_W2hi);
    cudaGetSymbolAddress((void**)&pW2l, S_W2lo);

    k_split3<<<(DINPROJ*DM512 + 511)/512, 512>>>(w_in, w_out, to_w);

    k_transpose_u<<<B16*L64, 512>>>(st, out_inp);

    cudaFuncSetAttribute(k_gemm_sp, cudaFuncAttributeMaxDynamicSharedMemorySize, GS_SMEM);
    k_gemm_sp<<<dim3(8, 9), 256, GS_SMEM>>>(pUh, pUl, pW1h, pW1l, pSzx, DINPROJ);

    cudaFuncSetAttribute(k_scanc, cudaFuncAttributeMaxDynamicSharedMemorySize, SC_SMEM);
    k_scanc<<<32, 512, SC_SMEM>>>(conv_w, conv_b, dt_bias, A_log);

    k_combine<<<B16*L64, 512>>>(fc_D_w, Dv, norm_w);

    k_gemm_sp<<<dim3(8, 4), 256, GS_SMEM>>>(pYh, pYl, pW2h, pW2l, pSout, DM512);

    cudaFuncSetAttribute(k_prepP, cudaFuncAttributeMaxDynamicSharedMemorySize, PP_SMEM);
    k_prepP<<<dim3(128, 4), 256, PP_SMEM>>>(out_outp);

    cudaFuncSetAttribute(k_bigmma, cudaFuncAttributeMaxDynamicSharedMemorySize, BM_SMEM);
    k_bigmma<<<dim3(4*((NCTX + 127)/128), B16), 256, BM_SMEM>>>(sw, to_b, out_final);
}

// round 12
// speedup vs baseline: 5.4093x; 1.0720x over previous
#include <cuda_runtime.h>
#include <cuda_bf16.h>
#include <math.h>
#include <stdint.h>

// Problem constants
#define B16    16
#define L64    64
#define DM512  512
#define NCTX   3131
#define DINPROJ 1042
#define CONVDIM 514
#define MROWS  50096            // 16*3131

// Scratch (static device arrays; zero-initialized, allocation-free)
__device__ float S_zx [B16*L64*DINPROJ];
__device__ float S_x  [B16*L64*DM512];
__device__ float S_ys [2*B16*L64*DM512];
__device__ float S_out[B16*L64*DM512];
// split-bf16 operands (pre-pipeline)
__device__ __nv_bfloat16 S_uhi [B16*L64*DM512];
__device__ __nv_bfloat16 S_ulo [B16*L64*DM512];
__device__ __nv_bfloat16 S_ynhi[B16*L64*DM512];
__device__ __nv_bfloat16 S_ynlo[B16*L64*DM512];
__device__ __nv_bfloat16 S_W1hi[1152*DM512];
__device__ __nv_bfloat16 S_W1lo[1152*DM512];
__device__ __nv_bfloat16 S_W2hi[DM512*DM512];
__device__ __nv_bfloat16 S_W2lo[DM512*DM512];
__device__ __nv_bfloat16 S_Whi [DM512*DM512];
__device__ __nv_bfloat16 S_Wlo [DM512*DM512];
// Pt fp32 (tf32-pre-rounded): Pt[b][d][hg], natural layout
__device__ float S_Pt[(size_t)B16*DM512*DM512];

// ---- helpers ---------------------------------------------------------------
__device__ __forceinline__ void mma16816(float* c, const uint32_t* a, const uint32_t* b) {
    asm volatile(
        "mma.sync.aligned.m16n8k16.row.col.f32.bf16.bf16.f32 "
        "{%0,%1,%2,%3}, {%4,%5,%6,%7}, {%8,%9}, {%0,%1,%2,%3};"
        : "+f"(c[0]), "+f"(c[1]), "+f"(c[2]), "+f"(c[3])
        : "r"(a[0]), "r"(a[1]), "r"(a[2]), "r"(a[3]), "r"(b[0]), "r"(b[1]));
}
__device__ __forceinline__ void mma_tf32(float* c, const uint32_t* a, const uint32_t* b) {
    asm volatile(
        "mma.sync.aligned.m16n8k8.row.col.f32.tf32.tf32.f32 "
        "{%0,%1,%2,%3}, {%4,%5,%6,%7}, {%8,%9}, {%0,%1,%2,%3};"
        : "+f"(c[0]), "+f"(c[1]), "+f"(c[2]), "+f"(c[3])
        : "r"(a[0]), "r"(a[1]), "r"(a[2]), "r"(a[3]), "r"(b[0]), "r"(b[1]));
}
__device__ __forceinline__ float to_tf32(float x) {
    uint32_t r;
    asm("cvt.rna.tf32.f32 %0, %1;" : "=r"(r) : "f"(x));
    return __uint_as_float(r);
}
__device__ __forceinline__ void bsplit(float v, __nv_bfloat16& h, __nv_bfloat16& l) {
    h = __float2bfloat16(v);
    l = __float2bfloat16(v - __bfloat162float(h));
}
__device__ __forceinline__ void cp16(void* dst, const void* src) {
    uint32_t d = (uint32_t)__cvta_generic_to_shared(dst);
    asm volatile("cp.async.cg.shared.global [%0], [%1], 16;" :: "r"(d), "l"(src));
}
// predicated 16B cp.async: src_size=0 zero-fills dst (OOB rows)
__device__ __forceinline__ void cp16p(void* dst, const void* src, bool pred) {
    uint32_t d = (uint32_t)__cvta_generic_to_shared(dst);
    int sz = pred ? 16 : 0;
    asm volatile("cp.async.cg.shared.global [%0], [%1], 16, %2;" :: "r"(d), "l"(src), "r"(sz));
}
__device__ __forceinline__ void cp8(void* dst, const void* src) {
    uint32_t d = (uint32_t)__cvta_generic_to_shared(dst);
    asm volatile("cp.async.ca.shared.global [%0], [%1], 8;" :: "r"(d), "l"(src));
}
#define CP_COMMIT() asm volatile("cp.async.commit_group;" ::: "memory")
#define CP_WAIT1()  asm volatile("cp.async.wait_group 1;" ::: "memory")
#define CP_WAIT0()  asm volatile("cp.async.wait_group 0;" ::: "memory")

// ---------------------------------------------------------------------------
// One launch splits all 3 weight matrices into bf16 hi/lo.
__global__ void k_split3(const float* __restrict__ w_in,
                         const float* __restrict__ w_out,
                         const float* __restrict__ to_w) {
    int i = blockIdx.x * blockDim.x + threadIdx.x;
    if (i < DINPROJ*DM512) {
        __nv_bfloat16 h, l;
        bsplit(w_in[i], h, l);
        S_W1hi[i] = h; S_W1lo[i] = l;
    }
    if (i < DM512*DM512) {
        __nv_bfloat16 h, l;
        bsplit(w_out[i], h, l);
        S_W2hi[i] = h; S_W2lo[i] = l;
        bsplit(to_w[i], h, l);
        S_Whi[i] = h; S_Wlo[i] = l;
    }
}

// ---------------------------------------------------------------------------
// u transpose + split, and inp passthrough (same layout as st)
__global__ void k_transpose_u(const float* __restrict__ st, float* __restrict__ out_inp) {
    int row = blockIdx.x;
    int b = row >> 6, g = row & 63;
    int tid = threadIdx.x;
    int h = tid >> 6, c = tid & 63;
    size_t si = (((size_t)(b*8 + h)*64) + g)*64 + c;
    float v = st[si];
    out_inp[si] = v;
    __nv_bfloat16 vh, vl;
    bsplit(v, vh, vl);
    S_uhi[row*DM512 + tid] = vh;
    S_ulo[row*DM512 + tid] = vl;
}

// ---------------------------------------------------------------------------
// Presplit GEMM: C[m,n] = sum_k A[m,k]*B[n,k], split bf16, M=1024, K=512
#define GS_SMEM 81920
__global__ __launch_bounds__(256) void k_gemm_sp(
    const __nv_bfloat16* __restrict__ Ahi, const __nv_bfloat16* __restrict__ Alo,
    const __nv_bfloat16* __restrict__ Bhi, const __nv_bfloat16* __restrict__ Blo,
    float* __restrict__ C, int N)
{
    extern __shared__ __nv_bfloat16 smG[];
    int tid = threadIdx.x;
    int wid = tid >> 5, lane = tid & 31;
    int warp_m = wid & 1, warp_n = wid >> 1;
    int lr = lane >> 2;
    int lk = (lane & 3) * 2;
    size_t rbase = (size_t)blockIdx.x * 128;
    int n0 = blockIdx.y * 128;

    const int BUF = 4*128*40;
    int m_st = tid >> 2;
    int kp_st = tid & 3;

    auto stage = [&](int kc, int buf) {
        __nv_bfloat16* Ah = smG + buf*BUF;
        __nv_bfloat16* Al = Ah + 128*40;
        __nv_bfloat16* Wh = Al + 128*40;
        __nv_bfloat16* Wl = Wh + 128*40;
        int kofs = kc*32 + kp_st*8;
        #pragma unroll
        for (int p = 0; p < 2; ++p) {
            int m = m_st + p*64;
            size_t ga = (rbase + m)*512 + kofs;
            cp16(&Ah[m*40 + kp_st*8], &Ahi[ga]);
            cp16(&Al[m*40 + kp_st*8], &Alo[ga]);
            size_t gw = (size_t)(n0 + m)*512 + kofs;
            cp16(&Wh[m*40 + kp_st*8], &Bhi[gw]);
            cp16(&Wl[m*40 + kp_st*8], &Blo[gw]);
        }
    };

    float acc[4][4][4];
    #pragma unroll
    for (int mt = 0; mt < 4; ++mt)
        #pragma unroll
        for (int nt = 0; nt < 4; ++nt)
            #pragma unroll
            for (int q = 0; q < 4; ++q) acc[mt][nt][q] = 0.f;

    stage(0, 0);
    CP_COMMIT();

    for (int kc = 0; kc < 16; ++kc) {
        int cur = kc & 1;
        if (kc < 15) { stage(kc + 1, cur ^ 1); CP_COMMIT(); CP_WAIT1(); }
        else         { CP_WAIT0(); }
        __syncthreads();

        __nv_bfloat16* Ah = smG + cur*BUF;
        __nv_bfloat16* Al = Ah + 128*40;
        __nv_bfloat16* Wh = Al + 128*40;
        __nv_bfloat16* Wl = Wh + 128*40;

        #pragma unroll
        for (int ks = 0; ks < 2; ++ks) {
            int k0 = ks*16;
            uint32_t ah[4][4], al[4][4], bh[4][2], bl[4][2];
            #pragma unroll
            for (int mt = 0; mt < 4; ++mt) {
                int rb = warp_m*64 + mt*16 + lr;
                const __nv_bfloat16* pa = &Ah[rb*40 + k0 + lk];
                ah[mt][0] = *(const uint32_t*)pa;
                ah[mt][1] = *(const uint32_t*)(pa + 8*40);
                ah[mt][2] = *(const uint32_t*)(pa + 8);
                ah[mt][3] = *(const uint32_t*)(pa + 8*40 + 8);
                const __nv_bfloat16* pl = &Al[rb*40 + k0 + lk];
                al[mt][0] = *(const uint32_t*)pl;
                al[mt][1] = *(const uint32_t*)(pl + 8*40);
                al[mt][2] = *(const uint32_t*)(pl + 8);
                al[mt][3] = *(const uint32_t*)(pl + 8*40 + 8);
            }
            #pragma unroll
            for (int nt = 0; nt < 4; ++nt) {
                int nb = warp_n*32 + nt*8 + lr;
                const __nv_bfloat16* pb = &Wh[nb*40 + k0 + lk];
                bh[nt][0] = *(const uint32_t*)pb;
                bh[nt][1] = *(const uint32_t*)(pb + 8);
                const __nv_bfloat16* pl = &Wl[nb*40 + k0 + lk];
                bl[nt][0] = *(const uint32_t*)pl;
                bl[nt][1] = *(const uint32_t*)(pl + 8);
            }
            #pragma unroll
            for (int mt = 0; mt < 4; ++mt)
                #pragma unroll
                for (int nt = 0; nt < 4; ++nt) {
                    mma16816(acc[mt][nt], ah[mt], bh[nt]);
                    mma16816(acc[mt][nt], ah[mt], bl[nt]);
                    mma16816(acc[mt][nt], al[mt], bh[nt]);
                }
        }
        __syncthreads();
    }

    #pragma unroll
    for (int mt = 0; mt < 4; ++mt) {
        int m = warp_m*64 + mt*16 + lr;
        #pragma unroll
        for (int nt = 0; nt < 4; ++nt) {
            int col = n0 + warp_n*32 + nt*8 + lk;
            if (col < N) {
                size_t r = rbase + m;
                float2 v0;
                v0.x = acc[mt][nt][0];
                v0.y = acc[mt][nt][1];
                *(float2*)&C[r*N + col] = v0;
                float2 v1;
                v1.x = acc[mt][nt][2];
                v1.y = acc[mt][nt][3];
                *(float2*)&C[(r + 8)*N + col] = v1;
            }
        }
    }
}

// ---------------------------------------------------------------------------
// Fused conv + scan, channel-split. Grid 128 = (i ext-batch)*4 + q (quarter),
// 128 threads. Each CTA stages its 128 x-cols slice + B/C cols, computes
// conv+SiLU inline, then the sequential scan for its channels.
// fw CTAs (i<16) also store S_x for k_combine.
#define ZS2_LD 132
#define SC_SMEM (64*ZS2_LD*4 + 512*4 + 128*4)
__global__ __launch_bounds__(128) void k_scanc(
    const float* __restrict__ conv_w, const float* __restrict__ conv_b,
    const float* __restrict__ dt_bias, const float* __restrict__ A_log)
{
    extern __shared__ float smS[];
    float* zs  = smS;               // [64][132]: 128 x-cols + B(128) + C(129)
    float* dts = smS + 64*ZS2_LD;   // [64][8]
    float* Bs  = dts + 512;         // [64]
    float* Cs  = Bs + 64;           // [64]

    int cta = blockIdx.x;
    int i = cta >> 2;               // extended batch 0..31
    int q = cta & 3;                // channel quarter
    int d = threadIdx.x;            // 0..127
    bool bw = (i >= 16);
    int b = bw ? i - 16 : i;
    int cbase = q*128;

    // stage: 64 rows x (64 x-pairs + 1 BC-pair) = 4160 cp8
    for (int p = 0; p < 33; ++p) {
        int idx = d + p*128;
        if (idx < 64*65) {
            int row = idx / 65, pr = idx - row*65;
            int gcol = (pr < 64) ? (512 + cbase + pr*2) : 1024;
            int scol = (pr < 64) ? (pr*2) : 128;
            cp8(&zs[row*ZS2_LD + scol],
                &S_zx[(size_t)(b*64 + row)*DINPROJ + gcol]);
        }
    }
    #pragma unroll
    for (int p = 0; p < 4; ++p) {
        int idx = d + p*128;
        int row = idx >> 3, hh = idx & 7;
        dts[idx] = S_zx[(b*64 + row)*DINPROJ + 1026 + (bw ? 8 : 0) + hh];
    }
    CP_COMMIT();
    CP_WAIT0();
    __syncthreads();

    // B / C channels: conv + silu (parallel over t)
    if (d < 64) {
        int t = d;
        float acc = conv_b[512];
        #pragma unroll
        for (int k = 0; k < 3; ++k) {
            int tt = t + k - 2;
            if (tt >= 0) acc += conv_w[512*3 + k] * zs[tt*ZS2_LD + 128];
        }
        Bs[t] = acc / (1.f + expf(-acc));
    } else {
        int t = d - 64;
        float acc = conv_b[513];
        #pragma unroll
        for (int k = 0; k < 3; ++k) {
            int tt = t + k - 2;
            if (tt >= 0) acc += conv_w[513*3 + k] * zs[tt*ZS2_LD + 129];
        }
        Cs[t] = acc / (1.f + expf(-acc));
    }
    __syncthreads();

    int dch = cbase + d;            // global x channel
    int h = dch >> 6;
    float Ah   = -expf(A_log[h]);
    float bias = dt_bias[h];
    float cb = conv_b[dch];
    float w0 = conv_w[dch*3], w1 = conv_w[dch*3 + 1], w2 = conv_w[dch*3 + 2];
    float hs = 0.f;
    S_ys[(size_t)(i*64)*512 + dch] = 0.f;
    #pragma unroll 4
    for (int t = 0; t < 64; ++t) {
        int tt = bw ? (63 - t) : t;
        float z0  = zs[tt*ZS2_LD + d];
        float zm1 = (tt >= 1) ? zs[(tt - 1)*ZS2_LD + d] : 0.f;
        float zm2 = (tt >= 2) ? zs[(tt - 2)*ZS2_LD + d] : 0.f;
        float cv = cb + w0*zm2 + w1*zm1 + w2*z0;
        float x  = cv / (1.f + expf(-cv));
        if (!bw) S_x[(size_t)(b*64 + tt)*512 + dch] = x;
        float v  = dts[tt*8 + h] + bias;
        float dt = (v > 20.f) ? v : log1pf(expf(v));
        float a  = expf(dt * Ah);
        hs = a*hs + dt*Bs[tt]*x;
        if (t < 63) S_ys[(size_t)(i*64 + t + 1)*512 + dch] = hs * Cs[tt];
    }
}

// ---------------------------------------------------------------------------
__global__ __launch_bounds__(512) void k_combine(
    const float* __restrict__ fc_D_w, const float* __restrict__ Dv,
    const float* __restrict__ norm_w)
{
    int row = blockIdx.x;
    int b = row >> 6, t = row & 63;
    int d = threadIdx.x;
    int h = d >> 6;
    int lane = d & 31, wid = d >> 5;

    float x  = S_x[row*512 + d];
    float z  = S_zx[row*DINPROJ + d];
    float yf = S_ys[row*512 + d];
    float yb = S_ys[((16 + b)*64 + (63 - t))*512 + d];

    float px[8];
    #pragma unroll
    for (int hh = 0; hh < 8; ++hh) px[hh] = x * fc_D_w[hh*512 + d];
    #pragma unroll
    for (int off = 16; off; off >>= 1)
        #pragma unroll
        for (int hh = 0; hh < 8; ++hh) px[hh] += __shfl_xor_sync(0xffffffffu, px[hh], off);

    __shared__ float wsum[16][8];
    __shared__ float dcf[8];
    if (lane == 0) {
        #pragma unroll
        for (int hh = 0; hh < 8; ++hh) wsum[wid][hh] = px[hh];
    }
    __syncthreads();
    if (d < 8) {
        float s = 0.f;
        #pragma unroll
        for (int w = 0; w < 16; ++w) s += wsum[w][d];
        dcf[d] = s + Dv[d];
    }
    __syncthreads();

    float y = yf + yb + x * dcf[h];
    y *= z / (1.f + expf(-z));

    float sq = y*y;
    #pragma unroll
    for (int off = 16; off; off >>= 1) sq += __shfl_xor_sync(0xffffffffu, sq, off);
    __shared__ float rsum[16];
    __shared__ float rscale;
    if (lane == 0) rsum[wid] = sq;
    __syncthreads();
    if (d == 0) {
        float s = 0.f;
        #pragma unroll
        for (int w = 0; w < 16; ++w) s += rsum[w];
        rscale = rsqrtf(s / 512.f + 1e-5f);
    }
    __syncthreads();
    float yn = y * rscale * norm_w[d];
    __nv_bfloat16 vh, vl;
    bsplit(yn, vh, vl);
    S_ynhi[row*512 + d] = vh;
    S_ynlo[row*512 + d] = vl;
}

// ---------------------------------------------------------------------------
// prepP: Pt[b][d][h*64+g] = sum_c to_w[d, h*64+c] * S_out[(b*64+g)*512 + h*64+c]
// Split-bf16 mma; epilogue writes tf32-rounded fp32 into S_Pt.
// Also emits the outp output (dbase==0 CTAs) while staging B — replaces k_permute.
#define PP_SMEM 55296
__global__ __launch_bounds__(256) void k_prepP(float* __restrict__ out_outp) {
    extern __shared__ __nv_bfloat16 smP[];
    __nv_bfloat16* Ahs = smP;
    __nv_bfloat16* Als = smP + 128*72;
    __nv_bfloat16* Bhs = smP + 2*128*72;
    __nv_bfloat16* Bls = Bhs + 64*72;

    int tid = threadIdx.x;
    int wid = tid >> 5, lane = tid & 31;
    int warp_m = wid & 1, warp_n = wid >> 1;
    int lr = lane >> 2;
    int lk = (lane & 3) * 2;
    int bh = blockIdx.x;
    int b = bh >> 3, h = bh & 7;
    int dbase = blockIdx.y * 128;

    {
        int r = tid >> 1, half = tid & 1;
        #pragma unroll
        for (int q0 = 0; q0 < 4; ++q0) {
            int q = half*4 + q0;
            size_t src = (size_t)(dbase + r)*512 + h*64 + q*8;
            cp16(&Ahs[r*72 + q*8], &S_Whi[src]);
            cp16(&Als[r*72 + q*8], &S_Wlo[src]);
        }
    }
    #pragma unroll
    for (int p = 0; p < 16; ++p) {
        int idx = tid + p*256;
        int g = idx >> 6, c = idx & 63;
        float v = S_out[(size_t)(b*64 + g)*512 + h*64 + c];
        if (dbase == 0) out_outp[(((b*8 + h)*64 + g)*64) + c] = v;
        __nv_bfloat16 vh, vl;
        bsplit(v, vh, vl);
        Bhs[g*72 + c] = vh;
        Bls[g*72 + c] = vl;
    }
    CP_COMMIT();
    CP_WAIT0();
    __syncthreads();

    float acc[4][2][4];
    #pragma unroll
    for (int mt = 0; mt < 4; ++mt)
        #pragma unroll
        for (int nt = 0; nt < 2; ++nt)
            #pragma unroll
            for (int q = 0; q < 4; ++q) acc[mt][nt][q] = 0.f;

    #pragma unroll
    for (int ks = 0; ks < 4; ++ks) {
        int k0 = ks*16;
        uint32_t ah[4][4], al[4][4], bhf[2][2], blf[2][2];
        #pragma unroll
        for (int mt = 0; mt < 4; ++mt) {
            int rb = warp_m*64 + mt*16 + lr;
            const __nv_bfloat16* pa = &Ahs[rb*72 + k0 + lk];
            ah[mt][0] = *(const uint32_t*)pa;
            ah[mt][1] = *(const uint32_t*)(pa + 8*72);
            ah[mt][2] = *(const uint32_t*)(pa + 8);
            ah[mt][3] = *(const uint32_t*)(pa + 8*72 + 8);
            const __nv_bfloat16* pl = &Als[rb*72 + k0 + lk];
            al[mt][0] = *(const uint32_t*)pl;
            al[mt][1] = *(const uint32_t*)(pl + 8*72);
            al[mt][2] = *(const uint32_t*)(pl + 8);
            al[mt][3] = *(const uint32_t*)(pl + 8*72 + 8);
        }
        #pragma unroll
        for (int nt = 0; nt < 2; ++nt) {
            int nb = warp_n*16 + nt*8 + lr;
            const __nv_bfloat16* pb = &Bhs[nb*72 + k0 + lk];
            bhf[nt][0] = *(const uint32_t*)pb;
            bhf[nt][1] = *(const uint32_t*)(pb + 8);
            const __nv_bfloat16* pl = &Bls[nb*72 + k0 + lk];
            blf[nt][0] = *(const uint32_t*)pl;
            blf[nt][1] = *(const uint32_t*)(pl + 8);
        }
        #pragma unroll
        for (int mt = 0; mt < 4; ++mt)
            #pragma unroll
            for (int nt = 0; nt < 2; ++nt) {
                mma16816(acc[mt][nt], ah[mt], bhf[nt]);
                mma16816(acc[mt][nt], ah[mt], blf[nt]);
                mma16816(acc[mt][nt], al[mt], bhf[nt]);
            }
    }

    #pragma unroll
    for (int mt = 0; mt < 4; ++mt) {
        int m = warp_m*64 + mt*16 + lr;
        #pragma unroll
        for (int nt = 0; nt < 2; ++nt) {
            int coln = warp_n*16 + nt*8 + lk;
            size_t base = ((size_t)b*512 + dbase + m)*512 + h*64 + coln;
            float2 v0;
            v0.x = to_tf32(acc[mt][nt][0]);
            v0.y = to_tf32(acc[mt][nt][1]);
            *(float2*)&S_Pt[base] = v0;
            float2 v1;
            v1.x = to_tf32(acc[mt][nt][2]);
            v1.y = to_tf32(acc[mt][nt][3]);
            *(float2*)&S_Pt[base + 8*512] = v1;
        }
    }
}

// ---------------------------------------------------------------------------
// Big GEMM (tf32, 3-stage all-cp.async pipeline, raw-bit A operands):
// out[b, n, dbase+col] = sum_hg sw[b,h,n,g]*Pt[b][d][hg] + bias
// Grid (100 = mtile*4+dchunk, 16 b), 256 threads. BK=32, prefetch distance 2.
// A fed as raw fp32 bits (HW truncates to tf32); B pre-rounded RNA in S_Pt.
// smem: 3 stages x (A[128][36] + B[128][36]) fp32 = 110592 B; 2 CTAs/SM.
#define BM_BUF  (2*128*36)
#define BM_SMEM (3*BM_BUF*4)
__global__ __launch_bounds__(256, 2) void k_bigmma(
    const float* __restrict__ sw, const float* __restrict__ bias,
    float* __restrict__ out)
{
    extern __shared__ float smB[];
    int tid = threadIdx.x;
    int wid = tid >> 5, lane = tid & 31;
    int warp_m = wid & 1, warp_n = wid >> 1;
    int lr = lane >> 2;
    int lq = lane & 3;
    int dc = blockIdx.x & 3;
    int mt0 = blockIdx.x >> 2;
    int n0 = mt0 * 128;
    int b  = blockIdx.y;
    int dbase = dc * 128;

    int arow = tid >> 1;         // 0..127
    int ahalf = tid & 1;
    bool avalid = (n0 + arow) < NCTX;

    auto stageA = [&](int kc, int buf) {
        float* As = smB + buf*BM_BUF;
        int h = kc >> 1;
        int g0 = (kc & 1)*32 + ahalf*16;
        const float* src = sw + ((size_t)(b*8 + h)*NCTX + (avalid ? n0 + arow : 0))*64 + g0;
        float* dst = &As[arow*36 + ahalf*16];
        cp16p(dst,      src,      avalid);
        cp16p(dst + 4,  src + 4,  avalid);
        cp16p(dst + 8,  src + 8,  avalid);
        cp16p(dst + 12, src + 12, avalid);
    };
    auto stageB = [&](int kc, int buf) {
        float* Bs = smB + buf*BM_BUF + 128*36;
        #pragma unroll
        for (int p = 0; p < 4; ++p) {
            int idx = tid + p*256;
            int row = idx >> 3, q = idx & 7;
            size_t src = ((size_t)b*512 + dbase + row)*512 + kc*32 + q*4;
            cp16(&Bs[row*36 + q*4], &S_Pt[src]);
        }
    };

    float acc[4][4][4];
    #pragma unroll
    for (int mt = 0; mt < 4; ++mt)
        #pragma unroll
        for (int nt = 0; nt < 4; ++nt)
            #pragma unroll
            for (int q = 0; q < 4; ++q) acc[mt][nt][q] = 0.f;

    stageA(0, 0); stageB(0, 0); CP_COMMIT();
    stageA(1, 1); stageB(1, 1); CP_COMMIT();

    for (int kc = 0; kc < 16; ++kc) {
        if (kc < 15) { CP_WAIT1(); }
        else         { CP_WAIT0(); }
        __syncthreads();
        if (kc + 2 < 16) {
            int nb = (kc + 2) % 3;
            stageA(kc + 2, nb);
            stageB(kc + 2, nb);
            CP_COMMIT();
        }

        float* As = smB + (kc % 3)*BM_BUF;
        float* Bs = As + 128*36;

        #pragma unroll
        for (int ks = 0; ks < 4; ++ks) {
            int k0 = ks*8;
            uint32_t af[4][4], bf[4][2];
            #pragma unroll
            for (int mt = 0; mt < 4; ++mt) {
                int rb = warp_m*64 + mt*16 + lr;
                const float* pa = &As[rb*36 + k0 + lq];
                af[mt][0] = __float_as_uint(pa[0]);
                af[mt][1] = __float_as_uint(pa[8*36]);
                af[mt][2] = __float_as_uint(pa[4]);
                af[mt][3] = __float_as_uint(pa[8*36 + 4]);
            }
            #pragma unroll
            for (int nt = 0; nt < 4; ++nt) {
                int nb = warp_n*32 + nt*8 + lr;
                const float* pb = &Bs[nb*36 + k0 + lq];
                bf[nt][0] = __float_as_uint(pb[0]);
                bf[nt][1] = __float_as_uint(pb[4]);
            }
            #pragma unroll
            for (int mt = 0; mt < 4; ++mt)
                #pragma unroll
                for (int nt = 0; nt < 4; ++nt)
                    mma_tf32(acc[mt][nt], af[mt], bf[nt]);
        }
    }

    // epilogue
    #pragma unroll
    for (int mt = 0; mt < 4; ++mt) {
        int m = warp_m*64 + mt*16 + lr;
        #pragma unroll
        for (int nt = 0; nt < 4; ++nt) {
            int col = dbase + warp_n*32 + nt*8 + lq*2;
            float b0 = __ldg(&bias[col]);
            float b1 = __ldg(&bias[col + 1]);
            if (n0 + m < NCTX) {
                size_t r = (size_t)b*NCTX + n0 + m;
                float2 v;
                v.x = acc[mt][nt][0] + b0;
                v.y = acc[mt][nt][1] + b1;
                *(float2*)&out[r*512 + col] = v;
            }
            if (n0 + m + 8 < NCTX) {
                size_t r = (size_t)b*NCTX + n0 + m + 8;
                float2 v;
                v.x = acc[mt][nt][2] + b0;
                v.y = acc[mt][nt][3] + b1;
                *(float2*)&out[r*512 + col] = v;
            }
        }
    }
}

// ---------------------------------------------------------------------------
extern "C" void kernel_launch(void* const* d_in, const int* in_sizes, int n_in,
                              void* d_out, int out_size) {
    const float* st     = (const float*)d_in[0];
    const float* sw     = (const float*)d_in[1];
    const float* w_in   = (const float*)d_in[2];
    const float* conv_w = (const float*)d_in[3];
    const float* conv_b = (const float*)d_in[4];
    const float* dt_bias= (const float*)d_in[5];
    const float* A_log  = (const float*)d_in[6];
    const float* Dv     = (const float*)d_in[7];
    const float* fc_D_w = (const float*)d_in[8];
    const float* norm_w = (const float*)d_in[9];
    const float* w_out  = (const float*)d_in[10];
    const float* to_w   = (const float*)d_in[11];
    const float* to_b   = (const float*)d_in[12];

    float* out       = (float*)d_out;
    float* out_final = out;
    float* out_inp   = out + (size_t)B16*NCTX*DM512;
    float* out_outp  = out_inp + (size_t)B16*8*64*64;

    float *pSzx, *pSout;
    __nv_bfloat16 *pUh, *pUl, *pYh, *pYl, *pW1h, *pW1l, *pW2h, *pW2l;
    cudaGetSymbolAddress((void**)&pSzx, S_zx);
    cudaGetSymbolAddress((void**)&pSout, S_out);
    cudaGetSymbolAddress((void**)&pUh, S_uhi);
    cudaGetSymbolAddress((void**)&pUl, S_ulo);
    cudaGetSymbolAddress((void**)&pYh, S_ynhi);
    cudaGetSymbolAddress((void**)&pYl, S_ynlo);
    cudaGetSymbolAddress((void**)&pW1h, S_W1hi);
    cudaGetSymbolAddress((void**)&pW1l, S_W1lo);
    cudaGetSymbolAddress((void**)&pW2h, S_W2hi);
    cudaGetSymbolAddress((void**)&pW2l, S_W2lo);

    k_split3<<<(DINPROJ*DM512 + 511)/512, 512>>>(w_in, w_out, to_w);

    k_transpose_u<<<B16*L64, 512>>>(st, out_inp);

    cudaFuncSetAttribute(k_gemm_sp, cudaFuncAttributeMaxDynamicSharedMemorySize, GS_SMEM);
    k_gemm_sp<<<dim3(8, 9), 256, GS_SMEM>>>(pUh, pUl, pW1h, pW1l, pSzx, DINPROJ);

    cudaFuncSetAttribute(k_scanc, cudaFuncAttributeMaxDynamicSharedMemorySize, SC_SMEM);
    k_scanc<<<128, 128, SC_SMEM>>>(conv_w, conv_b, dt_bias, A_log);

    k_combine<<<B16*L64, 512>>>(fc_D_w, Dv, norm_w);

    k_gemm_sp<<<dim3(8, 4), 256, GS_SMEM>>>(pYh, pYl, pW2h, pW2l, pSout, DM512);

    cudaFuncSetAttribute(k_prepP, cudaFuncAttributeMaxDynamicSharedMemorySize, PP_SMEM);
    k_prepP<<<dim3(128, 4), 256, PP_SMEM>>>(out_outp);

    cudaFuncSetAttribute(k_bigmma, cudaFuncAttributeMaxDynamicSharedMemorySize, BM_SMEM);
    k_bigmma<<<dim3(4*((NCTX + 127)/128), B16), 256, BM_SMEM>>>(sw, to_b, out_final);
}

// round 13
// speedup vs baseline: 5.9463x; 1.0993x over previous
#include <cuda_runtime.h>
#include <cuda_bf16.h>
#include <math.h>
#include <stdint.h>

// Problem constants
#define B16    16
#define L64    64
#define DM512  512
#define NCTX   3131
#define DINPROJ 1042
#define CONVDIM 514
#define MROWS  50096            // 16*3131

// Scratch (static device arrays; zero-initialized, allocation-free)
__device__ float S_zx [B16*L64*DINPROJ];
__device__ float S_x  [B16*L64*DM512];
__device__ float S_ys [2*B16*L64*DM512];
__device__ float S_out[B16*L64*DM512];
// split-bf16 operands (pre-pipeline)
__device__ __nv_bfloat16 S_uhi [B16*L64*DM512];
__device__ __nv_bfloat16 S_ulo [B16*L64*DM512];
__device__ __nv_bfloat16 S_ynhi[B16*L64*DM512];
__device__ __nv_bfloat16 S_ynlo[B16*L64*DM512];
__device__ __nv_bfloat16 S_W1hi[1152*DM512];
__device__ __nv_bfloat16 S_W1lo[1152*DM512];
__device__ __nv_bfloat16 S_W2hi[DM512*DM512];
__device__ __nv_bfloat16 S_W2lo[DM512*DM512];
__device__ __nv_bfloat16 S_Whi [DM512*DM512];
__device__ __nv_bfloat16 S_Wlo [DM512*DM512];
// Pt fp32 (tf32-pre-rounded): Pt[b][d][hg], natural layout
__device__ float S_Pt[(size_t)B16*DM512*DM512];

// ---- helpers ---------------------------------------------------------------
__device__ __forceinline__ void mma16816(float* c, const uint32_t* a, const uint32_t* b) {
    asm volatile(
        "mma.sync.aligned.m16n8k16.row.col.f32.bf16.bf16.f32 "
        "{%0,%1,%2,%3}, {%4,%5,%6,%7}, {%8,%9}, {%0,%1,%2,%3};"
        : "+f"(c[0]), "+f"(c[1]), "+f"(c[2]), "+f"(c[3])
        : "r"(a[0]), "r"(a[1]), "r"(a[2]), "r"(a[3]), "r"(b[0]), "r"(b[1]));
}
__device__ __forceinline__ void mma_tf32(float* c, const uint32_t* a, const uint32_t* b) {
    asm volatile(
        "mma.sync.aligned.m16n8k8.row.col.f32.tf32.tf32.f32 "
        "{%0,%1,%2,%3}, {%4,%5,%6,%7}, {%8,%9}, {%0,%1,%2,%3};"
        : "+f"(c[0]), "+f"(c[1]), "+f"(c[2]), "+f"(c[3])
        : "r"(a[0]), "r"(a[1]), "r"(a[2]), "r"(a[3]), "r"(b[0]), "r"(b[1]));
}
__device__ __forceinline__ float to_tf32(float x) {
    uint32_t r;
    asm("cvt.rna.tf32.f32 %0, %1;" : "=r"(r) : "f"(x));
    return __uint_as_float(r);
}
__device__ __forceinline__ void bsplit(float v, __nv_bfloat16& h, __nv_bfloat16& l) {
    h = __float2bfloat16(v);
    l = __float2bfloat16(v - __bfloat162float(h));
}
__device__ __forceinline__ void cp16(void* dst, const void* src) {
    uint32_t d = (uint32_t)__cvta_generic_to_shared(dst);
    asm volatile("cp.async.cg.shared.global [%0], [%1], 16;" :: "r"(d), "l"(src));
}
// predicated 16B cp.async: src_size=0 zero-fills dst (OOB rows)
__device__ __forceinline__ void cp16p(void* dst, const void* src, bool pred) {
    uint32_t d = (uint32_t)__cvta_generic_to_shared(dst);
    int sz = pred ? 16 : 0;
    asm volatile("cp.async.cg.shared.global [%0], [%1], 16, %2;" :: "r"(d), "l"(src), "r"(sz));
}
__device__ __forceinline__ void cp8(void* dst, const void* src) {
    uint32_t d = (uint32_t)__cvta_generic_to_shared(dst);
    asm volatile("cp.async.ca.shared.global [%0], [%1], 8;" :: "r"(d), "l"(src));
}
#define CP_COMMIT() asm volatile("cp.async.commit_group;" ::: "memory")
#define CP_WAIT1()  asm volatile("cp.async.wait_group 1;" ::: "memory")
#define CP_WAIT0()  asm volatile("cp.async.wait_group 0;" ::: "memory")

// ---------------------------------------------------------------------------
// Fused: u transpose/split + inp passthrough (blocks < 1024), weight splits
// (blocks >= 1024). Disjoint blockIdx ranges, fully independent work.
__global__ void k_pre(const float* __restrict__ st, float* __restrict__ out_inp,
                      const float* __restrict__ w_in,
                      const float* __restrict__ w_out,
                      const float* __restrict__ to_w) {
    int bid = blockIdx.x;
    int tid = threadIdx.x;
    if (bid < 1024) {
        int row = bid;
        int b = row >> 6, g = row & 63;
        int h = tid >> 6, c = tid & 63;
        size_t si = (((size_t)(b*8 + h)*64) + g)*64 + c;
        float v = st[si];
        out_inp[si] = v;
        __nv_bfloat16 vh, vl;
        bsplit(v, vh, vl);
        S_uhi[row*DM512 + tid] = vh;
        S_ulo[row*DM512 + tid] = vl;
    } else {
        int i = (bid - 1024)*512 + tid;
        if (i < DINPROJ*DM512) {
            __nv_bfloat16 h, l;
            bsplit(w_in[i], h, l);
            S_W1hi[i] = h; S_W1lo[i] = l;
        }
        if (i < DM512*DM512) {
            __nv_bfloat16 h, l;
            bsplit(w_out[i], h, l);
            S_W2hi[i] = h; S_W2lo[i] = l;
            bsplit(to_w[i], h, l);
            S_Whi[i] = h; S_Wlo[i] = l;
        }
    }
}

// ---------------------------------------------------------------------------
// Presplit GEMM, BM=64, BN=128: C[m,n] = sum_k A[m,k]*B[n,k], split bf16, K=512.
// 8 warps, warp grid 2x4, warp tile 32x32.
#define GS_SMEM 61440
__global__ __launch_bounds__(256) void k_gemm_sp64(
    const __nv_bfloat16* __restrict__ Ahi, const __nv_bfloat16* __restrict__ Alo,
    const __nv_bfloat16* __restrict__ Bhi, const __nv_bfloat16* __restrict__ Blo,
    float* __restrict__ C, int N)
{
    extern __shared__ __nv_bfloat16 smG[];
    int tid = threadIdx.x;
    int wid = tid >> 5, lane = tid & 31;
    int warp_m = wid & 1, warp_n = wid >> 1;
    int lr = lane >> 2;
    int lk = (lane & 3) * 2;
    size_t rbase = (size_t)blockIdx.x * 64;
    int n0 = blockIdx.y * 128;

    const int BUF = (2*64 + 2*128)*40;    // 15360 bf16 per buffer
    int m_st = tid >> 2;
    int kp_st = tid & 3;

    auto stage = [&](int kc, int buf) {
        __nv_bfloat16* Ah = smG + buf*BUF;
        __nv_bfloat16* Al = Ah + 64*40;
        __nv_bfloat16* Wh = Al + 64*40;
        __nv_bfloat16* Wl = Wh + 128*40;
        int kofs = kc*32 + kp_st*8;
        {
            size_t ga = (rbase + m_st)*512 + kofs;
            cp16(&Ah[m_st*40 + kp_st*8], &Ahi[ga]);
            cp16(&Al[m_st*40 + kp_st*8], &Alo[ga]);
        }
        #pragma unroll
        for (int p = 0; p < 2; ++p) {
            int m = m_st + p*64;
            size_t gw = (size_t)(n0 + m)*512 + kofs;
            cp16(&Wh[m*40 + kp_st*8], &Bhi[gw]);
            cp16(&Wl[m*40 + kp_st*8], &Blo[gw]);
        }
    };

    float acc[2][4][4];
    #pragma unroll
    for (int mt = 0; mt < 2; ++mt)
        #pragma unroll
        for (int nt = 0; nt < 4; ++nt)
            #pragma unroll
            for (int q = 0; q < 4; ++q) acc[mt][nt][q] = 0.f;

    stage(0, 0);
    CP_COMMIT();

    for (int kc = 0; kc < 16; ++kc) {
        int cur = kc & 1;
        if (kc < 15) { stage(kc + 1, cur ^ 1); CP_COMMIT(); CP_WAIT1(); }
        else         { CP_WAIT0(); }
        __syncthreads();

        __nv_bfloat16* Ah = smG + cur*BUF;
        __nv_bfloat16* Al = Ah + 64*40;
        __nv_bfloat16* Wh = Al + 64*40;
        __nv_bfloat16* Wl = Wh + 128*40;

        #pragma unroll
        for (int ks = 0; ks < 2; ++ks) {
            int k0 = ks*16;
            uint32_t ah[2][4], al[2][4], bh[4][2], bl[4][2];
            #pragma unroll
            for (int mt = 0; mt < 2; ++mt) {
                int rb = warp_m*32 + mt*16 + lr;
                const __nv_bfloat16* pa = &Ah[rb*40 + k0 + lk];
                ah[mt][0] = *(const uint32_t*)pa;
                ah[mt][1] = *(const uint32_t*)(pa + 8*40);
                ah[mt][2] = *(const uint32_t*)(pa + 8);
                ah[mt][3] = *(const uint32_t*)(pa + 8*40 + 8);
                const __nv_bfloat16* pl = &Al[rb*40 + k0 + lk];
                al[mt][0] = *(const uint32_t*)pl;
                al[mt][1] = *(const uint32_t*)(pl + 8*40);
                al[mt][2] = *(const uint32_t*)(pl + 8);
                al[mt][3] = *(const uint32_t*)(pl + 8*40 + 8);
            }
            #pragma unroll
            for (int nt = 0; nt < 4; ++nt) {
                int nb = warp_n*32 + nt*8 + lr;
                const __nv_bfloat16* pb = &Wh[nb*40 + k0 + lk];
                bh[nt][0] = *(const uint32_t*)pb;
                bh[nt][1] = *(const uint32_t*)(pb + 8);
                const __nv_bfloat16* pl = &Wl[nb*40 + k0 + lk];
                bl[nt][0] = *(const uint32_t*)pl;
                bl[nt][1] = *(const uint32_t*)(pl + 8);
            }
            #pragma unroll
            for (int mt = 0; mt < 2; ++mt)
                #pragma unroll
                for (int nt = 0; nt < 4; ++nt) {
                    mma16816(acc[mt][nt], ah[mt], bh[nt]);
                    mma16816(acc[mt][nt], ah[mt], bl[nt]);
                    mma16816(acc[mt][nt], al[mt], bh[nt]);
                }
        }
        __syncthreads();
    }

    #pragma unroll
    for (int mt = 0; mt < 2; ++mt) {
        int m = warp_m*32 + mt*16 + lr;
        #pragma unroll
        for (int nt = 0; nt < 4; ++nt) {
            int col = n0 + warp_n*32 + nt*8 + lk;
            if (col < N) {
                size_t r = rbase + m;
                float2 v0;
                v0.x = acc[mt][nt][0];
                v0.y = acc[mt][nt][1];
                *(float2*)&C[r*N + col] = v0;
                float2 v1;
                v1.x = acc[mt][nt][2];
                v1.y = acc[mt][nt][3];
                *(float2*)&C[(r + 8)*N + col] = v1;
            }
        }
    }
}

// ---------------------------------------------------------------------------
// Fused conv + scan v3, channel-split. Grid 128 = i*4 + q, 128 threads.
// Phase 1 precomputes a[t][h], dt[t][h], B[t], C[t] in parallel; phase 2 runs
// the serial scan with sliding-window conv (1 LDS/iter) and an FMA-only chain.
#define ZS2_LD 132
#define SC_SMEM (64*ZS2_LD*4 + 3*512*4 + 128*4)
__global__ __launch_bounds__(128) void k_scanc(
    const float* __restrict__ conv_w, const float* __restrict__ conv_b,
    const float* __restrict__ dt_bias, const float* __restrict__ A_log)
{
    extern __shared__ float smS[];
    float* zs  = smS;               // [64][132]: 128 x-cols + B(128) + C(129)
    float* dts = smS + 64*ZS2_LD;   // [64][8] raw dt
    float* av  = dts + 512;         // [64][8] exp(dt*A)
    float* dtv = av + 512;          // [64][8] softplus(dt)
    float* Bs  = dtv + 512;         // [64]
    float* Cs  = Bs + 64;           // [64]

    int cta = blockIdx.x;
    int i = cta >> 2;               // extended batch 0..31
    int q = cta & 3;                // channel quarter
    int d = threadIdx.x;            // 0..127
    bool bw = (i >= 16);
    int b = bw ? i - 16 : i;
    int cbase = q*128;

    // stage: 64 rows x (64 x-pairs + 1 BC-pair) via cp8
    for (int p = 0; p < 33; ++p) {
        int idx = d + p*128;
        if (idx < 64*65) {
            int row = idx / 65, pr = idx - row*65;
            int gcol = (pr < 64) ? (512 + cbase + pr*2) : 1024;
            int scol = (pr < 64) ? (pr*2) : 128;
            cp8(&zs[row*ZS2_LD + scol],
                &S_zx[(size_t)(b*64 + row)*DINPROJ + gcol]);
        }
    }
    #pragma unroll
    for (int p = 0; p < 4; ++p) {
        int idx = d + p*128;
        int row = idx >> 3, hh = idx & 7;
        dts[idx] = S_zx[(b*64 + row)*DINPROJ + 1026 + (bw ? 8 : 0) + hh];
    }
    CP_COMMIT();
    CP_WAIT0();
    __syncthreads();

    // Phase 1a: B / C channels conv + silu (parallel over t)
    if (d < 64) {
        int t = d;
        float acc = conv_b[512];
        #pragma unroll
        for (int k = 0; k < 3; ++k) {
            int tt = t + k - 2;
            if (tt >= 0) acc += conv_w[512*3 + k] * zs[tt*ZS2_LD + 128];
        }
        Bs[t] = acc / (1.f + expf(-acc));
    } else {
        int t = d - 64;
        float acc = conv_b[513];
        #pragma unroll
        for (int k = 0; k < 3; ++k) {
            int tt = t + k - 2;
            if (tt >= 0) acc += conv_w[513*3 + k] * zs[tt*ZS2_LD + 129];
        }
        Cs[t] = acc / (1.f + expf(-acc));
    }
    // Phase 1b: scan coefficients a/dt for all (t,h) (parallel)
    #pragma unroll
    for (int p = 0; p < 4; ++p) {
        int idx = d + p*128;
        int hh = idx & 7;
        float v = dts[idx] + dt_bias[hh];
        float dt = (v > 20.f) ? v : log1pf(expf(v));
        dtv[idx] = dt;
        av[idx]  = expf(dt * (-expf(A_log[hh])));
    }
    __syncthreads();

    // Phase 2: serial scan, sliding-window conv
    int dch = cbase + d;
    int h = dch >> 6;
    float cb = conv_b[dch];
    float w0 = conv_w[dch*3], w1 = conv_w[dch*3 + 1], w2 = conv_w[dch*3 + 2];
    float hs = 0.f;
    S_ys[(size_t)(i*64)*512 + dch] = 0.f;

    if (!bw) {
        float zm2 = 0.f, zm1 = 0.f;
        #pragma unroll 4
        for (int t = 0; t < 64; ++t) {
            float z0 = zs[t*ZS2_LD + d];
            float cv = cb + w0*zm2 + w1*zm1 + w2*z0;
            float x  = cv / (1.f + expf(-cv));
            S_x[(size_t)(b*64 + t)*512 + dch] = x;
            hs = av[t*8 + h]*hs + dtv[t*8 + h]*Bs[t]*x;
            if (t < 63) S_ys[(size_t)(i*64 + t + 1)*512 + dch] = hs * Cs[t];
            zm2 = zm1; zm1 = z0;
        }
    } else {
        float z0  = zs[63*ZS2_LD + d];
        float zm1 = zs[62*ZS2_LD + d];
        float zm2 = zs[61*ZS2_LD + d];
        #pragma unroll 4
        for (int t = 0; t < 64; ++t) {
            int tt = 63 - t;
            float cv = cb + w0*zm2 + w1*zm1 + w2*z0;
            float x  = cv / (1.f + expf(-cv));
            hs = av[tt*8 + h]*hs + dtv[tt*8 + h]*Bs[tt]*x;
            if (t < 63) S_ys[(size_t)(i*64 + t + 1)*512 + dch] = hs * Cs[tt];
            z0 = zm1; zm1 = zm2;
            int nxt = tt - 3;
            zm2 = (nxt >= 0) ? zs[nxt*ZS2_LD + d] : 0.f;
        }
    }
}

// ---------------------------------------------------------------------------
__global__ __launch_bounds__(512) void k_combine(
    const float* __restrict__ fc_D_w, const float* __restrict__ Dv,
    const float* __restrict__ norm_w)
{
    int row = blockIdx.x;
    int b = row >> 6, t = row & 63;
    int d = threadIdx.x;
    int h = d >> 6;
    int lane = d & 31, wid = d >> 5;

    float x  = S_x[row*512 + d];
    float z  = S_zx[row*DINPROJ + d];
    float yf = S_ys[row*512 + d];
    float yb = S_ys[((16 + b)*64 + (63 - t))*512 + d];

    float px[8];
    #pragma unroll
    for (int hh = 0; hh < 8; ++hh) px[hh] = x * fc_D_w[hh*512 + d];
    #pragma unroll
    for (int off = 16; off; off >>= 1)
        #pragma unroll
        for (int hh = 0; hh < 8; ++hh) px[hh] += __shfl_xor_sync(0xffffffffu, px[hh], off);

    __shared__ float wsum[16][8];
    __shared__ float dcf[8];
    if (lane == 0) {
        #pragma unroll
        for (int hh = 0; hh < 8; ++hh) wsum[wid][hh] = px[hh];
    }
    __syncthreads();
    if (d < 8) {
        float s = 0.f;
        #pragma unroll
        for (int w = 0; w < 16; ++w) s += wsum[w][d];
        dcf[d] = s + Dv[d];
    }
    __syncthreads();

    float y = yf + yb + x * dcf[h];
    y *= z / (1.f + expf(-z));

    float sq = y*y;
    #pragma unroll
    for (int off = 16; off; off >>= 1) sq += __shfl_xor_sync(0xffffffffu, sq, off);
    __shared__ float rsum[16];
    __shared__ float rscale;
    if (lane == 0) rsum[wid] = sq;
    __syncthreads();
    if (d == 0) {
        float s = 0.f;
        #pragma unroll
        for (int w = 0; w < 16; ++w) s += rsum[w];
        rscale = rsqrtf(s / 512.f + 1e-5f);
    }
    __syncthreads();
    float yn = y * rscale * norm_w[d];
    __nv_bfloat16 vh, vl;
    bsplit(yn, vh, vl);
    S_ynhi[row*512 + d] = vh;
    S_ynlo[row*512 + d] = vl;
}

// ---------------------------------------------------------------------------
// prepP: Pt[b][d][h*64+g] = sum_c to_w[d, h*64+c] * S_out[(b*64+g)*512 + h*64+c]
// Split-bf16 mma; epilogue writes tf32-rounded fp32 into S_Pt.
// Also emits the outp output (dbase==0 CTAs) while staging B.
#define PP_SMEM 55296
__global__ __launch_bounds__(256) void k_prepP(float* __restrict__ out_outp) {
    extern __shared__ __nv_bfloat16 smP[];
    __nv_bfloat16* Ahs = smP;
    __nv_bfloat16* Als = smP + 128*72;
    __nv_bfloat16* Bhs = smP + 2*128*72;
    __nv_bfloat16* Bls = Bhs + 64*72;

    int tid = threadIdx.x;
    int wid = tid >> 5, lane = tid & 31;
    int warp_m = wid & 1, warp_n = wid >> 1;
    int lr = lane >> 2;
    int lk = (lane & 3) * 2;
    int bh = blockIdx.x;
    int b = bh >> 3, h = bh & 7;
    int dbase = blockIdx.y * 128;

    {
        int r = tid >> 1, half = tid & 1;
        #pragma unroll
        for (int q0 = 0; q0 < 4; ++q0) {
            int q = half*4 + q0;
            size_t src = (size_t)(dbase + r)*512 + h*64 + q*8;
            cp16(&Ahs[r*72 + q*8], &S_Whi[src]);
            cp16(&Als[r*72 + q*8], &S_Wlo[src]);
        }
    }
    #pragma unroll
    for (int p = 0; p < 16; ++p) {
        int idx = tid + p*256;
        int g = idx >> 6, c = idx & 63;
        float v = S_out[(size_t)(b*64 + g)*512 + h*64 + c];
        if (dbase == 0) out_outp[(((b*8 + h)*64 + g)*64) + c] = v;
        __nv_bfloat16 vh, vl;
        bsplit(v, vh, vl);
        Bhs[g*72 + c] = vh;
        Bls[g*72 + c] = vl;
    }
    CP_COMMIT();
    CP_WAIT0();
    __syncthreads();

    float acc[4][2][4];
    #pragma unroll
    for (int mt = 0; mt < 4; ++mt)
        #pragma unroll
        for (int nt = 0; nt < 2; ++nt)
            #pragma unroll
            for (int q = 0; q < 4; ++q) acc[mt][nt][q] = 0.f;

    #pragma unroll
    for (int ks = 0; ks < 4; ++ks) {
        int k0 = ks*16;
        uint32_t ah[4][4], al[4][4], bhf[2][2], blf[2][2];
        #pragma unroll
        for (int mt = 0; mt < 4; ++mt) {
            int rb = warp_m*64 + mt*16 + lr;
            const __nv_bfloat16* pa = &Ahs[rb*72 + k0 + lk];
            ah[mt][0] = *(const uint32_t*)pa;
            ah[mt][1] = *(const uint32_t*)(pa + 8*72);
            ah[mt][2] = *(const uint32_t*)(pa + 8);
            ah[mt][3] = *(const uint32_t*)(pa + 8*72 + 8);
            const __nv_bfloat16* pl = &Als[rb*72 + k0 + lk];
            al[mt][0] = *(const uint32_t*)pl;
            al[mt][1] = *(const uint32_t*)(pl + 8*72);
            al[mt][2] = *(const uint32_t*)(pl + 8);
            al[mt][3] = *(const uint32_t*)(pl + 8*72 + 8);
        }
        #pragma unroll
        for (int nt = 0; nt < 2; ++nt) {
            int nb = warp_n*16 + nt*8 + lr;
            const __nv_bfloat16* pb = &Bhs[nb*72 + k0 + lk];
            bhf[nt][0] = *(const uint32_t*)pb;
            bhf[nt][1] = *(const uint32_t*)(pb + 8);
            const __nv_bfloat16* pl = &Bls[nb*72 + k0 + lk];
            blf[nt][0] = *(const uint32_t*)pl;
            blf[nt][1] = *(const uint32_t*)(pl + 8);
        }
        #pragma unroll
        for (int mt = 0; mt < 4; ++mt)
            #pragma unroll
            for (int nt = 0; nt < 2; ++nt) {
                mma16816(acc[mt][nt], ah[mt], bhf[nt]);
                mma16816(acc[mt][nt], ah[mt], blf[nt]);
                mma16816(acc[mt][nt], al[mt], bhf[nt]);
            }
    }

    #pragma unroll
    for (int mt = 0; mt < 4; ++mt) {
        int m = warp_m*64 + mt*16 + lr;
        #pragma unroll
        for (int nt = 0; nt < 2; ++nt) {
            int coln = warp_n*16 + nt*8 + lk;
            size_t base = ((size_t)b*512 + dbase + m)*512 + h*64 + coln;
            float2 v0;
            v0.x = to_tf32(acc[mt][nt][0]);
            v0.y = to_tf32(acc[mt][nt][1]);
            *(float2*)&S_Pt[base] = v0;
            float2 v1;
            v1.x = to_tf32(acc[mt][nt][2]);
            v1.y = to_tf32(acc[mt][nt][3]);
            *(float2*)&S_Pt[base + 8*512] = v1;
        }
    }
}

// ---------------------------------------------------------------------------
// Big GEMM (tf32, 3-stage all-cp.async pipeline, raw-bit A operands)
#define BM_BUF  (2*128*36)
#define BM_SMEM (3*BM_BUF*4)
__global__ __launch_bounds__(256, 2) void k_bigmma(
    const float* __restrict__ sw, const float* __restrict__ bias,
    float* __restrict__ out)
{
    extern __shared__ float smB[];
    int tid = threadIdx.x;
    int wid = tid >> 5, lane = tid & 31;
    int warp_m = wid & 1, warp_n = wid >> 1;
    int lr = lane >> 2;
    int lq = lane & 3;
    int dc = blockIdx.x & 3;
    int mt0 = blockIdx.x >> 2;
    int n0 = mt0 * 128;
    int b  = blockIdx.y;
    int dbase = dc * 128;

    int arow = tid >> 1;
    int ahalf = tid & 1;
    bool avalid = (n0 + arow) < NCTX;

    auto stageA = [&](int kc, int buf) {
        float* As = smB + buf*BM_BUF;
        int h = kc >> 1;
        int g0 = (kc & 1)*32 + ahalf*16;
        const float* src = sw + ((size_t)(b*8 + h)*NCTX + (avalid ? n0 + arow : 0))*64 + g0;
        float* dst = &As[arow*36 + ahalf*16];
        cp16p(dst,      src,      avalid);
        cp16p(dst + 4,  src + 4,  avalid);
        cp16p(dst + 8,  src + 8,  avalid);
        cp16p(dst + 12, src + 12, avalid);
    };
    auto stageB = [&](int kc, int buf) {
        float* Bs = smB + buf*BM_BUF + 128*36;
        #pragma unroll
        for (int p = 0; p < 4; ++p) {
            int idx = tid + p*256;
            int row = idx >> 3, q = idx & 7;
            size_t src = ((size_t)b*512 + dbase + row)*512 + kc*32 + q*4;
            cp16(&Bs[row*36 + q*4], &S_Pt[src]);
        }
    };

    float acc[4][4][4];
    #pragma unroll
    for (int mt = 0; mt < 4; ++mt)
        #pragma unroll
        for (int nt = 0; nt < 4; ++nt)
            #pragma unroll
            for (int q = 0; q < 4; ++q) acc[mt][nt][q] = 0.f;

    stageA(0, 0); stageB(0, 0); CP_COMMIT();
    stageA(1, 1); stageB(1, 1); CP_COMMIT();

    for (int kc = 0; kc < 16; ++kc) {
        if (kc < 15) { CP_WAIT1(); }
        else         { CP_WAIT0(); }
        __syncthreads();
        if (kc + 2 < 16) {
            int nb = (kc + 2) % 3;
            stageA(kc + 2, nb);
            stageB(kc + 2, nb);
            CP_COMMIT();
        }

        float* As = smB + (kc % 3)*BM_BUF;
        float* Bs = As + 128*36;

        #pragma unroll
        for (int ks = 0; ks < 4; ++ks) {
            int k0 = ks*8;
            uint32_t af[4][4], bf[4][2];
            #pragma unroll
            for (int mt = 0; mt < 4; ++mt) {
                int rb = warp_m*64 + mt*16 + lr;
                const float* pa = &As[rb*36 + k0 + lq];
                af[mt][0] = __float_as_uint(pa[0]);
                af[mt][1] = __float_as_uint(pa[8*36]);
                af[mt][2] = __float_as_uint(pa[4]);
                af[mt][3] = __float_as_uint(pa[8*36 + 4]);
            }
            #pragma unroll
            for (int nt = 0; nt < 4; ++nt) {
                int nb = warp_n*32 + nt*8 + lr;
                const float* pb = &Bs[nb*36 + k0 + lq];
                bf[nt][0] = __float_as_uint(pb[0]);
                bf[nt][1] = __float_as_uint(pb[4]);
            }
            #pragma unroll
            for (int mt = 0; mt < 4; ++mt)
                #pragma unroll
                for (int nt = 0; nt < 4; ++nt)
                    mma_tf32(acc[mt][nt], af[mt], bf[nt]);
        }
    }

    // epilogue
    #pragma unroll
    for (int mt = 0; mt < 4; ++mt) {
        int m = warp_m*64 + mt*16 + lr;
        #pragma unroll
        for (int nt = 0; nt < 4; ++nt) {
            int col = dbase + warp_n*32 + nt*8 + lq*2;
            float b0 = __ldg(&bias[col]);
            float b1 = __ldg(&bias[col + 1]);
            if (n0 + m < NCTX) {
                size_t r = (size_t)b*NCTX + n0 + m;
                float2 v;
                v.x = acc[mt][nt][0] + b0;
                v.y = acc[mt][nt][1] + b1;
                *(float2*)&out[r*512 + col] = v;
            }
            if (n0 + m + 8 < NCTX) {
                size_t r = (size_t)b*NCTX + n0 + m + 8;
                float2 v;
                v.x = acc[mt][nt][2] + b0;
                v.y = acc[mt][nt][3] + b1;
                *(float2*)&out[r*512 + col] = v;
            }
        }
    }
}

// ---------------------------------------------------------------------------
extern "C" void kernel_launch(void* const* d_in, const int* in_sizes, int n_in,
                              void* d_out, int out_size) {
    const float* st     = (const float*)d_in[0];
    const float* sw     = (const float*)d_in[1];
    const float* w_in   = (const float*)d_in[2];
    const float* conv_w = (const float*)d_in[3];
    const float* conv_b = (const float*)d_in[4];
    const float* dt_bias= (const float*)d_in[5];
    const float* A_log  = (const float*)d_in[6];
    const float* Dv     = (const float*)d_in[7];
    const float* fc_D_w = (const float*)d_in[8];
    const float* norm_w = (const float*)d_in[9];
    const float* w_out  = (const float*)d_in[10];
    const float* to_w   = (const float*)d_in[11];
    const float* to_b   = (const float*)d_in[12];

    float* out       = (float*)d_out;
    float* out_final = out;
    float* out_inp   = out + (size_t)B16*NCTX*DM512;
    float* out_outp  = out_inp + (size_t)B16*8*64*64;

    float *pSzx, *pSout;
    __nv_bfloat16 *pUh, *pUl, *pYh, *pYl, *pW1h, *pW1l, *pW2h, *pW2l;
    cudaGetSymbolAddress((void**)&pSzx, S_zx);
    cudaGetSymbolAddress((void**)&pSout, S_out);
    cudaGetSymbolAddress((void**)&pUh, S_uhi);
    cudaGetSymbolAddress((void**)&pUl, S_ulo);
    cudaGetSymbolAddress((void**)&pYh, S_ynhi);
    cudaGetSymbolAddress((void**)&pYl, S_ynlo);
    cudaGetSymbolAddress((void**)&pW1h, S_W1hi);
    cudaGetSymbolAddress((void**)&pW1l, S_W1lo);
    cudaGetSymbolAddress((void**)&pW2h, S_W2hi);
    cudaGetSymbolAddress((void**)&pW2l, S_W2lo);

    k_pre<<<1024 + 1042, 512>>>(st, out_inp, w_in, w_out, to_w);

    cudaFuncSetAttribute(k_gemm_sp64, cudaFuncAttributeMaxDynamicSharedMemorySize, GS_SMEM);
    k_gemm_sp64<<<dim3(16, 9), 256, GS_SMEM>>>(pUh, pUl, pW1h, pW1l, pSzx, DINPROJ);

    cudaFuncSetAttribute(k_scanc, cudaFuncAttributeMaxDynamicSharedMemorySize, SC_SMEM);
    k_scanc<<<128, 128, SC_SMEM>>>(conv_w, conv_b, dt_bias, A_log);

    k_combine<<<B16*L64, 512>>>(fc_D_w, Dv, norm_w);

    k_gemm_sp64<<<dim3(16, 4), 256, GS_SMEM>>>(pYh, pYl, pW2h, pW2l, pSout, DM512);

    cudaFuncSetAttribute(k_prepP, cudaFuncAttributeMaxDynamicSharedMemorySize, PP_SMEM);
    k_prepP<<<dim3(128, 4), 256, PP_SMEM>>>(out_outp);

    cudaFuncSetAttribute(k_bigmma, cudaFuncAttributeMaxDynamicSharedMemorySize, BM_SMEM);
    k_bigmma<<<dim3(4*((NCTX + 127)/128), B16), 256, BM_SMEM>>>(sw, to_b, out_final);
}

// round 14
// speedup vs baseline: 6.0814x; 1.0227x over previous
#include <cuda_runtime.h>
#include <cuda_bf16.h>
#include <math.h>
#include <stdint.h>

// Problem constants
#define B16    16
#define L64    64
#define DM512  512
#define NCTX   3131
#define DINPROJ 1042
#define CONVDIM 514
#define MROWS  50096            // 16*3131

// Scratch (static device arrays; zero-initialized, allocation-free)
__device__ float S_zx [B16*L64*DINPROJ];
__device__ float S_x  [B16*L64*DM512];
__device__ float S_ys [2*B16*L64*DM512];
// split-bf16 operands (pre-pipeline)
__device__ __nv_bfloat16 S_uhi [B16*L64*DM512];
__device__ __nv_bfloat16 S_ulo [B16*L64*DM512];
__device__ __nv_bfloat16 S_ynhi[B16*L64*DM512];
__device__ __nv_bfloat16 S_ynlo[B16*L64*DM512];
__device__ __nv_bfloat16 S_outhi[B16*L64*DM512];
__device__ __nv_bfloat16 S_outlo[B16*L64*DM512];
__device__ __nv_bfloat16 S_W1hi[1152*DM512];
__device__ __nv_bfloat16 S_W1lo[1152*DM512];
__device__ __nv_bfloat16 S_W2hi[DM512*DM512];
__device__ __nv_bfloat16 S_W2lo[DM512*DM512];
__device__ __nv_bfloat16 S_Whi [DM512*DM512];
__device__ __nv_bfloat16 S_Wlo [DM512*DM512];
// Pt fp32 (tf32-pre-rounded): Pt[b][d][hg], natural layout
__device__ float S_Pt[(size_t)B16*DM512*DM512];

// ---- helpers ---------------------------------------------------------------
#define GDC_WAIT() asm volatile("griddepcontrol.wait;" ::: "memory")

__device__ __forceinline__ void mma16816(float* c, const uint32_t* a, const uint32_t* b) {
    asm volatile(
        "mma.sync.aligned.m16n8k16.row.col.f32.bf16.bf16.f32 "
        "{%0,%1,%2,%3}, {%4,%5,%6,%7}, {%8,%9}, {%0,%1,%2,%3};"
        : "+f"(c[0]), "+f"(c[1]), "+f"(c[2]), "+f"(c[3])
        : "r"(a[0]), "r"(a[1]), "r"(a[2]), "r"(a[3]), "r"(b[0]), "r"(b[1]));
}
__device__ __forceinline__ void mma_tf32(float* c, const uint32_t* a, const uint32_t* b) {
    asm volatile(
        "mma.sync.aligned.m16n8k8.row.col.f32.tf32.tf32.f32 "
        "{%0,%1,%2,%3}, {%4,%5,%6,%7}, {%8,%9}, {%0,%1,%2,%3};"
        : "+f"(c[0]), "+f"(c[1]), "+f"(c[2]), "+f"(c[3])
        : "r"(a[0]), "r"(a[1]), "r"(a[2]), "r"(a[3]), "r"(b[0]), "r"(b[1]));
}
__device__ __forceinline__ float to_tf32(float x) {
    uint32_t r;
    asm("cvt.rna.tf32.f32 %0, %1;" : "=r"(r) : "f"(x));
    return __uint_as_float(r);
}
__device__ __forceinline__ void bsplit(float v, __nv_bfloat16& h, __nv_bfloat16& l) {
    h = __float2bfloat16(v);
    l = __float2bfloat16(v - __bfloat162float(h));
}
__device__ __forceinline__ void cp16(void* dst, const void* src) {
    uint32_t d = (uint32_t)__cvta_generic_to_shared(dst);
    asm volatile("cp.async.cg.shared.global [%0], [%1], 16;" :: "r"(d), "l"(src));
}
// predicated 16B cp.async: src_size=0 zero-fills dst (OOB rows)
__device__ __forceinline__ void cp16p(void* dst, const void* src, bool pred) {
    uint32_t d = (uint32_t)__cvta_generic_to_shared(dst);
    int sz = pred ? 16 : 0;
    asm volatile("cp.async.cg.shared.global [%0], [%1], 16, %2;" :: "r"(d), "l"(src), "r"(sz));
}
__device__ __forceinline__ void cp8(void* dst, const void* src) {
    uint32_t d = (uint32_t)__cvta_generic_to_shared(dst);
    asm volatile("cp.async.ca.shared.global [%0], [%1], 8;" :: "r"(d), "l"(src));
}
#define CP_COMMIT() asm volatile("cp.async.commit_group;" ::: "memory")
#define CP_WAIT1()  asm volatile("cp.async.wait_group 1;" ::: "memory")
#define CP_WAIT0()  asm volatile("cp.async.wait_group 0;" ::: "memory")

// ---------------------------------------------------------------------------
// Fused: u transpose/split + inp passthrough (blocks < 1024), weight splits
// (blocks >= 1024).
__global__ void k_pre(const float* __restrict__ st, float* __restrict__ out_inp,
                      const float* __restrict__ w_in,
                      const float* __restrict__ w_out,
                      const float* __restrict__ to_w) {
    int bid = blockIdx.x;
    int tid = threadIdx.x;
    if (bid < 1024) {
        int row = bid;
        int b = row >> 6, g = row & 63;
        int h = tid >> 6, c = tid & 63;
        size_t si = (((size_t)(b*8 + h)*64) + g)*64 + c;
        float v = st[si];
        out_inp[si] = v;
        __nv_bfloat16 vh, vl;
        bsplit(v, vh, vl);
        S_uhi[row*DM512 + tid] = vh;
        S_ulo[row*DM512 + tid] = vl;
    } else {
        int i = (bid - 1024)*512 + tid;
        if (i < DINPROJ*DM512) {
            __nv_bfloat16 h, l;
            bsplit(w_in[i], h, l);
            S_W1hi[i] = h; S_W1lo[i] = l;
        }
        if (i < DM512*DM512) {
            __nv_bfloat16 h, l;
            bsplit(w_out[i], h, l);
            S_W2hi[i] = h; S_W2lo[i] = l;
            bsplit(to_w[i], h, l);
            S_Whi[i] = h; S_Wlo[i] = l;
        }
    }
}

// ---------------------------------------------------------------------------
// Presplit GEMM, BM=64, BN=128. mode 0: C[m,n] fp32. mode 1: split bf16 to
// S_outhi/S_outlo + permuted outp output (out-projection epilogue).
#define GS_SMEM 61440
__global__ __launch_bounds__(256) void k_gemm_sp64(
    const __nv_bfloat16* __restrict__ Ahi, const __nv_bfloat16* __restrict__ Alo,
    const __nv_bfloat16* __restrict__ Bhi, const __nv_bfloat16* __restrict__ Blo,
    float* __restrict__ C, int N, int mode, float* __restrict__ outp)
{
    extern __shared__ __nv_bfloat16 smG[];
    GDC_WAIT();
    int tid = threadIdx.x;
    int wid = tid >> 5, lane = tid & 31;
    int warp_m = wid & 1, warp_n = wid >> 1;
    int lr = lane >> 2;
    int lk = (lane & 3) * 2;
    size_t rbase = (size_t)blockIdx.x * 64;
    int n0 = blockIdx.y * 128;

    const int BUF = (2*64 + 2*128)*40;
    int m_st = tid >> 2;
    int kp_st = tid & 3;

    auto stage = [&](int kc, int buf) {
        __nv_bfloat16* Ah = smG + buf*BUF;
        __nv_bfloat16* Al = Ah + 64*40;
        __nv_bfloat16* Wh = Al + 64*40;
        __nv_bfloat16* Wl = Wh + 128*40;
        int kofs = kc*32 + kp_st*8;
        {
            size_t ga = (rbase + m_st)*512 + kofs;
            cp16(&Ah[m_st*40 + kp_st*8], &Ahi[ga]);
            cp16(&Al[m_st*40 + kp_st*8], &Alo[ga]);
        }
        #pragma unroll
        for (int p = 0; p < 2; ++p) {
            int m = m_st + p*64;
            size_t gw = (size_t)(n0 + m)*512 + kofs;
            cp16(&Wh[m*40 + kp_st*8], &Bhi[gw]);
            cp16(&Wl[m*40 + kp_st*8], &Blo[gw]);
        }
    };

    float acc[2][4][4];
    #pragma unroll
    for (int mt = 0; mt < 2; ++mt)
        #pragma unroll
        for (int nt = 0; nt < 4; ++nt)
            #pragma unroll
            for (int q = 0; q < 4; ++q) acc[mt][nt][q] = 0.f;

    stage(0, 0);
    CP_COMMIT();

    for (int kc = 0; kc < 16; ++kc) {
        int cur = kc & 1;
        if (kc < 15) { stage(kc + 1, cur ^ 1); CP_COMMIT(); CP_WAIT1(); }
        else         { CP_WAIT0(); }
        __syncthreads();

        __nv_bfloat16* Ah = smG + cur*BUF;
        __nv_bfloat16* Al = Ah + 64*40;
        __nv_bfloat16* Wh = Al + 64*40;
        __nv_bfloat16* Wl = Wh + 128*40;

        #pragma unroll
        for (int ks = 0; ks < 2; ++ks) {
            int k0 = ks*16;
            uint32_t ah[2][4], al[2][4], bh[4][2], bl[4][2];
            #pragma unroll
            for (int mt = 0; mt < 2; ++mt) {
                int rb = warp_m*32 + mt*16 + lr;
                const __nv_bfloat16* pa = &Ah[rb*40 + k0 + lk];
                ah[mt][0] = *(const uint32_t*)pa;
                ah[mt][1] = *(const uint32_t*)(pa + 8*40);
                ah[mt][2] = *(const uint32_t*)(pa + 8);
                ah[mt][3] = *(const uint32_t*)(pa + 8*40 + 8);
                const __nv_bfloat16* pl = &Al[rb*40 + k0 + lk];
                al[mt][0] = *(const uint32_t*)pl;
                al[mt][1] = *(const uint32_t*)(pl + 8*40);
                al[mt][2] = *(const uint32_t*)(pl + 8);
                al[mt][3] = *(const uint32_t*)(pl + 8*40 + 8);
            }
            #pragma unroll
            for (int nt = 0; nt < 4; ++nt) {
                int nb = warp_n*32 + nt*8 + lr;
                const __nv_bfloat16* pb = &Wh[nb*40 + k0 + lk];
                bh[nt][0] = *(const uint32_t*)pb;
                bh[nt][1] = *(const uint32_t*)(pb + 8);
                const __nv_bfloat16* pl = &Wl[nb*40 + k0 + lk];
                bl[nt][0] = *(const uint32_t*)pl;
                bl[nt][1] = *(const uint32_t*)(pl + 8);
            }
            #pragma unroll
            for (int mt = 0; mt < 2; ++mt)
                #pragma unroll
                for (int nt = 0; nt < 4; ++nt) {
                    mma16816(acc[mt][nt], ah[mt], bh[nt]);
                    mma16816(acc[mt][nt], ah[mt], bl[nt]);
                    mma16816(acc[mt][nt], al[mt], bh[nt]);
                }
        }
        __syncthreads();
    }

    #pragma unroll
    for (int mt = 0; mt < 2; ++mt) {
        int m = warp_m*32 + mt*16 + lr;
        #pragma unroll
        for (int nt = 0; nt < 4; ++nt) {
            int col = n0 + warp_n*32 + nt*8 + lk;
            if (col >= N) continue;
            size_t r0 = rbase + m;
            size_t r1 = r0 + 8;
            if (mode == 0) {
                float2 v0;
                v0.x = acc[mt][nt][0];
                v0.y = acc[mt][nt][1];
                *(float2*)&C[r0*N + col] = v0;
                float2 v1;
                v1.x = acc[mt][nt][2];
                v1.y = acc[mt][nt][3];
                *(float2*)&C[r1*N + col] = v1;
            } else {
                int h = col >> 6, c = col & 63;
                #pragma unroll
                for (int rr = 0; rr < 2; ++rr) {
                    size_t r = rr ? r1 : r0;
                    float v0 = acc[mt][nt][2*rr], v1 = acc[mt][nt][2*rr + 1];
                    __nv_bfloat16 h0, l0, h1, l1;
                    bsplit(v0, h0, l0);
                    bsplit(v1, h1, l1);
                    __nv_bfloat162 H; H.x = h0; H.y = h1;
                    __nv_bfloat162 L; L.x = l0; L.y = l1;
                    *(uint32_t*)&S_outhi[r*512 + col] = *(uint32_t*)&H;
                    *(uint32_t*)&S_outlo[r*512 + col] = *(uint32_t*)&L;
                    int b = (int)(r >> 6), g = (int)(r & 63);
                    float2 ov; ov.x = v0; ov.y = v1;
                    *(float2*)&outp[(((b*8 + h)*64 + g)*64) + c] = ov;
                }
            }
        }
    }
}

// ---------------------------------------------------------------------------
// Fused conv + scan v3, channel-split. Grid 128 = i*4 + q, 128 threads.
#define ZS2_LD 132
#define SC_SMEM (64*ZS2_LD*4 + 3*512*4 + 128*4)
__global__ __launch_bounds__(128) void k_scanc(
    const float* __restrict__ conv_w, const float* __restrict__ conv_b,
    const float* __restrict__ dt_bias, const float* __restrict__ A_log)
{
    extern __shared__ float smS[];
    GDC_WAIT();
    float* zs  = smS;
    float* dts = smS + 64*ZS2_LD;
    float* av  = dts + 512;
    float* dtv = av + 512;
    float* Bs  = dtv + 512;
    float* Cs  = Bs + 64;

    int cta = blockIdx.x;
    int i = cta >> 2;
    int q = cta & 3;
    int d = threadIdx.x;
    bool bw = (i >= 16);
    int b = bw ? i - 16 : i;
    int cbase = q*128;

    for (int p = 0; p < 33; ++p) {
        int idx = d + p*128;
        if (idx < 64*65) {
            int row = idx / 65, pr = idx - row*65;
            int gcol = (pr < 64) ? (512 + cbase + pr*2) : 1024;
            int scol = (pr < 64) ? (pr*2) : 128;
            cp8(&zs[row*ZS2_LD + scol],
                &S_zx[(size_t)(b*64 + row)*DINPROJ + gcol]);
        }
    }
    #pragma unroll
    for (int p = 0; p < 4; ++p) {
        int idx = d + p*128;
        int row = idx >> 3, hh = idx & 7;
        dts[idx] = S_zx[(b*64 + row)*DINPROJ + 1026 + (bw ? 8 : 0) + hh];
    }
    CP_COMMIT();
    CP_WAIT0();
    __syncthreads();

    if (d < 64) {
        int t = d;
        float acc = conv_b[512];
        #pragma unroll
        for (int k = 0; k < 3; ++k) {
            int tt = t + k - 2;
            if (tt >= 0) acc += conv_w[512*3 + k] * zs[tt*ZS2_LD + 128];
        }
        Bs[t] = acc / (1.f + expf(-acc));
    } else {
        int t = d - 64;
        float acc = conv_b[513];
        #pragma unroll
        for (int k = 0; k < 3; ++k) {
            int tt = t + k - 2;
            if (tt >= 0) acc += conv_w[513*3 + k] * zs[tt*ZS2_LD + 129];
        }
        Cs[t] = acc / (1.f + expf(-acc));
    }
    #pragma unroll
    for (int p = 0; p < 4; ++p) {
        int idx = d + p*128;
        int hh = idx & 7;
        float v = dts[idx] + dt_bias[hh];
        float dt = (v > 20.f) ? v : log1pf(expf(v));
        dtv[idx] = dt;
        av[idx]  = expf(dt * (-expf(A_log[hh])));
    }
    __syncthreads();

    int dch = cbase + d;
    int h = dch >> 6;
    float cb = conv_b[dch];
    float w0 = conv_w[dch*3], w1 = conv_w[dch*3 + 1], w2 = conv_w[dch*3 + 2];
    float hs = 0.f;
    S_ys[(size_t)(i*64)*512 + dch] = 0.f;

    if (!bw) {
        float zm2 = 0.f, zm1 = 0.f;
        #pragma unroll 4
        for (int t = 0; t < 64; ++t) {
            float z0 = zs[t*ZS2_LD + d];
            float cv = cb + w0*zm2 + w1*zm1 + w2*z0;
            float x  = cv / (1.f + expf(-cv));
            S_x[(size_t)(b*64 + t)*512 + dch] = x;
            hs = av[t*8 + h]*hs + dtv[t*8 + h]*Bs[t]*x;
            if (t < 63) S_ys[(size_t)(i*64 + t + 1)*512 + dch] = hs * Cs[t];
            zm2 = zm1; zm1 = z0;
        }
    } else {
        float z0  = zs[63*ZS2_LD + d];
        float zm1 = zs[62*ZS2_LD + d];
        float zm2 = zs[61*ZS2_LD + d];
        #pragma unroll 4
        for (int t = 0; t < 64; ++t) {
            int tt = 63 - t;
            float cv = cb + w0*zm2 + w1*zm1 + w2*z0;
            float x  = cv / (1.f + expf(-cv));
            hs = av[tt*8 + h]*hs + dtv[tt*8 + h]*Bs[tt]*x;
            if (t < 63) S_ys[(size_t)(i*64 + t + 1)*512 + dch] = hs * Cs[tt];
            z0 = zm1; zm1 = zm2;
            int nxt = tt - 3;
            zm2 = (nxt >= 0) ? zs[nxt*ZS2_LD + d] : 0.f;
        }
    }
}

// ---------------------------------------------------------------------------
__global__ __launch_bounds__(512) void k_combine(
    const float* __restrict__ fc_D_w, const float* __restrict__ Dv,
    const float* __restrict__ norm_w)
{
    GDC_WAIT();
    int row = blockIdx.x;
    int b = row >> 6, t = row & 63;
    int d = threadIdx.x;
    int h = d >> 6;
    int lane = d & 31, wid = d >> 5;

    float x  = S_x[row*512 + d];
    float z  = S_zx[row*DINPROJ + d];
    float yf = S_ys[row*512 + d];
    float yb = S_ys[((16 + b)*64 + (63 - t))*512 + d];

    float px[8];
    #pragma unroll
    for (int hh = 0; hh < 8; ++hh) px[hh] = x * fc_D_w[hh*512 + d];
    #pragma unroll
    for (int off = 16; off; off >>= 1)
        #pragma unroll
        for (int hh = 0; hh < 8; ++hh) px[hh] += __shfl_xor_sync(0xffffffffu, px[hh], off);

    __shared__ float wsum[16][8];
    __shared__ float dcf[8];
    if (lane == 0) {
        #pragma unroll
        for (int hh = 0; hh < 8; ++hh) wsum[wid][hh] = px[hh];
    }
    __syncthreads();
    if (d < 8) {
        float s = 0.f;
        #pragma unroll
        for (int w = 0; w < 16; ++w) s += wsum[w][d];
        dcf[d] = s + Dv[d];
    }
    __syncthreads();

    float y = yf + yb + x * dcf[h];
    y *= z / (1.f + expf(-z));

    float sq = y*y;
    #pragma unroll
    for (int off = 16; off; off >>= 1) sq += __shfl_xor_sync(0xffffffffu, sq, off);
    __shared__ float rsum[16];
    __shared__ float rscale;
    if (lane == 0) rsum[wid] = sq;
    __syncthreads();
    if (d == 0) {
        float s = 0.f;
        #pragma unroll
        for (int w = 0; w < 16; ++w) s += rsum[w];
        rscale = rsqrtf(s / 512.f + 1e-5f);
    }
    __syncthreads();
    float yn = y * rscale * norm_w[d];
    __nv_bfloat16 vh, vl;
    bsplit(yn, vh, vl);
    S_ynhi[row*512 + d] = vh;
    S_ynlo[row*512 + d] = vl;
}

// ---------------------------------------------------------------------------
// prepP: Pt[b][d][h*64+g] = sum_c to_w[d, h*64+c] * out[(b*64+g)*512 + h*64+c]
// B operand pre-split by gemm2 epilogue -> pure cp.async staging.
#define PP_SMEM 55296
__global__ __launch_bounds__(256) void k_prepP() {
    extern __shared__ __nv_bfloat16 smP[];
    GDC_WAIT();
    __nv_bfloat16* Ahs = smP;
    __nv_bfloat16* Als = smP + 128*72;
    __nv_bfloat16* Bhs = smP + 2*128*72;
    __nv_bfloat16* Bls = Bhs + 64*72;

    int tid = threadIdx.x;
    int wid = tid >> 5, lane = tid & 31;
    int warp_m = wid & 1, warp_n = wid >> 1;
    int lr = lane >> 2;
    int lk = (lane & 3) * 2;
    int bh = blockIdx.x;
    int b = bh >> 3, h = bh & 7;
    int dbase = blockIdx.y * 128;

    {
        int r = tid >> 1, half = tid & 1;
        #pragma unroll
        for (int q0 = 0; q0 < 4; ++q0) {
            int q = half*4 + q0;
            size_t src = (size_t)(dbase + r)*512 + h*64 + q*8;
            cp16(&Ahs[r*72 + q*8], &S_Whi[src]);
            cp16(&Als[r*72 + q*8], &S_Wlo[src]);
        }
    }
    #pragma unroll
    for (int p = 0; p < 2; ++p) {
        int idx = tid + p*256;
        int g = idx >> 3, c8 = (idx & 7)*8;
        size_t src = (size_t)(b*64 + g)*512 + h*64 + c8;
        cp16(&Bhs[g*72 + c8], &S_outhi[src]);
        cp16(&Bls[g*72 + c8], &S_outlo[src]);
    }
    CP_COMMIT();
    CP_WAIT0();
    __syncthreads();

    float acc[4][2][4];
    #pragma unroll
    for (int mt = 0; mt < 4; ++mt)
        #pragma unroll
        for (int nt = 0; nt < 2; ++nt)
            #pragma unroll
            for (int q = 0; q < 4; ++q) acc[mt][nt][q] = 0.f;

    #pragma unroll
    for (int ks = 0; ks < 4; ++ks) {
        int k0 = ks*16;
        uint32_t ah[4][4], al[4][4], bhf[2][2], blf[2][2];
        #pragma unroll
        for (int mt = 0; mt < 4; ++mt) {
            int rb = warp_m*64 + mt*16 + lr;
            const __nv_bfloat16* pa = &Ahs[rb*72 + k0 + lk];
            ah[mt][0] = *(const uint32_t*)pa;
            ah[mt][1] = *(const uint32_t*)(pa + 8*72);
            ah[mt][2] = *(const uint32_t*)(pa + 8);
            ah[mt][3] = *(const uint32_t*)(pa + 8*72 + 8);
            const __nv_bfloat16* pl = &Als[rb*72 + k0 + lk];
            al[mt][0] = *(const uint32_t*)pl;
            al[mt][1] = *(const uint32_t*)(pl + 8*72);
            al[mt][2] = *(const uint32_t*)(pl + 8);
            al[mt][3] = *(const uint32_t*)(pl + 8*72 + 8);
        }
        #pragma unroll
        for (int nt = 0; nt < 2; ++nt) {
            int nb = warp_n*16 + nt*8 + lr;
            const __nv_bfloat16* pb = &Bhs[nb*72 + k0 + lk];
            bhf[nt][0] = *(const uint32_t*)pb;
            bhf[nt][1] = *(const uint32_t*)(pb + 8);
            const __nv_bfloat16* pl = &Bls[nb*72 + k0 + lk];
            blf[nt][0] = *(const uint32_t*)pl;
            blf[nt][1] = *(const uint32_t*)(pl + 8);
        }
        #pragma unroll
        for (int mt = 0; mt < 4; ++mt)
            #pragma unroll
            for (int nt = 0; nt < 2; ++nt) {
                mma16816(acc[mt][nt], ah[mt], bhf[nt]);
                mma16816(acc[mt][nt], ah[mt], blf[nt]);
                mma16816(acc[mt][nt], al[mt], bhf[nt]);
            }
    }

    #pragma unroll
    for (int mt = 0; mt < 4; ++mt) {
        int m = warp_m*64 + mt*16 + lr;
        #pragma unroll
        for (int nt = 0; nt < 2; ++nt) {
            int coln = warp_n*16 + nt*8 + lk;
            size_t base = ((size_t)b*512 + dbase + m)*512 + h*64 + coln;
            float2 v0;
            v0.x = to_tf32(acc[mt][nt][0]);
            v0.y = to_tf32(acc[mt][nt][1]);
            *(float2*)&S_Pt[base] = v0;
            float2 v1;
            v1.x = to_tf32(acc[mt][nt][2]);
            v1.y = to_tf32(acc[mt][nt][3]);
            *(float2*)&S_Pt[base + 8*512] = v1;
        }
    }
}

// ---------------------------------------------------------------------------
// Big GEMM (tf32, 3-stage all-cp.async pipeline, raw-bit A operands)
#define BM_BUF  (2*128*36)
#define BM_SMEM (3*BM_BUF*4)
__global__ __launch_bounds__(256, 2) void k_bigmma(
    const float* __restrict__ sw, const float* __restrict__ bias,
    float* __restrict__ out)
{
    extern __shared__ float smB[];
    GDC_WAIT();
    int tid = threadIdx.x;
    int wid = tid >> 5, lane = tid & 31;
    int warp_m = wid & 1, warp_n = wid >> 1;
    int lr = lane >> 2;
    int lq = lane & 3;
    int dc = blockIdx.x & 3;
    int mt0 = blockIdx.x >> 2;
    int n0 = mt0 * 128;
    int b  = blockIdx.y;
    int dbase = dc * 128;

    int arow = tid >> 1;
    int ahalf = tid & 1;
    bool avalid = (n0 + arow) < NCTX;

    auto stageA = [&](int kc, int buf) {
        float* As = smB + buf*BM_BUF;
        int h = kc >> 1;
        int g0 = (kc & 1)*32 + ahalf*16;
        const float* src = sw + ((size_t)(b*8 + h)*NCTX + (avalid ? n0 + arow : 0))*64 + g0;
        float* dst = &As[arow*36 + ahalf*16];
        cp16p(dst,      src,      avalid);
        cp16p(dst + 4,  src + 4,  avalid);
        cp16p(dst + 8,  src + 8,  avalid);
        cp16p(dst + 12, src + 12, avalid);
    };
    auto stageB = [&](int kc, int buf) {
        float* Bs = smB + buf*BM_BUF + 128*36;
        #pragma unroll
        for (int p = 0; p < 4; ++p) {
            int idx = tid + p*256;
            int row = idx >> 3, q = idx & 7;
            size_t src = ((size_t)b*512 + dbase + row)*512 + kc*32 + q*4;
            cp16(&Bs[row*36 + q*4], &S_Pt[src]);
        }
    };

    float acc[4][4][4];
    #pragma unroll
    for (int mt = 0; mt < 4; ++mt)
        #pragma unroll
        for (int nt = 0; nt < 4; ++nt)
            #pragma unroll
            for (int q = 0; q < 4; ++q) acc[mt][nt][q] = 0.f;

    stageA(0, 0); stageB(0, 0); CP_COMMIT();
    stageA(1, 1); stageB(1, 1); CP_COMMIT();

    for (int kc = 0; kc < 16; ++kc) {
        if (kc < 15) { CP_WAIT1(); }
        else         { CP_WAIT0(); }
        __syncthreads();
        if (kc + 2 < 16) {
            int nb = (kc + 2) % 3;
            stageA(kc + 2, nb);
            stageB(kc + 2, nb);
            CP_COMMIT();
        }

        float* As = smB + (kc % 3)*BM_BUF;
        float* Bs = As + 128*36;

        #pragma unroll
        for (int ks = 0; ks < 4; ++ks) {
            int k0 = ks*8;
            uint32_t af[4][4], bf[4][2];
            #pragma unroll
            for (int mt = 0; mt < 4; ++mt) {
                int rb = warp_m*64 + mt*16 + lr;
                const float* pa = &As[rb*36 + k0 + lq];
                af[mt][0] = __float_as_uint(pa[0]);
                af[mt][1] = __float_as_uint(pa[8*36]);
                af[mt][2] = __float_as_uint(pa[4]);
                af[mt][3] = __float_as_uint(pa[8*36 + 4]);
            }
            #pragma unroll
            for (int nt = 0; nt < 4; ++nt) {
                int nb = warp_n*32 + nt*8 + lr;
                const float* pb = &Bs[nb*36 + k0 + lq];
                bf[nt][0] = __float_as_uint(pb[0]);
                bf[nt][1] = __float_as_uint(pb[4]);
            }
            #pragma unroll
            for (int mt = 0; mt < 4; ++mt)
                #pragma unroll
                for (int nt = 0; nt < 4; ++nt)
                    mma_tf32(acc[mt][nt], af[mt], bf[nt]);
        }
    }

    // epilogue
    #pragma unroll
    for (int mt = 0; mt < 4; ++mt) {
        int m = warp_m*64 + mt*16 + lr;
        #pragma unroll
        for (int nt = 0; nt < 4; ++nt) {
            int col = dbase + warp_n*32 + nt*8 + lq*2;
            float b0 = __ldg(&bias[col]);
            float b1 = __ldg(&bias[col + 1]);
            if (n0 + m < NCTX) {
                size_t r = (size_t)b*NCTX + n0 + m;
                float2 v;
                v.x = acc[mt][nt][0] + b0;
                v.y = acc[mt][nt][1] + b1;
                *(float2*)&out[r*512 + col] = v;
            }
            if (n0 + m + 8 < NCTX) {
                size_t r = (size_t)b*NCTX + n0 + m + 8;
                float2 v;
                v.x = acc[mt][nt][2] + b0;
                v.y = acc[mt][nt][3] + b1;
                *(float2*)&out[r*512 + col] = v;
            }
        }
    }
}

// ---------------------------------------------------------------------------
// Launch helper with PDL (programmatic stream serialization)
template <typename F, typename... Args>
static void launch_pdl(F fn, dim3 grid, dim3 block, size_t smem, Args... args) {
    cudaLaunchConfig_t cfg = {};
    cfg.gridDim = grid;
    cfg.blockDim = block;
    cfg.dynamicSmemBytes = smem;
    cfg.stream = 0;
    cudaLaunchAttribute attr[1];
    attr[0].id = cudaLaunchAttributeProgrammaticStreamSerialization;
    attr[0].val.programmaticStreamSerializationAllowed = 1;
    cfg.attrs = attr;
    cfg.numAttrs = 1;
    cudaLaunchKernelEx(&cfg, fn, args...);
}

extern "C" void kernel_launch(void* const* d_in, const int* in_sizes, int n_in,
                              void* d_out, int out_size) {
    const float* st     = (const float*)d_in[0];
    const float* sw     = (const float*)d_in[1];
    const float* w_in   = (const float*)d_in[2];
    const float* conv_w = (const float*)d_in[3];
    const float* conv_b = (const float*)d_in[4];
    const float* dt_bias= (const float*)d_in[5];
    const float* A_log  = (const float*)d_in[6];
    const float* Dv     = (const float*)d_in[7];
    const float* fc_D_w = (const float*)d_in[8];
    const float* norm_w = (const float*)d_in[9];
    const float* w_out  = (const float*)d_in[10];
    const float* to_w   = (const float*)d_in[11];
    const float* to_b   = (const float*)d_in[12];

    float* out       = (float*)d_out;
    float* out_final = out;
    float* out_inp   = out + (size_t)B16*NCTX*DM512;
    float* out_outp  = out_inp + (size_t)B16*8*64*64;

    float* pSzx;
    __nv_bfloat16 *pUh, *pUl, *pYh, *pYl, *pW1h, *pW1l, *pW2h, *pW2l;
    cudaGetSymbolAddress((void**)&pSzx, S_zx);
    cudaGetSymbolAddress((void**)&pUh, S_uhi);
    cudaGetSymbolAddress((void**)&pUl, S_ulo);
    cudaGetSymbolAddress((void**)&pYh, S_ynhi);
    cudaGetSymbolAddress((void**)&pYl, S_ynlo);
    cudaGetSymbolAddress((void**)&pW1h, S_W1hi);
    cudaGetSymbolAddress((void**)&pW1l, S_W1lo);
    cudaGetSymbolAddress((void**)&pW2h, S_W2hi);
    cudaGetSymbolAddress((void**)&pW2l, S_W2lo);

    k_pre<<<1024 + 1042, 512>>>(st, out_inp, w_in, w_out, to_w);

    cudaFuncSetAttribute(k_gemm_sp64, cudaFuncAttributeMaxDynamicSharedMemorySize, GS_SMEM);
    launch_pdl(k_gemm_sp64, dim3(16, 9), dim3(256), (size_t)GS_SMEM,
               (const __nv_bfloat16*)pUh, (const __nv_bfloat16*)pUl,
               (const __nv_bfloat16*)pW1h, (const __nv_bfloat16*)pW1l,
               pSzx, (int)DINPROJ, 0, (float*)nullptr);

    cudaFuncSetAttribute(k_scanc, cudaFuncAttributeMaxDynamicSharedMemorySize, SC_SMEM);
    launch_pdl(k_scanc, dim3(128), dim3(128), (size_t)SC_SMEM,
               conv_w, conv_b, dt_bias, A_log);

    launch_pdl(k_combine, dim3(B16*L64), dim3(512), (size_t)0, fc_D_w, Dv, norm_w);

    launch_pdl(k_gemm_sp64, dim3(16, 4), dim3(256), (size_t)GS_SMEM,
               (const __nv_bfloat16*)pYh, (const __nv_bfloat16*)pYl,
               (const __nv_bfloat16*)pW2h, (const __nv_bfloat16*)pW2l,
               (float*)nullptr, (int)DM512, 1, out_outp);

    cudaFuncSetAttribute(k_prepP, cudaFuncAttributeMaxDynamicSharedMemorySize, PP_SMEM);
    launch_pdl(k_prepP, dim3(128, 4), dim3(256), (size_t)PP_SMEM);

    cudaFuncSetAttribute(k_bigmma, cudaFuncAttributeMaxDynamicSharedMemorySize, BM_SMEM);
    launch_pdl(k_bigmma, dim3(4*((NCTX + 127)/128), B16), dim3(256), (size_t)BM_SMEM,
               sw, to_b, out_final);
}